// round 1
// baseline (speedup 1.0000x reference)
#include <cuda_runtime.h>
#include <math.h>

#ifndef M_PI
#define M_PI 3.14159265358979323846
#endif

namespace {
constexpr int BB  = 2;
constexpr int NH  = 12;
constexpr int SEQ = 2048;
constexpr int HD  = 64;
constexpr int CD  = 768;     // DIM
constexpr int QD  = 2304;    // 3*DIM
constexpr int MROWS = BB * SEQ;  // 4096
}

// ---- scratch (static device globals; allocation-free) ----
__device__ float g_q [BB*NH*SEQ*HD];
__device__ float g_k [BB*NH*SEQ*HD];
__device__ float g_v [BB*NH*SEQ*HD];
__device__ float g_qf[BB*NH*SEQ*HD];
__device__ float g_kf[BB*NH*SEQ*HD];
__device__ float g_c [NH*SEQ];
__device__ float g_S [(size_t)BB*NH*SEQ*SEQ];   // ~403 MB
__device__ float g_O [BB*NH*SEQ*HD];
__device__ float g_Ot[BB*SEQ*CD];

// ============================================================
// Filter taps: c_h[u] = Re(ifft(A_h))[u], closed form.
// A_h[n] = 1 for n<m, exp(-(n-m)*4/N) for n>=m, m = floor(N*sigmoid(p_h)).
// ============================================================
__global__ void filter_kernel(const float* __restrict__ fp)
{
    int h = blockIdx.y;
    int u = blockIdx.x * blockDim.x + threadIdx.x;
    if (u >= SEQ) return;

    double p   = (double)fp[h];
    double sig = 1.0 / (1.0 + exp(-p));
    double md  = floor((double)SEQ * sig);
    int    m   = (int)md;
    double alpha = 4.0 / (double)SEQ;
    double theta = 2.0 * M_PI * (double)u / (double)SEQ;
    double wr = cos(theta), wi = sin(theta);
    double am = theta * (double)m;
    double wmr = cos(am), wmi = sin(am);

    // S1 = sum_{n=0}^{m-1} w^n
    double s1r;
    if (u == 0) {
        s1r = md;
    } else {
        double nr = 1.0 - wmr, ni = -wmi;
        double dr = 1.0 - wr,  di = -wi;
        double den = dr*dr + di*di;
        s1r = (nr*dr + ni*di) / den;
    }

    // S2 = w^m * (1 - e^{-a(N-m)} w^{-m}) / (1 - e^{-a} w)
    double e1 = exp(-alpha * (double)(SEQ - m));
    double ea = exp(-alpha);
    double nr2 = 1.0 - e1*wmr, ni2 = e1*wmi;        // 1 - e1*(cos - i sin)
    double dr2 = 1.0 - ea*wr,  di2 = -ea*wi;
    double den2 = dr2*dr2 + di2*di2;
    double tr = (nr2*dr2 + ni2*di2) / den2;
    double ti = (ni2*dr2 - nr2*di2) / den2;
    double s2r = wmr*tr - wmi*ti;                   // Re(w^m * t)

    g_c[h*SEQ + u] = (float)((s1r + s2r) / (double)SEQ);
}

// ============================================================
// Generic tiled SGEMM, NT: C[m,n] = sum_k A[m,k]*B[n,k]
// 64x64 tile, TK=16, 256 threads, 4x4 per thread, batched via blockIdx.z.
// ============================================================
template<class Epi>
__global__ __launch_bounds__(256) void gemm_nt(const float* __restrict__ A,
                                               const float* __restrict__ Bm,
                                               int M, int Nn, int K,
                                               size_t sA, size_t sB, Epi epi)
{
    constexpr int TM=64, TN=64, TK=16;
    __shared__ float As[TK][TM+4];
    __shared__ float Bs[TK][TN+4];
    const float* Ab = A  + (size_t)blockIdx.z * sA;
    const float* Bb = Bm + (size_t)blockIdx.z * sB;
    const int m0 = blockIdx.y * TM, n0 = blockIdx.x * TN;
    const int tid = threadIdx.x;
    const int tx = tid & 15, ty = tid >> 4;
    float acc[4][4] = {};

    for (int k0 = 0; k0 < K; k0 += TK) {
        {   // 256 threads load exactly TM*TK/4 = 256 float4 per tile
            int m  = tid >> 2;
            int kq = tid & 3;
            float4 t = *(const float4*)(Ab + (size_t)(m0+m)*K + k0 + kq*4);
            As[kq*4+0][m]=t.x; As[kq*4+1][m]=t.y; As[kq*4+2][m]=t.z; As[kq*4+3][m]=t.w;
            float4 u = *(const float4*)(Bb + (size_t)(n0+m)*K + k0 + kq*4);
            Bs[kq*4+0][m]=u.x; Bs[kq*4+1][m]=u.y; Bs[kq*4+2][m]=u.z; Bs[kq*4+3][m]=u.w;
        }
        __syncthreads();
        #pragma unroll
        for (int kk = 0; kk < TK; kk++) {
            float a[4], b[4];
            *(float4*)a = *(const float4*)&As[kk][ty*4];
            *(float4*)b = *(const float4*)&Bs[kk][tx*4];
            #pragma unroll
            for (int i = 0; i < 4; i++)
                #pragma unroll
                for (int j = 0; j < 4; j++)
                    acc[i][j] = fmaf(a[i], b[j], acc[i][j]);
        }
        __syncthreads();
    }
    #pragma unroll
    for (int i = 0; i < 4; i++)
        #pragma unroll
        for (int j = 0; j < 4; j++)
            epi(blockIdx.z, m0 + ty*4 + i, n0 + tx*4 + j, acc[i][j]);
}

// NN: C[m,n] = sum_k A[m,k]*B[k,n]
template<class Epi>
__global__ __launch_bounds__(256) void gemm_nn(const float* __restrict__ A,
                                               const float* __restrict__ Bm,
                                               int M, int Nn, int K,
                                               size_t sA, size_t sB, Epi epi)
{
    constexpr int TM=64, TN=64, TK=16;
    __shared__ float As[TK][TM+4];
    __shared__ float Bs[TK][TN+4];
    const float* Ab = A  + (size_t)blockIdx.z * sA;
    const float* Bb = Bm + (size_t)blockIdx.z * sB;
    const int m0 = blockIdx.y * TM, n0 = blockIdx.x * TN;
    const int tid = threadIdx.x;
    const int tx = tid & 15, ty = tid >> 4;
    float acc[4][4] = {};

    for (int k0 = 0; k0 < K; k0 += TK) {
        {
            int m  = tid >> 2;
            int kq = tid & 3;
            float4 t = *(const float4*)(Ab + (size_t)(m0+m)*K + k0 + kq*4);
            As[kq*4+0][m]=t.x; As[kq*4+1][m]=t.y; As[kq*4+2][m]=t.z; As[kq*4+3][m]=t.w;
            int kk = tid >> 4;           // TK*TN/4 = 256 float4
            int nq = tid & 15;
            float4 u = *(const float4*)(Bb + (size_t)(k0+kk)*Nn + n0 + nq*4);
            *(float4*)&Bs[kk][nq*4] = u;
        }
        __syncthreads();
        #pragma unroll
        for (int kk = 0; kk < TK; kk++) {
            float a[4], b[4];
            *(float4*)a = *(const float4*)&As[kk][ty*4];
            *(float4*)b = *(const float4*)&Bs[kk][tx*4];
            #pragma unroll
            for (int i = 0; i < 4; i++)
                #pragma unroll
                for (int j = 0; j < 4; j++)
                    acc[i][j] = fmaf(a[i], b[j], acc[i][j]);
        }
        __syncthreads();
    }
    #pragma unroll
    for (int i = 0; i < 4; i++)
        #pragma unroll
        for (int j = 0; j < 4; j++)
            epi(blockIdx.z, m0 + ty*4 + i, n0 + tx*4 + j, acc[i][j]);
}

// ============================================================
// Circulant apply: dst[n,d] = sum_m c_h[(n-m) mod N] * src[m,d]
// grid: (SEQ/64, BB*NH)
// ============================================================
__global__ __launch_bounds__(256) void circ_apply(const float* __restrict__ src,
                                                  float* __restrict__ dst)
{
    const int bh = blockIdx.y;
    const int h  = bh % NH;
    const int n0 = blockIdx.x * 64;
    const float* q  = src + (size_t)bh * SEQ * HD;
    float*       o  = dst + (size_t)bh * SEQ * HD;
    const float* cf = g_c + h * SEQ;

    __shared__ float csh[128];
    __shared__ float qsh[64][HD+4];

    const int tid = threadIdx.x;
    const int tx = tid & 15, ty = tid >> 4;
    float acc[4][4] = {};

    for (int m0 = 0; m0 < SEQ; m0 += 64) {
        if (tid < 128) {
            int idx = n0 - m0 - 63 + tid;
            idx = (idx % SEQ + SEQ) % SEQ;
            csh[tid] = cf[idx];
        }
        for (int i = tid; i < 64*16; i += 256) {   // 64 rows x 16 float4
            int m = i >> 4, dq = i & 15;
            float4 t = *(const float4*)(q + (size_t)(m0+m)*HD + dq*4);
            *(float4*)&qsh[m][dq*4] = t;
        }
        __syncthreads();
        #pragma unroll 4
        for (int ml = 0; ml < 64; ml++) {
            float a[4];
            #pragma unroll
            for (int i = 0; i < 4; i++) a[i] = csh[ty*4 + i - ml + 63];
            float b[4];
            *(float4*)b = *(const float4*)&qsh[ml][tx*4];
            #pragma unroll
            for (int i = 0; i < 4; i++)
                #pragma unroll
                for (int j = 0; j < 4; j++)
                    acc[i][j] = fmaf(a[i], b[j], acc[i][j]);
        }
        __syncthreads();
    }
    #pragma unroll
    for (int i = 0; i < 4; i++) {
        float4 r = make_float4(acc[i][0], acc[i][1], acc[i][2], acc[i][3]);
        *(float4*)(o + (size_t)(n0 + ty*4 + i)*HD + tx*4) = r;
    }
}

// ============================================================
// Row softmax over g_S: one block per row of 2048
// ============================================================
__global__ __launch_bounds__(256) void softmax_kernel()
{
    __shared__ float sm[8];
    float* p = g_S + (size_t)blockIdx.x * SEQ;
    float4* p4 = (float4*)p;
    const int tid = threadIdx.x;

    float4 v0 = p4[tid];
    float4 v1 = p4[tid + 256];
    float mx = fmaxf(fmaxf(fmaxf(v0.x,v0.y), fmaxf(v0.z,v0.w)),
                     fmaxf(fmaxf(v1.x,v1.y), fmaxf(v1.z,v1.w)));
    #pragma unroll
    for (int o = 16; o; o >>= 1) mx = fmaxf(mx, __shfl_xor_sync(0xffffffffu, mx, o));
    if ((tid & 31) == 0) sm[tid >> 5] = mx;
    __syncthreads();
    mx = sm[0];
    #pragma unroll
    for (int i = 1; i < 8; i++) mx = fmaxf(mx, sm[i]);
    __syncthreads();

    v0.x = __expf(v0.x - mx); v0.y = __expf(v0.y - mx);
    v0.z = __expf(v0.z - mx); v0.w = __expf(v0.w - mx);
    v1.x = __expf(v1.x - mx); v1.y = __expf(v1.y - mx);
    v1.z = __expf(v1.z - mx); v1.w = __expf(v1.w - mx);
    float s = (v0.x+v0.y+v0.z+v0.w) + (v1.x+v1.y+v1.z+v1.w);
    #pragma unroll
    for (int o = 16; o; o >>= 1) s += __shfl_xor_sync(0xffffffffu, s, o);
    if ((tid & 31) == 0) sm[tid >> 5] = s;
    __syncthreads();
    s = 0.f;
    #pragma unroll
    for (int i = 0; i < 8; i++) s += sm[i];
    float inv = 1.0f / s;

    v0.x*=inv; v0.y*=inv; v0.z*=inv; v0.w*=inv;
    v1.x*=inv; v1.y*=inv; v1.z*=inv; v1.w*=inv;
    p4[tid] = v0;
    p4[tid + 256] = v1;
}

// (b,h,n,d) -> (b,n, h*64+d)
__global__ __launch_bounds__(256) void transpose_O_kernel()
{
    int idx = blockIdx.x * blockDim.x + threadIdx.x;
    int d = idx & (HD-1);
    int n = (idx / HD) & (SEQ-1);
    int h = (idx / (HD*SEQ)) % NH;
    int b = idx / (HD*SEQ*NH);
    g_Ot[((size_t)(b*SEQ + n))*CD + h*HD + d] = g_O[idx];
}

// ---- epilogues ----
struct EpiQKV {
    __device__ void operator()(int, int r, int j, float v) const {
        int b = r / SEQ, n = r % SEQ;
        int s = j / CD; int rem = j % CD;
        int h = rem / HD, d = rem % HD;
        float* dst = (s == 0) ? g_q : ((s == 1) ? g_k : g_v);
        dst[(((size_t)b*NH + h)*SEQ + n)*HD + d] = v;
    }
};
struct EpiS {
    __device__ void operator()(int bz, int m, int n, float v) const {
        g_S[((size_t)bz*SEQ + m)*SEQ + n] = v * 0.125f;   // 64^-0.5
    }
};
struct EpiO {
    __device__ void operator()(int bz, int m, int n, float v) const {
        g_O[((size_t)bz*SEQ + m)*HD + n] = v;
    }
};
struct EpiOut {
    float* out; const float* pb;
    __device__ void operator()(int, int r, int o, float v) const {
        out[(size_t)r*CD + o] = v + pb[o];
    }
};

extern "C" void kernel_launch(void* const* d_in, const int* /*in_sizes*/, int /*n_in*/,
                              void* d_out, int /*out_size*/)
{
    const float* x      = (const float*)d_in[0];
    const float* qkv_w  = (const float*)d_in[1];
    const float* proj_w = (const float*)d_in[2];
    const float* proj_b = (const float*)d_in[3];
    const float* fp     = (const float*)d_in[4];
    float* out = (float*)d_out;

    float *p_q, *p_k, *p_v, *p_qf, *p_kf, *p_S;
    cudaGetSymbolAddress((void**)&p_q,  g_q);
    cudaGetSymbolAddress((void**)&p_k,  g_k);
    cudaGetSymbolAddress((void**)&p_v,  g_v);
    cudaGetSymbolAddress((void**)&p_qf, g_qf);
    cudaGetSymbolAddress((void**)&p_kf, g_kf);
    cudaGetSymbolAddress((void**)&p_S,  g_S);
    float *p_Ot;
    cudaGetSymbolAddress((void**)&p_Ot, g_Ot);

    // 1. filter taps
    filter_kernel<<<dim3(SEQ/256, NH), 256>>>(fp);
    // 2. QKV projection (scattered into q/k/v head layout)
    gemm_nt<<<dim3(QD/64, MROWS/64, 1), 256>>>(x, qkv_w, MROWS, QD, CD,
                                               (size_t)0, (size_t)0, EpiQKV{});
    // 3. spectral filtering as circulant matmuls
    circ_apply<<<dim3(SEQ/64, BB*NH), 256>>>(p_q, p_qf);
    circ_apply<<<dim3(SEQ/64, BB*NH), 256>>>(p_k, p_kf);
    // 4. attention scores
    gemm_nt<<<dim3(SEQ/64, SEQ/64, BB*NH), 256>>>(p_qf, p_kf, SEQ, SEQ, HD,
                                                  (size_t)SEQ*HD, (size_t)SEQ*HD, EpiS{});
    // 5. softmax
    softmax_kernel<<<BB*NH*SEQ, 256>>>();
    // 6. P@V
    gemm_nn<<<dim3(HD/64, SEQ/64, BB*NH), 256>>>(p_S, p_v, SEQ, HD, SEQ,
                                                 (size_t)SEQ*SEQ, (size_t)SEQ*HD, EpiO{});
    // 7. head merge transpose
    transpose_O_kernel<<<BB*NH*SEQ*HD/256, 256>>>();
    // 8. output projection + bias
    gemm_nt<<<dim3(CD/64, MROWS/64, 1), 256>>>(p_Ot, proj_w, MROWS, CD, CD,
                                               (size_t)0, (size_t)0, EpiOut{out, proj_b});
}

// round 3
// speedup vs baseline: 1.2548x; 1.2548x over previous
#include <cuda_runtime.h>
#include <math.h>

#ifndef M_PI
#define M_PI 3.14159265358979323846
#endif

namespace {
constexpr int BB  = 2;
constexpr int NH  = 12;
constexpr int SEQ = 2048;
constexpr int HD  = 64;
constexpr int CD  = 768;     // DIM
constexpr int QD  = 2304;    // 3*DIM
constexpr int MROWS = BB * SEQ;  // 4096
}

// ---- scratch (static device globals; allocation-free) ----
__device__ float g_q [BB*NH*SEQ*HD];
__device__ float g_k [BB*NH*SEQ*HD];
__device__ float g_v [BB*NH*SEQ*HD];
__device__ float g_qf[BB*NH*SEQ*HD];
__device__ float g_kf[BB*NH*SEQ*HD];
__device__ float g_c [NH*SEQ];
__device__ float g_S [(size_t)BB*NH*SEQ*SEQ];   // ~403 MB
__device__ float g_Ot[BB*SEQ*CD];

// ============================================================
// Filter taps: c_h[u] = Re(ifft(A_h))[u], closed form.
// ============================================================
__global__ void filter_kernel(const float* __restrict__ fp)
{
    int h = blockIdx.y;
    int u = blockIdx.x * blockDim.x + threadIdx.x;
    if (u >= SEQ) return;

    double p   = (double)fp[h];
    double sig = 1.0 / (1.0 + exp(-p));
    double md  = floor((double)SEQ * sig);
    int    m   = (int)md;
    double alpha = 4.0 / (double)SEQ;
    double theta = 2.0 * M_PI * (double)u / (double)SEQ;
    double wr = cos(theta), wi = sin(theta);
    double am = theta * (double)m;
    double wmr = cos(am), wmi = sin(am);

    double s1r;
    if (u == 0) {
        s1r = md;
    } else {
        double nr = 1.0 - wmr, ni = -wmi;
        double dr = 1.0 - wr,  di = -wi;
        double den = dr*dr + di*di;
        s1r = (nr*dr + ni*di) / den;
    }

    double e1 = exp(-alpha * (double)(SEQ - m));
    double ea = exp(-alpha);
    double nr2 = 1.0 - e1*wmr, ni2 = e1*wmi;
    double dr2 = 1.0 - ea*wr,  di2 = -ea*wi;
    double den2 = dr2*dr2 + di2*di2;
    double tr = (nr2*dr2 + ni2*di2) / den2;
    double ti = (ni2*dr2 - nr2*di2) / den2;
    double s2r = wmr*tr - wmi*ti;

    g_c[h*SEQ + u] = (float)((s1r + s2r) / (double)SEQ);
}

// ============================================================
// SGEMM NT 128x128x16, 256 threads, 8x8 micro (2x2 blocks of 4x4).
// C[m,n] = sum_k A[m,k]*B[n,k]
// ============================================================
template<class Epi>
__global__ __launch_bounds__(256,2) void gemm_nt128(const float* __restrict__ A,
                                                    const float* __restrict__ B,
                                                    int M, int N, int K,
                                                    size_t sA, size_t sB, Epi epi)
{
    constexpr int TK = 16;
    __shared__ float As[TK][128+4];
    __shared__ float Bs[TK][128+4];
    const float* Ab = A + (size_t)blockIdx.z * sA;
    const float* Bb = B + (size_t)blockIdx.z * sB;
    const int m0 = blockIdx.y * 128, n0 = blockIdx.x * 128;
    const int tid = threadIdx.x;
    const int tx = tid & 15, ty = tid >> 4;
    float acc[8][8] = {};

    for (int k0 = 0; k0 < K; k0 += TK) {
        #pragma unroll
        for (int l = 0; l < 2; l++) {
            int i = tid + 256*l;
            int r = i >> 2, kq = i & 3;
            float4 t = *(const float4*)(Ab + (size_t)(m0+r)*K + k0 + kq*4);
            As[kq*4+0][r]=t.x; As[kq*4+1][r]=t.y; As[kq*4+2][r]=t.z; As[kq*4+3][r]=t.w;
            float4 u = *(const float4*)(Bb + (size_t)(n0+r)*K + k0 + kq*4);
            Bs[kq*4+0][r]=u.x; Bs[kq*4+1][r]=u.y; Bs[kq*4+2][r]=u.z; Bs[kq*4+3][r]=u.w;
        }
        __syncthreads();
        #pragma unroll
        for (int kk = 0; kk < TK; kk++) {
            float a[8], b[8];
            *(float4*)(a  ) = *(const float4*)&As[kk][tx==tx ? ty*4 : 0];
            *(float4*)(a+4) = *(const float4*)&As[kk][64 + ty*4];
            *(float4*)(b  ) = *(const float4*)&Bs[kk][tx*4];
            *(float4*)(b+4) = *(const float4*)&Bs[kk][64 + tx*4];
            #pragma unroll
            for (int i = 0; i < 8; i++)
                #pragma unroll
                for (int j = 0; j < 8; j++)
                    acc[i][j] = fmaf(a[i], b[j], acc[i][j]);
        }
        __syncthreads();
    }
    #pragma unroll
    for (int i = 0; i < 8; i++) {
        int m = m0 + (i < 4 ? ty*4 + i : 64 + ty*4 + i - 4);
        epi.store4(blockIdx.z, m, n0 + tx*4,
                   make_float4(acc[i][0], acc[i][1], acc[i][2], acc[i][3]));
        epi.store4(blockIdx.z, m, n0 + 64 + tx*4,
                   make_float4(acc[i][4], acc[i][5], acc[i][6], acc[i][7]));
    }
}

// ============================================================
// SGEMM NN 128x64x16 (for P@V): C[m,n] = sum_k A[m,k]*B[k,n], N=64.
// 256 threads, 4x8 micro (n split 2x4).
// ============================================================
template<class Epi>
__global__ __launch_bounds__(256) void gemm_nn_pv(const float* __restrict__ A,
                                                  const float* __restrict__ B,
                                                  int K, size_t sA, size_t sB, Epi epi)
{
    constexpr int TK = 16;
    __shared__ float As[TK][128+4];
    __shared__ float Bs[TK][64+4];
    const float* Ab = A + (size_t)blockIdx.z * sA;
    const float* Bb = B + (size_t)blockIdx.z * sB;
    const int m0 = blockIdx.x * 128;
    const int tid = threadIdx.x;
    const int tx = tid & 7, ty = tid >> 3;
    float acc[4][8] = {};

    for (int k0 = 0; k0 < K; k0 += TK) {
        #pragma unroll
        for (int l = 0; l < 2; l++) {
            int i = tid + 256*l;
            int r = i >> 2, kq = i & 3;
            float4 t = *(const float4*)(Ab + (size_t)(m0+r)*K + k0 + kq*4);
            As[kq*4+0][r]=t.x; As[kq*4+1][r]=t.y; As[kq*4+2][r]=t.z; As[kq*4+3][r]=t.w;
        }
        {
            int kk = tid >> 4, nq = tid & 15;   // 16x16 float4 = 16x64 floats
            *(float4*)&Bs[kk][nq*4] = *(const float4*)(Bb + (size_t)(k0+kk)*HD + nq*4);
        }
        __syncthreads();
        #pragma unroll
        for (int kk = 0; kk < TK; kk++) {
            float a[4], b[8];
            *(float4*)(a  ) = *(const float4*)&As[kk][ty*4];
            *(float4*)(b  ) = *(const float4*)&Bs[kk][tx*4];
            *(float4*)(b+4) = *(const float4*)&Bs[kk][32 + tx*4];
            #pragma unroll
            for (int i = 0; i < 4; i++)
                #pragma unroll
                for (int j = 0; j < 8; j++)
                    acc[i][j] = fmaf(a[i], b[j], acc[i][j]);
        }
        __syncthreads();
    }
    #pragma unroll
    for (int i = 0; i < 4; i++) {
        int m = m0 + ty*4 + i;
        epi.store4(blockIdx.z, m, tx*4,
                   make_float4(acc[i][0], acc[i][1], acc[i][2], acc[i][3]));
        epi.store4(blockIdx.z, m, 32 + tx*4,
                   make_float4(acc[i][4], acc[i][5], acc[i][6], acc[i][7]));
    }
}

// ============================================================
// Circulant apply: dst[n,d] = scale * sum_m c_h[(n-m) & 2047] * src[m,d]
// 128(n) x 64(d) tile, K=m loop. grid: (SEQ/128, BB*NH)
// ============================================================
__global__ __launch_bounds__(256) void circ_apply(const float* __restrict__ src,
                                                  float* __restrict__ dst, float scale)
{
    constexpr int TK = 16;
    const int bh = blockIdx.y;
    const int h  = bh % NH;
    const int n0 = blockIdx.x * 128;
    const float* q  = src + (size_t)bh * SEQ * HD;
    float*       o  = dst + (size_t)bh * SEQ * HD;
    const float* cf = g_c + h * SEQ;

    __shared__ float csh[160];
    __shared__ float Bs[TK][64+4];

    const int tid = threadIdx.x;
    const int tx = tid & 7, ty = tid >> 3;
    float acc[4][8] = {};

    for (int m0 = 0; m0 < SEQ; m0 += TK) {
        if (tid < 160)
            csh[tid] = cf[(n0 - m0 - 15 + tid) & (SEQ-1)];
        {
            int kk = tid >> 4, nq = tid & 15;
            *(float4*)&Bs[kk][nq*4] = *(const float4*)(q + (size_t)(m0+kk)*HD + nq*4);
        }
        __syncthreads();
        #pragma unroll
        for (int kk = 0; kk < TK; kk++) {
            float a[4], b[8];
            #pragma unroll
            for (int i = 0; i < 4; i++) a[i] = csh[ty*4 + i - kk + 15];
            *(float4*)(b  ) = *(const float4*)&Bs[kk][tx*4];
            *(float4*)(b+4) = *(const float4*)&Bs[kk][32 + tx*4];
            #pragma unroll
            for (int i = 0; i < 4; i++)
                #pragma unroll
                for (int j = 0; j < 8; j++)
                    acc[i][j] = fmaf(a[i], b[j], acc[i][j]);
        }
        __syncthreads();
    }
    #pragma unroll
    for (int i = 0; i < 4; i++) {
        int n = n0 + ty*4 + i;
        float4 r0 = make_float4(acc[i][0]*scale, acc[i][1]*scale, acc[i][2]*scale, acc[i][3]*scale);
        float4 r1 = make_float4(acc[i][4]*scale, acc[i][5]*scale, acc[i][6]*scale, acc[i][7]*scale);
        *(float4*)(o + (size_t)n*HD + tx*4)      = r0;
        *(float4*)(o + (size_t)n*HD + 32 + tx*4) = r1;
    }
}

// ============================================================
// Row softmax over g_S: one block per row of 2048
// ============================================================
__global__ __launch_bounds__(256) void softmax_kernel()
{
    __shared__ float sm[8];
    float* p = g_S + (size_t)blockIdx.x * SEQ;
    float4* p4 = (float4*)p;
    const int tid = threadIdx.x;

    float4 v0 = p4[tid];
    float4 v1 = p4[tid + 256];
    float mx = fmaxf(fmaxf(fmaxf(v0.x,v0.y), fmaxf(v0.z,v0.w)),
                     fmaxf(fmaxf(v1.x,v1.y), fmaxf(v1.z,v1.w)));
    #pragma unroll
    for (int o = 16; o; o >>= 1) mx = fmaxf(mx, __shfl_xor_sync(0xffffffffu, mx, o));
    if ((tid & 31) == 0) sm[tid >> 5] = mx;
    __syncthreads();
    mx = sm[0];
    #pragma unroll
    for (int i = 1; i < 8; i++) mx = fmaxf(mx, sm[i]);
    __syncthreads();

    v0.x = __expf(v0.x - mx); v0.y = __expf(v0.y - mx);
    v0.z = __expf(v0.z - mx); v0.w = __expf(v0.w - mx);
    v1.x = __expf(v1.x - mx); v1.y = __expf(v1.y - mx);
    v1.z = __expf(v1.z - mx); v1.w = __expf(v1.w - mx);
    float s = (v0.x+v0.y+v0.z+v0.w) + (v1.x+v1.y+v1.z+v1.w);
    #pragma unroll
    for (int o = 16; o; o >>= 1) s += __shfl_xor_sync(0xffffffffu, s, o);
    if ((tid & 31) == 0) sm[tid >> 5] = s;
    __syncthreads();
    s = 0.f;
    #pragma unroll
    for (int i = 0; i < 8; i++) s += sm[i];
    float inv = 1.0f / s;

    v0.x*=inv; v0.y*=inv; v0.z*=inv; v0.w*=inv;
    v1.x*=inv; v1.y*=inv; v1.z*=inv; v1.w*=inv;
    p4[tid] = v0;
    p4[tid + 256] = v1;
}

// ---- epilogues ----
struct EpiQKV {      // scatter (row, 3*DIM col) -> per-head q/k/v
    __device__ void store4(int, int r, int j, float4 v) const {
        int b = r / SEQ, n = r % SEQ;
        int s = j / CD; int rem = j - s*CD;
        int h = rem / HD, d = rem - h*HD;
        float* dst = (s == 0) ? g_q : ((s == 1) ? g_k : g_v);
        *(float4*)&dst[(((size_t)b*NH + h)*SEQ + n)*HD + d] = v;
    }
};
struct EpiS {        // scores (scale already folded into q_filt)
    __device__ void store4(int bz, int m, int n, float4 v) const {
        *(float4*)&g_S[((size_t)bz*SEQ + m)*SEQ + n] = v;
    }
};
struct EpiO {        // P@V output, directly into (b, n, h*64+d) merged layout
    __device__ void store4(int bz, int m, int n, float4 v) const {
        int b = bz / NH, h = bz - b*NH;
        *(float4*)&g_Ot[((size_t)(b*SEQ + m))*CD + h*HD + n] = v;
    }
};
struct EpiOut {      // final projection + bias
    float* out; const float* pb;
    __device__ void store4(int, int r, int n, float4 v) const {
        float4 bb = *(const float4*)(pb + n);
        v.x += bb.x; v.y += bb.y; v.z += bb.z; v.w += bb.w;
        *(float4*)&out[(size_t)r*CD + n] = v;
    }
};

extern "C" void kernel_launch(void* const* d_in, const int* /*in_sizes*/, int /*n_in*/,
                              void* d_out, int /*out_size*/)
{
    const float* x      = (const float*)d_in[0];
    const float* qkv_w  = (const float*)d_in[1];
    const float* proj_w = (const float*)d_in[2];
    const float* proj_b = (const float*)d_in[3];
    const float* fp     = (const float*)d_in[4];
    float* out = (float*)d_out;

    float *p_q, *p_k, *p_v, *p_qf, *p_kf, *p_S, *p_Ot;
    cudaGetSymbolAddress((void**)&p_q,  g_q);
    cudaGetSymbolAddress((void**)&p_k,  g_k);
    cudaGetSymbolAddress((void**)&p_v,  g_v);
    cudaGetSymbolAddress((void**)&p_qf, g_qf);
    cudaGetSymbolAddress((void**)&p_kf, g_kf);
    cudaGetSymbolAddress((void**)&p_S,  g_S);
    cudaGetSymbolAddress((void**)&p_Ot, g_Ot);

    // 1. filter taps
    filter_kernel<<<dim3(SEQ/256, NH), 256>>>(fp);
    // 2. QKV projection (scattered into q/k/v head layout)
    gemm_nt128<<<dim3(QD/128, MROWS/128, 1), 256>>>(x, qkv_w, MROWS, QD, CD,
                                                    (size_t)0, (size_t)0, EpiQKV{});
    // 3. spectral filtering as circulant matmuls (q side carries 1/8 scale)
    circ_apply<<<dim3(SEQ/128, BB*NH), 256>>>(p_q, p_qf, 0.125f);
    circ_apply<<<dim3(SEQ/128, BB*NH), 256>>>(p_k, p_kf, 1.0f);
    // 4. attention scores
    gemm_nt128<<<dim3(SEQ/128, SEQ/128, BB*NH), 256>>>(p_qf, p_kf, SEQ, SEQ, HD,
                                                       (size_t)SEQ*HD, (size_t)SEQ*HD, EpiS{});
    // 5. softmax
    softmax_kernel<<<BB*NH*SEQ, 256>>>();
    // 6. P@V  (writes merged (b,n,c) layout directly)
    gemm_nn_pv<<<dim3(SEQ/128, 1, BB*NH), 256>>>(p_S, p_v, SEQ,
                                                 (size_t)SEQ*SEQ, (size_t)SEQ*HD, EpiO{});
    // 7. output projection + bias
    gemm_nt128<<<dim3(CD/128, MROWS/128, 1), 256>>>(p_Ot, proj_w, MROWS, CD, CD,
                                                    (size_t)0, (size_t)0, EpiOut{out, proj_b});
}

// round 4
// speedup vs baseline: 1.3914x; 1.1088x over previous
#include <cuda_runtime.h>
#include <math.h>

#ifndef M_PI
#define M_PI 3.14159265358979323846
#endif

namespace {
constexpr int BB  = 2;
constexpr int NH  = 12;
constexpr int SEQ = 2048;
constexpr int HD  = 64;
constexpr int CD  = 768;
constexpr int QD  = 2304;
constexpr int MROWS = BB * SEQ;  // 4096
}

// ---- scratch ----
__device__ float g_q [BB*NH*SEQ*HD];
__device__ float g_k [BB*NH*SEQ*HD];
__device__ float g_v [BB*NH*SEQ*HD];
__device__ float g_qf[BB*NH*SEQ*HD];
__device__ float g_kf[BB*NH*SEQ*HD];
__device__ float g_c [NH*SEQ];
__device__ float g_S [(size_t)BB*NH*SEQ*SEQ];
__device__ float g_Ot[BB*SEQ*CD];

// ============================================================
// mma helpers
// ============================================================
__device__ __forceinline__ unsigned f2tf(float x) {
    unsigned r;
    asm("cvt.rna.tf32.f32 %0, %1;" : "=r"(r) : "f"(x));
    return r;
}
__device__ __forceinline__ void split_tf(float x, unsigned& hi, unsigned& lo) {
    hi = f2tf(x);
    float l = x - __uint_as_float(hi);
    lo = f2tf(l);
}
__device__ __forceinline__ void mma8(float* c, const unsigned* a, const unsigned* b) {
    asm volatile(
        "mma.sync.aligned.m16n8k8.row.col.f32.tf32.tf32.f32 "
        "{%0,%1,%2,%3}, {%4,%5,%6,%7}, {%8,%9}, {%0,%1,%2,%3};"
        : "+f"(c[0]), "+f"(c[1]), "+f"(c[2]), "+f"(c[3])
        : "r"(a[0]), "r"(a[1]), "r"(a[2]), "r"(a[3]), "r"(b[0]), "r"(b[1]));
}

// Load + split one A operand pair (two 16-row frags) from m-major smem [.][36]
// a0=(g,t) a1=(g+8,t) a2=(g,t+4) a3=(g+8,t+4)
__device__ __forceinline__ void load_a_frag(const float* ap, unsigned* ah, unsigned* al) {
    float x0 = ap[0];
    float x1 = ap[8*36];
    float x2 = ap[4];
    float x3 = ap[8*36 + 4];
    split_tf(x0, ah[0], al[0]);
    split_tf(x1, ah[1], al[1]);
    split_tf(x2, ah[2], al[2]);
    split_tf(x3, ah[3], al[3]);
}

// ============================================================
// Filter taps (closed form), unchanged
// ============================================================
__global__ void filter_kernel(const float* __restrict__ fp)
{
    int h = blockIdx.y;
    int u = blockIdx.x * blockDim.x + threadIdx.x;
    if (u >= SEQ) return;

    double p   = (double)fp[h];
    double sig = 1.0 / (1.0 + exp(-p));
    double md  = floor((double)SEQ * sig);
    int    m   = (int)md;
    double alpha = 4.0 / (double)SEQ;
    double theta = 2.0 * M_PI * (double)u / (double)SEQ;
    double wr = cos(theta), wi = sin(theta);
    double am = theta * (double)m;
    double wmr = cos(am), wmi = sin(am);

    double s1r;
    if (u == 0) {
        s1r = md;
    } else {
        double nr = 1.0 - wmr, ni = -wmi;
        double dr = 1.0 - wr,  di = -wi;
        double den = dr*dr + di*di;
        s1r = (nr*dr + ni*di) / den;
    }
    double e1 = exp(-alpha * (double)(SEQ - m));
    double ea = exp(-alpha);
    double nr2 = 1.0 - e1*wmr, ni2 = e1*wmi;
    double dr2 = 1.0 - ea*wr,  di2 = -ea*wi;
    double den2 = dr2*dr2 + di2*di2;
    double tr = (nr2*dr2 + ni2*di2) / den2;
    double ti = (ni2*dr2 - nr2*di2) / den2;
    double s2r = wmr*tr - wmi*ti;

    g_c[h*SEQ + u] = (float)((s1r + s2r) / (double)SEQ);
}

// ============================================================
// NT tensor-core GEMM: C[m,n] = sum_k A[m,k] * B[n,k]
// block 128x128, TK=32, 8 warps (4m x 2n), warp tile 32x64.
// ============================================================
template<class Epi>
__global__ __launch_bounds__(256) void mma_nt(const float* __restrict__ A,
                                              const float* __restrict__ B,
                                              int K, size_t sA, size_t sB, Epi epi)
{
    __shared__ float As[128*36];
    __shared__ float Bs[128*36];
    const int m0 = blockIdx.y * 128, n0 = blockIdx.x * 128;
    const float* Ab = A + (size_t)blockIdx.z * sA;
    const float* Bb = B + (size_t)blockIdx.z * sB;
    const int tid = threadIdx.x, lane = tid & 31, wid = tid >> 5;
    const int wm = (wid >> 1) * 32, wn = (wid & 1) * 64;
    const int g = lane >> 2, t = lane & 3;
    const int sm = tid >> 3, skq = tid & 7;

    float C[2][8][4] = {};

    for (int k0 = 0; k0 < K; k0 += 32) {
        #pragma unroll
        for (int j = 0; j < 4; j++) {
            int m = sm + 32*j;
            float4 a4 = *(const float4*)(Ab + (size_t)(m0+m)*K + k0 + skq*4);
            *(float4*)&As[m*36 + skq*4] = a4;
            float4 b4 = *(const float4*)(Bb + (size_t)(n0+m)*K + k0 + skq*4);
            *(float4*)&Bs[m*36 + skq*4] = b4;
        }
        __syncthreads();
        #pragma unroll
        for (int ko = 0; ko < 32; ko += 8) {
            unsigned ah[2][4], al[2][4];
            #pragma unroll
            for (int im = 0; im < 2; im++)
                load_a_frag(&As[(wm + im*16 + g)*36 + ko + t], ah[im], al[im]);
            #pragma unroll
            for (int jn = 0; jn < 8; jn++) {
                const float* bp = &Bs[(wn + jn*8 + g)*36 + ko + t];
                unsigned bh[2], bl[2];
                split_tf(bp[0], bh[0], bl[0]);
                split_tf(bp[4], bh[1], bl[1]);
                #pragma unroll
                for (int im = 0; im < 2; im++) {
                    mma8(C[im][jn], ah[im], bh);
                    mma8(C[im][jn], ah[im], bl);
                    mma8(C[im][jn], al[im], bh);
                }
            }
        }
        __syncthreads();
    }
    #pragma unroll
    for (int im = 0; im < 2; im++)
        #pragma unroll
        for (int jn = 0; jn < 8; jn++) {
            int r  = m0 + wm + im*16 + g;
            int cc = n0 + wn + jn*8 + 2*t;
            epi.store2(blockIdx.z, r,   cc, C[im][jn][0], C[im][jn][1]);
            epi.store2(blockIdx.z, r+8, cc, C[im][jn][2], C[im][jn][3]);
        }
}

// ============================================================
// Circulant filter as tensor-core GEMM.
// out[n, 0:64]=q_filt (x0.125 folded), out[n,64:128]=k_filt.
// A generated from taps, B = [q | k] columns. grid (16, 24)
// ============================================================
__global__ __launch_bounds__(256) void mma_circ()
{
    __shared__ float As[128*36];
    __shared__ float Bs[32*136];
    __shared__ float csh[SEQ];

    const int m0 = blockIdx.x * 128;
    const int bh = blockIdx.y;
    const int h  = bh % NH;
    const float* srcq = g_q + (size_t)bh * SEQ * HD;
    const float* srck = g_k + (size_t)bh * SEQ * HD;

    const int tid = threadIdx.x, lane = tid & 31, wid = tid >> 5;
    const int wm = (wid >> 1) * 32, wn = (wid & 1) * 64;
    const int g = lane >> 2, t = lane & 3;

    for (int i = tid; i < SEQ; i += 256) csh[i] = g_c[h*SEQ + i];
    __syncthreads();

    float C[2][8][4] = {};

    const int amm = (tid & 7) + 8*(tid >> 5);   // 0..63
    const int akr = (tid >> 3) & 3;             // kk residue 0..3
    const int nq = tid & 31, kb = tid >> 5;
    const float* bsrc = (nq < 16) ? srcq : srck;
    const int ncol = (nq & 15) * 4;

    for (int k0 = 0; k0 < SEQ; k0 += 32) {
        #pragma unroll
        for (int jj = 0; jj < 2; jj++) {
            int mm = amm + 64*jj;
            #pragma unroll
            for (int c = 0; c < 8; c++) {
                int kk = akr + 4*c;
                As[mm*36 + kk] = csh[(m0 + mm - k0 - kk) & (SEQ-1)];
            }
        }
        #pragma unroll
        for (int jb = 0; jb < 4; jb++) {
            int kk = kb + 8*jb;
            float4 b4 = *(const float4*)(bsrc + (size_t)(k0+kk)*HD + ncol);
            *(float4*)&Bs[kk*136 + nq*4] = b4;
        }
        __syncthreads();
        #pragma unroll
        for (int ko = 0; ko < 32; ko += 8) {
            unsigned ah[2][4], al[2][4];
            #pragma unroll
            for (int im = 0; im < 2; im++)
                load_a_frag(&As[(wm + im*16 + g)*36 + ko + t], ah[im], al[im]);
            #pragma unroll
            for (int jn = 0; jn < 8; jn++) {
                const float* bp = &Bs[(ko + t)*136 + wn + jn*8 + g];
                unsigned bh2[2], bl2[2];
                split_tf(bp[0],     bh2[0], bl2[0]);
                split_tf(bp[4*136], bh2[1], bl2[1]);
                #pragma unroll
                for (int im = 0; im < 2; im++) {
                    mma8(C[im][jn], ah[im], bh2);
                    mma8(C[im][jn], ah[im], bl2);
                    mma8(C[im][jn], al[im], bh2);
                }
            }
        }
        __syncthreads();
    }

    float* qf = g_qf + (size_t)bh * SEQ * HD;
    float* kf = g_kf + (size_t)bh * SEQ * HD;
    #pragma unroll
    for (int im = 0; im < 2; im++)
        #pragma unroll
        for (int jn = 0; jn < 8; jn++) {
            int cc = wn + jn*8 + 2*t;
            #pragma unroll
            for (int half = 0; half < 2; half++) {
                int r = m0 + wm + im*16 + g + 8*half;
                float v0 = C[im][jn][2*half], v1 = C[im][jn][2*half+1];
                if (cc < 64) {
                    float2 w = make_float2(v0*0.125f, v1*0.125f);
                    *(float2*)&qf[(size_t)r*HD + cc] = w;
                } else {
                    float2 w = make_float2(v0, v1);
                    *(float2*)&kf[(size_t)r*HD + cc - 64] = w;
                }
            }
        }
}

// ============================================================
// P@V tensor-core GEMM (NN): O[m,d] = sum_k S[m,k] v[k,d]
// block 128x64, warps 4x2, warp tile 32x32. grid (16, 24)
// Writes merged (b, n, h*64+d) layout.
// ============================================================
__global__ __launch_bounds__(256) void mma_pv()
{
    __shared__ float As[128*36];
    __shared__ float Bs[32*136];

    const int m0 = blockIdx.x * 128;
    const int bh = blockIdx.y;
    const float* Ab = g_S + (size_t)bh * SEQ * SEQ;
    const float* vb = g_v + (size_t)bh * SEQ * HD;

    const int tid = threadIdx.x, lane = tid & 31, wid = tid >> 5;
    const int wm = (wid >> 1) * 32, wn = (wid & 1) * 32;
    const int g = lane >> 2, t = lane & 3;
    const int sm = tid >> 3, skq = tid & 7;
    const int nq = tid & 15, kb = tid >> 4;

    float C[2][4][4] = {};

    for (int k0 = 0; k0 < SEQ; k0 += 32) {
        #pragma unroll
        for (int j = 0; j < 4; j++) {
            int m = sm + 32*j;
            float4 a4 = *(const float4*)(Ab + (size_t)(m0+m)*SEQ + k0 + skq*4);
            *(float4*)&As[m*36 + skq*4] = a4;
        }
        #pragma unroll
        for (int jb = 0; jb < 2; jb++) {
            int kk = kb + 16*jb;
            float4 b4 = *(const float4*)(vb + (size_t)(k0+kk)*HD + nq*4);
            *(float4*)&Bs[kk*136 + nq*4] = b4;
        }
        __syncthreads();
        #pragma unroll
        for (int ko = 0; ko < 32; ko += 8) {
            unsigned ah[2][4], al[2][4];
            #pragma unroll
            for (int im = 0; im < 2; im++)
                load_a_frag(&As[(wm + im*16 + g)*36 + ko + t], ah[im], al[im]);
            #pragma unroll
            for (int jn = 0; jn < 4; jn++) {
                const float* bp = &Bs[(ko + t)*136 + wn + jn*8 + g];
                unsigned bh2[2], bl2[2];
                split_tf(bp[0],     bh2[0], bl2[0]);
                split_tf(bp[4*136], bh2[1], bl2[1]);
                #pragma unroll
                for (int im = 0; im < 2; im++) {
                    mma8(C[im][jn], ah[im], bh2);
                    mma8(C[im][jn], ah[im], bl2);
                    mma8(C[im][jn], al[im], bh2);
                }
            }
        }
        __syncthreads();
    }

    const int b = bh / NH, hh = bh - b*NH;
    #pragma unroll
    for (int im = 0; im < 2; im++)
        #pragma unroll
        for (int jn = 0; jn < 4; jn++) {
            int cc = wn + jn*8 + 2*t;
            #pragma unroll
            for (int half = 0; half < 2; half++) {
                int r = m0 + wm + im*16 + g + 8*half;
                float2 w = make_float2(C[im][jn][2*half], C[im][jn][2*half+1]);
                *(float2*)&g_Ot[((size_t)(b*SEQ + r))*CD + hh*HD + cc] = w;
            }
        }
}

// ============================================================
// Row softmax, unchanged
// ============================================================
__global__ __launch_bounds__(256) void softmax_kernel()
{
    __shared__ float sm[8];
    float* p = g_S + (size_t)blockIdx.x * SEQ;
    float4* p4 = (float4*)p;
    const int tid = threadIdx.x;

    float4 v0 = p4[tid];
    float4 v1 = p4[tid + 256];
    float mx = fmaxf(fmaxf(fmaxf(v0.x,v0.y), fmaxf(v0.z,v0.w)),
                     fmaxf(fmaxf(v1.x,v1.y), fmaxf(v1.z,v1.w)));
    #pragma unroll
    for (int o = 16; o; o >>= 1) mx = fmaxf(mx, __shfl_xor_sync(0xffffffffu, mx, o));
    if ((tid & 31) == 0) sm[tid >> 5] = mx;
    __syncthreads();
    mx = sm[0];
    #pragma unroll
    for (int i = 1; i < 8; i++) mx = fmaxf(mx, sm[i]);
    __syncthreads();

    v0.x = __expf(v0.x - mx); v0.y = __expf(v0.y - mx);
    v0.z = __expf(v0.z - mx); v0.w = __expf(v0.w - mx);
    v1.x = __expf(v1.x - mx); v1.y = __expf(v1.y - mx);
    v1.z = __expf(v1.z - mx); v1.w = __expf(v1.w - mx);
    float s = (v0.x+v0.y+v0.z+v0.w) + (v1.x+v1.y+v1.z+v1.w);
    #pragma unroll
    for (int o = 16; o; o >>= 1) s += __shfl_xor_sync(0xffffffffu, s, o);
    if ((tid & 31) == 0) sm[tid >> 5] = s;
    __syncthreads();
    s = 0.f;
    #pragma unroll
    for (int i = 0; i < 8; i++) s += sm[i];
    float inv = 1.0f / s;

    v0.x*=inv; v0.y*=inv; v0.z*=inv; v0.w*=inv;
    v1.x*=inv; v1.y*=inv; v1.z*=inv; v1.w*=inv;
    p4[tid] = v0;
    p4[tid + 256] = v1;
}

// ---- epilogues ----
struct EpiQKV {
    __device__ void store2(int, int r, int c, float v0, float v1) const {
        int b = r >> 11, n = r & (SEQ-1);
        int s = c / CD; int rem = c - s*CD;
        int h = rem >> 6, d = rem & 63;
        float* dst = (s == 0) ? g_q : ((s == 1) ? g_k : g_v);
        *(float2*)&dst[(((size_t)b*NH + h)*SEQ + n)*HD + d] = make_float2(v0, v1);
    }
};
struct EpiS {
    __device__ void store2(int z, int r, int c, float v0, float v1) const {
        *(float2*)&g_S[((size_t)z*SEQ + r)*SEQ + c] = make_float2(v0, v1);
    }
};
struct EpiOut {
    float* out; const float* pb;
    __device__ void store2(int, int r, int c, float v0, float v1) const {
        *(float2*)&out[(size_t)r*CD + c] = make_float2(v0 + pb[c], v1 + pb[c+1]);
    }
};

extern "C" void kernel_launch(void* const* d_in, const int* /*in_sizes*/, int /*n_in*/,
                              void* d_out, int /*out_size*/)
{
    const float* x      = (const float*)d_in[0];
    const float* qkv_w  = (const float*)d_in[1];
    const float* proj_w = (const float*)d_in[2];
    const float* proj_b = (const float*)d_in[3];
    const float* fp     = (const float*)d_in[4];
    float* out = (float*)d_out;

    float *p_qf, *p_kf, *p_Ot;
    cudaGetSymbolAddress((void**)&p_qf, g_qf);
    cudaGetSymbolAddress((void**)&p_kf, g_kf);
    cudaGetSymbolAddress((void**)&p_Ot, g_Ot);

    // 1. filter taps
    filter_kernel<<<dim3(SEQ/256, NH), 256>>>(fp);
    // 2. QKV projection
    mma_nt<<<dim3(QD/128, MROWS/128, 1), 256>>>(x, qkv_w, CD,
                                                (size_t)0, (size_t)0, EpiQKV{});
    // 3. spectral filtering (q scale folded)
    mma_circ<<<dim3(SEQ/128, BB*NH), 256>>>();
    // 4. attention scores
    mma_nt<<<dim3(SEQ/128, SEQ/128, BB*NH), 256>>>(p_qf, p_kf, HD,
                                                   (size_t)SEQ*HD, (size_t)SEQ*HD, EpiS{});
    // 5. softmax
    softmax_kernel<<<BB*NH*SEQ, 256>>>();
    // 6. P@V -> merged layout
    mma_pv<<<dim3(SEQ/128, BB*NH), 256>>>();
    // 7. output projection + bias
    mma_nt<<<dim3(CD/128, MROWS/128, 1), 256>>>(p_Ot, proj_w, CD,
                                                (size_t)0, (size_t)0, EpiOut{out, proj_b});
}

// round 6
// speedup vs baseline: 1.7121x; 1.2305x over previous
#include <cuda_runtime.h>
#include <math.h>

#ifndef M_PI
#define M_PI 3.14159265358979323846
#endif

namespace {
constexpr int BB  = 2;
constexpr int NH  = 12;
constexpr int SEQ = 2048;
constexpr int HD  = 64;
constexpr int CD  = 768;
constexpr int QD  = 2304;
constexpr int MROWS = BB * SEQ;  // 4096
constexpr int KSTR = 68;         // smem stride for 64-wide K tiles (bank-safe)
}

// ---- scratch ----
__device__ float g_q [BB*NH*SEQ*HD];
__device__ float g_k [BB*NH*SEQ*HD];
__device__ float g_v [BB*NH*SEQ*HD];
__device__ float g_qf[BB*NH*SEQ*HD];
__device__ float g_kf[BB*NH*SEQ*HD];
__device__ float g_c [NH*SEQ];
__device__ float g_Ot[BB*SEQ*CD];

// ============================================================
// mma helpers
// ============================================================
__device__ __forceinline__ unsigned f2tf(float x) {
    unsigned r;
    asm("cvt.rna.tf32.f32 %0, %1;" : "=r"(r) : "f"(x));
    return r;
}
__device__ __forceinline__ void split_tf(float x, unsigned& hi, unsigned& lo) {
    hi = f2tf(x);
    float l = x - __uint_as_float(hi);
    lo = f2tf(l);
}
__device__ __forceinline__ void mma8(float* c, const unsigned* a, const unsigned* b) {
    asm volatile(
        "mma.sync.aligned.m16n8k8.row.col.f32.tf32.tf32.f32 "
        "{%0,%1,%2,%3}, {%4,%5,%6,%7}, {%8,%9}, {%0,%1,%2,%3};"
        : "+f"(c[0]), "+f"(c[1]), "+f"(c[2]), "+f"(c[3])
        : "r"(a[0]), "r"(a[1]), "r"(a[2]), "r"(a[3]), "r"(b[0]), "r"(b[1]));
}
__device__ __forceinline__ void mma16bf(float* c, const unsigned* a, const unsigned* b) {
    asm volatile(
        "mma.sync.aligned.m16n8k16.row.col.f32.bf16.bf16.f32 "
        "{%0,%1,%2,%3}, {%4,%5,%6,%7}, {%8,%9}, {%0,%1,%2,%3};"
        : "+f"(c[0]), "+f"(c[1]), "+f"(c[2]), "+f"(c[3])
        : "r"(a[0]), "r"(a[1]), "r"(a[2]), "r"(a[3]), "r"(b[0]), "r"(b[1]));
}
// pack (even,odd) f32 pair into bf16x2 hi + residual lo (even=lower half)
__device__ __forceinline__ void split_bf16_pair(float xe, float xo, unsigned& hi, unsigned& lo) {
    unsigned h;
    asm("cvt.rn.bf16x2.f32 %0, %1, %2;" : "=r"(h) : "f"(xo), "f"(xe));
    float re = xe - __uint_as_float(h << 16);
    float ro = xo - __uint_as_float(h & 0xffff0000u);
    unsigned l;
    asm("cvt.rn.bf16x2.f32 %0, %1, %2;" : "=r"(l) : "f"(ro), "f"(re));
    hi = h; lo = l;
}

// Load + split one A operand pair from m-major smem [.][36]
__device__ __forceinline__ void load_a_frag(const float* ap, unsigned* ah, unsigned* al) {
    float x0 = ap[0];
    float x1 = ap[8*36];
    float x2 = ap[4];
    float x3 = ap[8*36 + 4];
    split_tf(x0, ah[0], al[0]);
    split_tf(x1, ah[1], al[1]);
    split_tf(x2, ah[2], al[2]);
    split_tf(x3, ah[3], al[3]);
}

// ============================================================
// Filter taps (closed form)
// ============================================================
__global__ void filter_kernel(const float* __restrict__ fp)
{
    int h = blockIdx.y;
    int u = blockIdx.x * blockDim.x + threadIdx.x;
    if (u >= SEQ) return;

    double p   = (double)fp[h];
    double sig = 1.0 / (1.0 + exp(-p));
    double md  = floor((double)SEQ * sig);
    int    m   = (int)md;
    double alpha = 4.0 / (double)SEQ;
    double theta = 2.0 * M_PI * (double)u / (double)SEQ;
    double wr = cos(theta), wi = sin(theta);
    double am = theta * (double)m;
    double wmr = cos(am), wmi = sin(am);

    double s1r;
    if (u == 0) {
        s1r = md;
    } else {
        double nr = 1.0 - wmr, ni = -wmi;
        double dr = 1.0 - wr,  di = -wi;
        double den = dr*dr + di*di;
        s1r = (nr*dr + ni*di) / den;
    }
    double e1 = exp(-alpha * (double)(SEQ - m));
    double ea = exp(-alpha);
    double nr2 = 1.0 - e1*wmr, ni2 = e1*wmi;
    double dr2 = 1.0 - ea*wr,  di2 = -ea*wi;
    double den2 = dr2*dr2 + di2*di2;
    double tr = (nr2*dr2 + ni2*di2) / den2;
    double ti = (ni2*dr2 - nr2*di2) / den2;
    double s2r = wmr*tr - wmi*ti;

    g_c[h*SEQ + u] = (float)((s1r + s2r) / (double)SEQ);
}

// ============================================================
// NT tensor-core GEMM (tf32 split): C[m,n] = sum_k A[m,k]*B[n,k]
// ============================================================
template<class Epi>
__global__ __launch_bounds__(256) void mma_nt(const float* __restrict__ A,
                                              const float* __restrict__ B,
                                              int K, size_t sA, size_t sB, Epi epi)
{
    __shared__ float As[128*36];
    __shared__ float Bs[128*36];
    const int m0 = blockIdx.y * 128, n0 = blockIdx.x * 128;
    const float* Ab = A + (size_t)blockIdx.z * sA;
    const float* Bb = B + (size_t)blockIdx.z * sB;
    const int tid = threadIdx.x, lane = tid & 31, wid = tid >> 5;
    const int wm = (wid >> 1) * 32, wn = (wid & 1) * 64;
    const int g = lane >> 2, t = lane & 3;
    const int sm = tid >> 3, skq = tid & 7;

    float C[2][8][4] = {};

    for (int k0 = 0; k0 < K; k0 += 32) {
        #pragma unroll
        for (int j = 0; j < 4; j++) {
            int m = sm + 32*j;
            float4 a4 = *(const float4*)(Ab + (size_t)(m0+m)*K + k0 + skq*4);
            *(float4*)&As[m*36 + skq*4] = a4;
            float4 b4 = *(const float4*)(Bb + (size_t)(n0+m)*K + k0 + skq*4);
            *(float4*)&Bs[m*36 + skq*4] = b4;
        }
        __syncthreads();
        #pragma unroll
        for (int ko = 0; ko < 32; ko += 8) {
            unsigned ah[2][4], al[2][4];
            #pragma unroll
            for (int im = 0; im < 2; im++)
                load_a_frag(&As[(wm + im*16 + g)*36 + ko + t], ah[im], al[im]);
            #pragma unroll
            for (int jn = 0; jn < 8; jn++) {
                const float* bp = &Bs[(wn + jn*8 + g)*36 + ko + t];
                unsigned bh[2], bl[2];
                split_tf(bp[0], bh[0], bl[0]);
                split_tf(bp[4], bh[1], bl[1]);
                #pragma unroll
                for (int im = 0; im < 2; im++) {
                    mma8(C[im][jn], ah[im], bh);
                    mma8(C[im][jn], ah[im], bl);
                    mma8(C[im][jn], al[im], bh);
                }
            }
        }
        __syncthreads();
    }
    #pragma unroll
    for (int im = 0; im < 2; im++)
        #pragma unroll
        for (int jn = 0; jn < 8; jn++) {
            int r  = m0 + wm + im*16 + g;
            int cc = n0 + wn + jn*8 + 2*t;
            epi.store2(blockIdx.z, r,   cc, C[im][jn][0], C[im][jn][1]);
            epi.store2(blockIdx.z, r+8, cc, C[im][jn][2], C[im][jn][3]);
        }
}

// ============================================================
// Circulant filter as tensor-core GEMM (tf32 split).
// out[n, 0:64]=q_filt (x0.125 folded), out[n,64:128]=k_filt.
// ============================================================
__global__ __launch_bounds__(256) void mma_circ()
{
    __shared__ float As[128*36];
    __shared__ float Bs[32*136];
    __shared__ float csh[SEQ];

    const int m0 = blockIdx.x * 128;
    const int bh = blockIdx.y;
    const int h  = bh % NH;
    const float* srcq = g_q + (size_t)bh * SEQ * HD;
    const float* srck = g_k + (size_t)bh * SEQ * HD;

    const int tid = threadIdx.x, lane = tid & 31, wid = tid >> 5;
    const int wm = (wid >> 1) * 32, wn = (wid & 1) * 64;
    const int g = lane >> 2, t = lane & 3;

    for (int i = tid; i < SEQ; i += 256) csh[i] = g_c[h*SEQ + i];
    __syncthreads();

    float C[2][8][4] = {};

    const int amm = (tid & 7) + 8*(tid >> 5);
    const int akr = (tid >> 3) & 3;
    const int nq = tid & 31, kb = tid >> 5;
    const float* bsrc = (nq < 16) ? srcq : srck;
    const int ncol = (nq & 15) * 4;

    for (int k0 = 0; k0 < SEQ; k0 += 32) {
        #pragma unroll
        for (int jj = 0; jj < 2; jj++) {
            int mm = amm + 64*jj;
            #pragma unroll
            for (int c = 0; c < 8; c++) {
                int kk = akr + 4*c;
                As[mm*36 + kk] = csh[(m0 + mm - k0 - kk) & (SEQ-1)];
            }
        }
        #pragma unroll
        for (int jb = 0; jb < 4; jb++) {
            int kk = kb + 8*jb;
            float4 b4 = *(const float4*)(bsrc + (size_t)(k0+kk)*HD + ncol);
            *(float4*)&Bs[kk*136 + nq*4] = b4;
        }
        __syncthreads();
        #pragma unroll
        for (int ko = 0; ko < 32; ko += 8) {
            unsigned ah[2][4], al[2][4];
            #pragma unroll
            for (int im = 0; im < 2; im++)
                load_a_frag(&As[(wm + im*16 + g)*36 + ko + t], ah[im], al[im]);
            #pragma unroll
            for (int jn = 0; jn < 8; jn++) {
                const float* bp = &Bs[(ko + t)*136 + wn + jn*8 + g];
                unsigned bh2[2], bl2[2];
                split_tf(bp[0],     bh2[0], bl2[0]);
                split_tf(bp[4*136], bh2[1], bl2[1]);
                #pragma unroll
                for (int im = 0; im < 2; im++) {
                    mma8(C[im][jn], ah[im], bh2);
                    mma8(C[im][jn], ah[im], bl2);
                    mma8(C[im][jn], al[im], bh2);
                }
            }
        }
        __syncthreads();
    }

    float* qf = g_qf + (size_t)bh * SEQ * HD;
    float* kf = g_kf + (size_t)bh * SEQ * HD;
    #pragma unroll
    for (int im = 0; im < 2; im++)
        #pragma unroll
        for (int jn = 0; jn < 8; jn++) {
            int cc = wn + jn*8 + 2*t;
            #pragma unroll
            for (int half = 0; half < 2; half++) {
                int r = m0 + wm + im*16 + g + 8*half;
                float v0 = C[im][jn][2*half], v1 = C[im][jn][2*half+1];
                if (cc < 64) {
                    *(float2*)&qf[(size_t)r*HD + cc] = make_float2(v0*0.125f, v1*0.125f);
                } else {
                    *(float2*)&kf[(size_t)r*HD + cc - 64] = make_float2(v0, v1);
                }
            }
        }
}

// ============================================================
// Fused flash attention: S = Qf Kf^T (tf32 split), online softmax,
// O += P V (bf16 split). Writes merged (b,n,h*64+d) layout.
// grid (SEQ/128, BB*NH), 256 threads (8 warps x 16 q-rows).
// ============================================================
__global__ __launch_bounds__(256) void flash_attn()
{
    __shared__ unsigned Khs[64*KSTR], Kls[64*KSTR];  // tf32 bits, [kv][d], d=64 wide
    __shared__ unsigned Vhs[64*36],   Vls[64*36];    // bf16x2 pairs, [d][kvpair]

    const int bh = blockIdx.y;
    const int m0 = blockIdx.x * 128;
    const float* qf = g_qf + (size_t)bh * SEQ * HD;
    const float* kf = g_kf + (size_t)bh * SEQ * HD;
    const float* vv = g_v  + (size_t)bh * SEQ * HD;

    const int tid = threadIdx.x, lane = tid & 31, w = tid >> 5;
    const int g = lane >> 2, t = lane & 3;

    // persistent Q fragments (tf32 split), rows m0+16w+g / +8
    unsigned qh[8][4], ql[8][4];
    {
        const float* r0 = qf + (size_t)(m0 + 16*w + g) * HD;
        const float* r1 = r0 + 8*HD;
        #pragma unroll
        for (int c = 0; c < 8; c++) {
            split_tf(r0[8*c + t],     qh[c][0], ql[c][0]);
            split_tf(r1[8*c + t],     qh[c][1], ql[c][1]);
            split_tf(r0[8*c + t + 4], qh[c][2], ql[c][2]);
            split_tf(r1[8*c + t + 4], qh[c][3], ql[c][3]);
        }
    }

    float O[8][4] = {};
    float mr0 = -1e30f, mr1 = -1e30f, l0 = 0.f, l1 = 0.f;

    for (int k0 = 0; k0 < SEQ; k0 += 64) {
        // ---- stage K tile (pre-split tf32), [kv][d] stride KSTR ----
        #pragma unroll
        for (int j = 0; j < 4; j++) {
            int r = tid >> 2, c4 = ((tid & 3) + 4*j) * 4;
            float4 kx = *(const float4*)(kf + (size_t)(k0 + r)*HD + c4);
            unsigned h0,lo0,h1,lo1,h2,lo2,h3,lo3;
            split_tf(kx.x, h0, lo0); split_tf(kx.y, h1, lo1);
            split_tf(kx.z, h2, lo2); split_tf(kx.w, h3, lo3);
            unsigned* kh = &Khs[r*KSTR + c4];
            unsigned* kl = &Kls[r*KSTR + c4];
            kh[0]=h0; kh[1]=h1; kh[2]=h2; kh[3]=h3;
            kl[0]=lo0; kl[1]=lo1; kl[2]=lo2; kl[3]=lo3;
        }
        // ---- stage V tile (pre-split bf16 pairs, transposed) ----
        #pragma unroll
        for (int j = 0; j < 2; j++) {
            int i = tid + 256*j;
            int kp = i & 31, d0 = (i >> 5) * 4;
            float4 a = *(const float4*)(vv + (size_t)(k0 + 2*kp)*HD + d0);
            float4 b = *(const float4*)(vv + (size_t)(k0 + 2*kp + 1)*HD + d0);
            const float ae[4] = {a.x, a.y, a.z, a.w};
            const float be[4] = {b.x, b.y, b.z, b.w};
            #pragma unroll
            for (int e = 0; e < 4; e++) {
                unsigned hi, lo;
                split_bf16_pair(ae[e], be[e], hi, lo);
                Vhs[(d0+e)*36 + kp] = hi;
                Vls[(d0+e)*36 + kp] = lo;
            }
        }
        __syncthreads();

        // ---- S = Qf Kf^T ----
        float S[8][4] = {};
        #pragma unroll
        for (int ko = 0; ko < 8; ko++) {
            #pragma unroll
            for (int jn = 0; jn < 8; jn++) {
                const unsigned* kh = &Khs[(8*jn + g)*KSTR + 8*ko + t];
                const unsigned* kl = &Kls[(8*jn + g)*KSTR + 8*ko + t];
                unsigned bh2[2] = { kh[0], kh[4] };
                unsigned bl2[2] = { kl[0], kl[4] };
                mma8(S[jn], qh[ko], bh2);
                mma8(S[jn], qh[ko], bl2);
                mma8(S[jn], ql[ko], bh2);
            }
        }

        // ---- online softmax ----
        float rm0 = -1e30f, rm1 = -1e30f;
        #pragma unroll
        for (int jn = 0; jn < 8; jn++) {
            rm0 = fmaxf(rm0, fmaxf(S[jn][0], S[jn][1]));
            rm1 = fmaxf(rm1, fmaxf(S[jn][2], S[jn][3]));
        }
        rm0 = fmaxf(rm0, __shfl_xor_sync(0xffffffffu, rm0, 1));
        rm0 = fmaxf(rm0, __shfl_xor_sync(0xffffffffu, rm0, 2));
        rm1 = fmaxf(rm1, __shfl_xor_sync(0xffffffffu, rm1, 1));
        rm1 = fmaxf(rm1, __shfl_xor_sync(0xffffffffu, rm1, 2));
        float mn0 = fmaxf(mr0, rm0), mn1 = fmaxf(mr1, rm1);
        float a0 = __expf(mr0 - mn0), a1 = __expf(mr1 - mn1);
        mr0 = mn0; mr1 = mn1;

        float ps0 = 0.f, ps1 = 0.f;
        unsigned ph[8][2], pl[8][2];
        #pragma unroll
        for (int jn = 0; jn < 8; jn++) {
            float p0 = __expf(S[jn][0] - mn0);
            float p1 = __expf(S[jn][1] - mn0);
            float p2 = __expf(S[jn][2] - mn1);
            float p3 = __expf(S[jn][3] - mn1);
            ps0 += p0 + p1; ps1 += p2 + p3;
            split_bf16_pair(p0, p1, ph[jn][0], pl[jn][0]);
            split_bf16_pair(p2, p3, ph[jn][1], pl[jn][1]);
        }
        l0 = l0*a0 + ps0; l1 = l1*a1 + ps1;
        #pragma unroll
        for (int jn = 0; jn < 8; jn++) {
            O[jn][0] *= a0; O[jn][1] *= a0; O[jn][2] *= a1; O[jn][3] *= a1;
        }

        // ---- O += P V (bf16 split, m16n8k16) ----
        #pragma unroll
        for (int kc = 0; kc < 4; kc++) {
            unsigned ah2[4] = { ph[2*kc][0], ph[2*kc][1], ph[2*kc+1][0], ph[2*kc+1][1] };
            unsigned al2[4] = { pl[2*kc][0], pl[2*kc][1], pl[2*kc+1][0], pl[2*kc+1][1] };
            #pragma unroll
            for (int jn = 0; jn < 8; jn++) {
                const unsigned* vh = &Vhs[(8*jn + g)*36 + 8*kc + t];
                const unsigned* vl = &Vls[(8*jn + g)*36 + 8*kc + t];
                unsigned bh2[2] = { vh[0], vh[4] };
                unsigned bl2[2] = { vl[0], vl[4] };
                mma16bf(O[jn], ah2, bh2);
                mma16bf(O[jn], ah2, bl2);
                mma16bf(O[jn], al2, bh2);
            }
        }
        __syncthreads();
    }

    // ---- epilogue ----
    l0 += __shfl_xor_sync(0xffffffffu, l0, 1);
    l0 += __shfl_xor_sync(0xffffffffu, l0, 2);
    l1 += __shfl_xor_sync(0xffffffffu, l1, 1);
    l1 += __shfl_xor_sync(0xffffffffu, l1, 2);
    float i0 = 1.f / l0, i1 = 1.f / l1;

    const int b = bh / NH, hh = bh - b*NH;
    const int r0 = m0 + 16*w + g, r1 = r0 + 8;
    #pragma unroll
    for (int jn = 0; jn < 8; jn++) {
        int cc = 8*jn + 2*t;
        *(float2*)&g_Ot[((size_t)(b*SEQ + r0))*CD + hh*HD + cc] =
            make_float2(O[jn][0]*i0, O[jn][1]*i0);
        *(float2*)&g_Ot[((size_t)(b*SEQ + r1))*CD + hh*HD + cc] =
            make_float2(O[jn][2]*i1, O[jn][3]*i1);
    }
}

// ---- epilogues ----
struct EpiQKV {
    __device__ void store2(int, int r, int c, float v0, float v1) const {
        int b = r >> 11, n = r & (SEQ-1);
        int s = c / CD; int rem = c - s*CD;
        int h = rem >> 6, d = rem & 63;
        float* dst = (s == 0) ? g_q : ((s == 1) ? g_k : g_v);
        *(float2*)&dst[(((size_t)b*NH + h)*SEQ + n)*HD + d] = make_float2(v0, v1);
    }
};
struct EpiOut {
    float* out; const float* pb;
    __device__ void store2(int, int r, int c, float v0, float v1) const {
        *(float2*)&out[(size_t)r*CD + c] = make_float2(v0 + pb[c], v1 + pb[c+1]);
    }
};

extern "C" void kernel_launch(void* const* d_in, const int* /*in_sizes*/, int /*n_in*/,
                              void* d_out, int /*out_size*/)
{
    const float* x      = (const float*)d_in[0];
    const float* qkv_w  = (const float*)d_in[1];
    const float* proj_w = (const float*)d_in[2];
    const float* proj_b = (const float*)d_in[3];
    const float* fp     = (const float*)d_in[4];
    float* out = (float*)d_out;

    float *p_Ot;
    cudaGetSymbolAddress((void**)&p_Ot, g_Ot);

    // 1. filter taps
    filter_kernel<<<dim3(SEQ/256, NH), 256>>>(fp);
    // 2. QKV projection
    mma_nt<<<dim3(QD/128, MROWS/128, 1), 256>>>(x, qkv_w, CD,
                                                (size_t)0, (size_t)0, EpiQKV{});
    // 3. spectral filtering (q scale folded)
    mma_circ<<<dim3(SEQ/128, BB*NH), 256>>>();
    // 4-6. fused attention (QK^T + softmax + PV)
    flash_attn<<<dim3(SEQ/128, BB*NH), 256>>>();
    // 7. output projection + bias
    mma_nt<<<dim3(CD/128, MROWS/128, 1), 256>>>(p_Ot, proj_w, CD,
                                                (size_t)0, (size_t)0, EpiOut{out, proj_b});
}

// round 7
// speedup vs baseline: 2.2978x; 1.3421x over previous
#include <cuda_runtime.h>
#include <math.h>

#ifndef M_PI
#define M_PI 3.14159265358979323846
#endif

namespace {
constexpr int BB  = 2;
constexpr int NH  = 12;
constexpr int SEQ = 2048;
constexpr int HD  = 64;
constexpr int CD  = 768;
constexpr int QD  = 2304;
constexpr int MROWS = BB * SEQ;  // 4096
}

// ---- scratch ----
__device__ float g_q [BB*NH*SEQ*HD];
__device__ float g_k [BB*NH*SEQ*HD];
__device__ float g_v [BB*NH*SEQ*HD];
__device__ float g_qf[BB*NH*SEQ*HD];
__device__ float g_kf[BB*NH*SEQ*HD];
__device__ float g_c [NH*SEQ];
__device__ float g_Ot[BB*SEQ*CD];

// ============================================================
// mma helpers
// ============================================================
__device__ __forceinline__ unsigned f2tf(float x) {
    unsigned r;
    asm("cvt.rna.tf32.f32 %0, %1;" : "=r"(r) : "f"(x));
    return r;
}
__device__ __forceinline__ void split_tf(float x, unsigned& hi, unsigned& lo) {
    hi = f2tf(x);
    float l = x - __uint_as_float(hi);
    lo = f2tf(l);
}
__device__ __forceinline__ void mma8(float* c, const unsigned* a, const unsigned* b) {
    asm volatile(
        "mma.sync.aligned.m16n8k8.row.col.f32.tf32.tf32.f32 "
        "{%0,%1,%2,%3}, {%4,%5,%6,%7}, {%8,%9}, {%0,%1,%2,%3};"
        : "+f"(c[0]), "+f"(c[1]), "+f"(c[2]), "+f"(c[3])
        : "r"(a[0]), "r"(a[1]), "r"(a[2]), "r"(a[3]), "r"(b[0]), "r"(b[1]));
}
__device__ __forceinline__ void mma16bf(float* c, const unsigned* a, const unsigned* b) {
    asm volatile(
        "mma.sync.aligned.m16n8k16.row.col.f32.bf16.bf16.f32 "
        "{%0,%1,%2,%3}, {%4,%5,%6,%7}, {%8,%9}, {%0,%1,%2,%3};"
        : "+f"(c[0]), "+f"(c[1]), "+f"(c[2]), "+f"(c[3])
        : "r"(a[0]), "r"(a[1]), "r"(a[2]), "r"(a[3]), "r"(b[0]), "r"(b[1]));
}
// pack (even,odd) f32 pair into bf16x2 hi + residual lo (even=lower half)
__device__ __forceinline__ void split_bf16_pair(float xe, float xo, unsigned& hi, unsigned& lo) {
    unsigned h;
    asm("cvt.rn.bf16x2.f32 %0, %1, %2;" : "=r"(h) : "f"(xo), "f"(xe));
    float re = xe - __uint_as_float(h << 16);
    float ro = xo - __uint_as_float(h & 0xffff0000u);
    unsigned l;
    asm("cvt.rn.bf16x2.f32 %0, %1, %2;" : "=r"(l) : "f"(ro), "f"(re));
    hi = h; lo = l;
}

// Load + split one A operand pair from m-major smem [.][36] (tf32 path)
__device__ __forceinline__ void load_a_frag(const float* ap, unsigned* ah, unsigned* al) {
    float x0 = ap[0];
    float x1 = ap[8*36];
    float x2 = ap[4];
    float x3 = ap[8*36 + 4];
    split_tf(x0, ah[0], al[0]);
    split_tf(x1, ah[1], al[1]);
    split_tf(x2, ah[2], al[2]);
    split_tf(x3, ah[3], al[3]);
}

// ============================================================
// Filter taps (closed form)
// ============================================================
__global__ void filter_kernel(const float* __restrict__ fp)
{
    int h = blockIdx.y;
    int u = blockIdx.x * blockDim.x + threadIdx.x;
    if (u >= SEQ) return;

    double p   = (double)fp[h];
    double sig = 1.0 / (1.0 + exp(-p));
    double md  = floor((double)SEQ * sig);
    int    m   = (int)md;
    double alpha = 4.0 / (double)SEQ;
    double theta = 2.0 * M_PI * (double)u / (double)SEQ;
    double wr = cos(theta), wi = sin(theta);
    double am = theta * (double)m;
    double wmr = cos(am), wmi = sin(am);

    double s1r;
    if (u == 0) {
        s1r = md;
    } else {
        double nr = 1.0 - wmr, ni = -wmi;
        double dr = 1.0 - wr,  di = -wi;
        double den = dr*dr + di*di;
        s1r = (nr*dr + ni*di) / den;
    }
    double e1 = exp(-alpha * (double)(SEQ - m));
    double ea = exp(-alpha);
    double nr2 = 1.0 - e1*wmr, ni2 = e1*wmi;
    double dr2 = 1.0 - ea*wr,  di2 = -ea*wi;
    double den2 = dr2*dr2 + di2*di2;
    double tr = (nr2*dr2 + ni2*di2) / den2;
    double ti = (ni2*dr2 - nr2*di2) / den2;
    double s2r = wmr*tr - wmi*ti;

    g_c[h*SEQ + u] = (float)((s1r + s2r) / (double)SEQ);
}

// ============================================================
// NT tensor-core GEMM (tf32 split): C[m,n] = sum_k A[m,k]*B[n,k]
// (QKV + output projection; unchanged, proven)
// ============================================================
template<class Epi>
__global__ __launch_bounds__(256) void mma_nt(const float* __restrict__ A,
                                              const float* __restrict__ B,
                                              int K, size_t sA, size_t sB, Epi epi)
{
    __shared__ float As[128*36];
    __shared__ float Bs[128*36];
    const int m0 = blockIdx.y * 128, n0 = blockIdx.x * 128;
    const float* Ab = A + (size_t)blockIdx.z * sA;
    const float* Bb = B + (size_t)blockIdx.z * sB;
    const int tid = threadIdx.x, lane = tid & 31, wid = tid >> 5;
    const int wm = (wid >> 1) * 32, wn = (wid & 1) * 64;
    const int g = lane >> 2, t = lane & 3;
    const int sm = tid >> 3, skq = tid & 7;

    float C[2][8][4] = {};

    for (int k0 = 0; k0 < K; k0 += 32) {
        #pragma unroll
        for (int j = 0; j < 4; j++) {
            int m = sm + 32*j;
            float4 a4 = *(const float4*)(Ab + (size_t)(m0+m)*K + k0 + skq*4);
            *(float4*)&As[m*36 + skq*4] = a4;
            float4 b4 = *(const float4*)(Bb + (size_t)(n0+m)*K + k0 + skq*4);
            *(float4*)&Bs[m*36 + skq*4] = b4;
        }
        __syncthreads();
        #pragma unroll
        for (int ko = 0; ko < 32; ko += 8) {
            unsigned ah[2][4], al[2][4];
            #pragma unroll
            for (int im = 0; im < 2; im++)
                load_a_frag(&As[(wm + im*16 + g)*36 + ko + t], ah[im], al[im]);
            #pragma unroll
            for (int jn = 0; jn < 8; jn++) {
                const float* bp = &Bs[(wn + jn*8 + g)*36 + ko + t];
                unsigned bh[2], bl[2];
                split_tf(bp[0], bh[0], bl[0]);
                split_tf(bp[4], bh[1], bl[1]);
                #pragma unroll
                for (int im = 0; im < 2; im++) {
                    mma8(C[im][jn], ah[im], bh);
                    mma8(C[im][jn], ah[im], bl);
                    mma8(C[im][jn], al[im], bh);
                }
            }
        }
        __syncthreads();
    }
    #pragma unroll
    for (int im = 0; im < 2; im++)
        #pragma unroll
        for (int jn = 0; jn < 8; jn++) {
            int r  = m0 + wm + im*16 + g;
            int cc = n0 + wn + jn*8 + 2*t;
            epi.store2(blockIdx.z, r,   cc, C[im][jn][0], C[im][jn][1]);
            epi.store2(blockIdx.z, r+8, cc, C[im][jn][2], C[im][jn][3]);
        }
}

// ============================================================
// Circulant filter, bf16-split tensor-core version.
// out[n, 0:64]=q_filt (x0.125 folded), out[n,64:128]=k_filt.
// A[128 rows][32 k] generated from taps as bf16x2 pairs,
// B[128 cols][32 k] staged from q|k as bf16x2 pairs.
// ============================================================
__global__ __launch_bounds__(256) void mma_circ()
{
    __shared__ unsigned Ah[128*20], Al[128*20];   // [row][kpair], stride 20
    __shared__ unsigned Bh[128*17], Bl[128*17];   // [col][kpair], stride 17
    __shared__ float csh[SEQ];

    const int m0 = blockIdx.x * 128;
    const int bh = blockIdx.y;
    const int h  = bh % NH;
    const float* srcq = g_q + (size_t)bh * SEQ * HD;
    const float* srck = g_k + (size_t)bh * SEQ * HD;

    const int tid = threadIdx.x, lane = tid & 31, wid = tid >> 5;
    const int wm = (wid >> 1) * 32, wn = (wid & 1) * 64;
    const int g = lane >> 2, t = lane & 3;

    for (int i = tid; i < SEQ; i += 256) csh[i] = g_c[h*SEQ + i];
    __syncthreads();

    float C[2][8][4] = {};

    for (int k0 = 0; k0 < SEQ; k0 += 32) {
        // ---- generate A tile from taps (pre-split bf16 pairs) ----
        #pragma unroll
        for (int it = 0; it < 8; it++) {
            int i = tid + 256*it;
            int mm = i >> 4, kp = i & 15;
            int base = m0 + mm - k0 - 2*kp;
            float ce = csh[base & (SEQ-1)];
            float co = csh[(base - 1) & (SEQ-1)];
            unsigned hi, lo;
            split_bf16_pair(ce, co, hi, lo);
            Ah[mm*20 + kp] = hi;
            Al[mm*20 + kp] = lo;
        }
        // ---- stage B tile (transposed q|k, pre-split bf16 pairs) ----
        #pragma unroll
        for (int it = 0; it < 8; it++) {
            int i = tid + 256*it;
            int n = i & 127, p = i >> 7;
            const float* src = (n < 64) ? srcq : srck;
            int col = n & 63;
            float e = src[(size_t)(k0 + 2*p)*HD + col];
            float o = src[(size_t)(k0 + 2*p + 1)*HD + col];
            unsigned hi, lo;
            split_bf16_pair(e, o, hi, lo);
            Bh[n*17 + p] = hi;
            Bl[n*17 + p] = lo;
        }
        __syncthreads();

        #pragma unroll
        for (int c = 0; c < 2; c++) {
            unsigned ah[2][4], al[2][4];
            #pragma unroll
            for (int im = 0; im < 2; im++) {
                const unsigned* ap = &Ah[(wm + 16*im + g)*20 + 8*c + t];
                const unsigned* alp = &Al[(wm + 16*im + g)*20 + 8*c + t];
                ah[im][0] = ap[0];      ah[im][1] = ap[8*20];
                ah[im][2] = ap[4];      ah[im][3] = ap[8*20 + 4];
                al[im][0] = alp[0];     al[im][1] = alp[8*20];
                al[im][2] = alp[4];     al[im][3] = alp[8*20 + 4];
            }
            #pragma unroll
            for (int jn = 0; jn < 8; jn++) {
                const unsigned* bp  = &Bh[(wn + 8*jn + g)*17 + 8*c + t];
                const unsigned* blp = &Bl[(wn + 8*jn + g)*17 + 8*c + t];
                unsigned bh2[2] = { bp[0],  bp[4]  };
                unsigned bl2[2] = { blp[0], blp[4] };
                #pragma unroll
                for (int im = 0; im < 2; im++) {
                    mma16bf(C[im][jn], ah[im], bh2);
                    mma16bf(C[im][jn], ah[im], bl2);
                    mma16bf(C[im][jn], al[im], bh2);
                }
            }
        }
        __syncthreads();
    }

    float* qf = g_qf + (size_t)bh * SEQ * HD;
    float* kf = g_kf + (size_t)bh * SEQ * HD;
    #pragma unroll
    for (int im = 0; im < 2; im++)
        #pragma unroll
        for (int jn = 0; jn < 8; jn++) {
            int cc = wn + jn*8 + 2*t;
            #pragma unroll
            for (int half = 0; half < 2; half++) {
                int r = m0 + wm + im*16 + g + 8*half;
                float v0 = C[im][jn][2*half], v1 = C[im][jn][2*half+1];
                if (cc < 64) {
                    *(float2*)&qf[(size_t)r*HD + cc] = make_float2(v0*0.125f, v1*0.125f);
                } else {
                    *(float2*)&kf[(size_t)r*HD + cc - 64] = make_float2(v0, v1);
                }
            }
        }
}

// ============================================================
// Fused flash attention, all-bf16-split mma:
// S = Qf Kf^T, online softmax, O += P V.
// grid (SEQ/128, BB*NH), 256 threads (8 warps x 16 q-rows), 2 blocks/SM.
// ============================================================
__global__ __launch_bounds__(256,2) void flash_attn()
{
    __shared__ unsigned Khs[64*36], Kls[64*36];   // bf16x2 pairs, [kv][dpair]
    __shared__ unsigned Vhs[64*36], Vls[64*36];   // bf16x2 pairs, [d][kvpair]

    const int bh = blockIdx.y;
    const int m0 = blockIdx.x * 128;
    const float* qf = g_qf + (size_t)bh * SEQ * HD;
    const float* kf = g_kf + (size_t)bh * SEQ * HD;
    const float* vv = g_v  + (size_t)bh * SEQ * HD;

    const int tid = threadIdx.x, lane = tid & 31, w = tid >> 5;
    const int g = lane >> 2, t = lane & 3;

    // persistent Q fragments (bf16 split, packed pairs), rows m0+16w+g / +8
    unsigned qh[4][4], ql[4][4];
    {
        const float* r0 = qf + (size_t)(m0 + 16*w + g) * HD;
        const float* r1 = r0 + 8*HD;
        #pragma unroll
        for (int c = 0; c < 4; c++) {
            split_bf16_pair(r0[16*c + 2*t],     r0[16*c + 2*t + 1], qh[c][0], ql[c][0]);
            split_bf16_pair(r1[16*c + 2*t],     r1[16*c + 2*t + 1], qh[c][1], ql[c][1]);
            split_bf16_pair(r0[16*c + 8 + 2*t], r0[16*c + 9 + 2*t], qh[c][2], ql[c][2]);
            split_bf16_pair(r1[16*c + 8 + 2*t], r1[16*c + 9 + 2*t], qh[c][3], ql[c][3]);
        }
    }

    float O[8][4] = {};
    float mr0 = -1e30f, mr1 = -1e30f, l0 = 0.f, l1 = 0.f;

    for (int k0 = 0; k0 < SEQ; k0 += 64) {
        // ---- stage K tile (pre-split bf16 pairs), [kv][dpair] stride 36 ----
        #pragma unroll
        for (int j = 0; j < 4; j++) {
            int r = tid >> 2, c4 = ((tid & 3) + 4*j) * 4;
            float4 kx = *(const float4*)(kf + (size_t)(k0 + r)*HD + c4);
            unsigned h01, l01, h23, l23;
            split_bf16_pair(kx.x, kx.y, h01, l01);
            split_bf16_pair(kx.z, kx.w, h23, l23);
            int p = ((tid & 3) + 4*j) * 2;
            Khs[r*36 + p] = h01; Khs[r*36 + p + 1] = h23;
            Kls[r*36 + p] = l01; Kls[r*36 + p + 1] = l23;
        }
        // ---- stage V tile (pre-split bf16 pairs, transposed) ----
        #pragma unroll
        for (int j = 0; j < 2; j++) {
            int i = tid + 256*j;
            int kp = i & 31, d0 = (i >> 5) * 4;
            float4 a = *(const float4*)(vv + (size_t)(k0 + 2*kp)*HD + d0);
            float4 b = *(const float4*)(vv + (size_t)(k0 + 2*kp + 1)*HD + d0);
            const float ae[4] = {a.x, a.y, a.z, a.w};
            const float be[4] = {b.x, b.y, b.z, b.w};
            #pragma unroll
            for (int e = 0; e < 4; e++) {
                unsigned hi, lo;
                split_bf16_pair(ae[e], be[e], hi, lo);
                Vhs[(d0+e)*36 + kp] = hi;
                Vls[(d0+e)*36 + kp] = lo;
            }
        }
        __syncthreads();

        // ---- S = Qf Kf^T (bf16 3-term split) ----
        float S[8][4] = {};
        #pragma unroll
        for (int c = 0; c < 4; c++) {
            #pragma unroll
            for (int jn = 0; jn < 8; jn++) {
                const unsigned* kh = &Khs[(8*jn + g)*36 + 8*c + t];
                const unsigned* kl = &Kls[(8*jn + g)*36 + 8*c + t];
                unsigned bh2[2] = { kh[0], kh[4] };
                unsigned bl2[2] = { kl[0], kl[4] };
                mma16bf(S[jn], qh[c], bh2);
                mma16bf(S[jn], qh[c], bl2);
                mma16bf(S[jn], ql[c], bh2);
            }
        }

        // ---- online softmax ----
        float rm0 = -1e30f, rm1 = -1e30f;
        #pragma unroll
        for (int jn = 0; jn < 8; jn++) {
            rm0 = fmaxf(rm0, fmaxf(S[jn][0], S[jn][1]));
            rm1 = fmaxf(rm1, fmaxf(S[jn][2], S[jn][3]));
        }
        rm0 = fmaxf(rm0, __shfl_xor_sync(0xffffffffu, rm0, 1));
        rm0 = fmaxf(rm0, __shfl_xor_sync(0xffffffffu, rm0, 2));
        rm1 = fmaxf(rm1, __shfl_xor_sync(0xffffffffu, rm1, 1));
        rm1 = fmaxf(rm1, __shfl_xor_sync(0xffffffffu, rm1, 2));
        float mn0 = fmaxf(mr0, rm0), mn1 = fmaxf(mr1, rm1);
        float a0 = __expf(mr0 - mn0), a1 = __expf(mr1 - mn1);
        mr0 = mn0; mr1 = mn1;

        #pragma unroll
        for (int jn = 0; jn < 8; jn++) {
            O[jn][0] *= a0; O[jn][1] *= a0; O[jn][2] *= a1; O[jn][3] *= a1;
        }

        // ---- P conversion + P@V in two halves (register relief) ----
        float ps0 = 0.f, ps1 = 0.f;
        #pragma unroll
        for (int half = 0; half < 2; half++) {
            unsigned ph[4][2], pl[4][2];
            #pragma unroll
            for (int q4 = 0; q4 < 4; q4++) {
                int jn = 4*half + q4;
                float p0 = __expf(S[jn][0] - mn0);
                float p1 = __expf(S[jn][1] - mn0);
                float p2 = __expf(S[jn][2] - mn1);
                float p3 = __expf(S[jn][3] - mn1);
                ps0 += p0 + p1; ps1 += p2 + p3;
                split_bf16_pair(p0, p1, ph[q4][0], pl[q4][0]);
                split_bf16_pair(p2, p3, ph[q4][1], pl[q4][1]);
            }
            #pragma unroll
            for (int kc2 = 0; kc2 < 2; kc2++) {
                int kc = 2*half + kc2;
                unsigned ah2[4] = { ph[2*kc2][0], ph[2*kc2][1], ph[2*kc2+1][0], ph[2*kc2+1][1] };
                unsigned al2[4] = { pl[2*kc2][0], pl[2*kc2][1], pl[2*kc2+1][0], pl[2*kc2+1][1] };
                #pragma unroll
                for (int jn = 0; jn < 8; jn++) {
                    const unsigned* vh = &Vhs[(8*jn + g)*36 + 8*kc + t];
                    const unsigned* vl = &Vls[(8*jn + g)*36 + 8*kc + t];
                    unsigned bh2[2] = { vh[0], vh[4] };
                    unsigned bl2[2] = { vl[0], vl[4] };
                    mma16bf(O[jn], ah2, bh2);
                    mma16bf(O[jn], ah2, bl2);
                    mma16bf(O[jn], al2, bh2);
                }
            }
        }
        l0 = l0*a0 + ps0; l1 = l1*a1 + ps1;
        __syncthreads();
    }

    // ---- epilogue ----
    l0 += __shfl_xor_sync(0xffffffffu, l0, 1);
    l0 += __shfl_xor_sync(0xffffffffu, l0, 2);
    l1 += __shfl_xor_sync(0xffffffffu, l1, 1);
    l1 += __shfl_xor_sync(0xffffffffu, l1, 2);
    float i0 = 1.f / l0, i1 = 1.f / l1;

    const int b = bh / NH, hh = bh - b*NH;
    const int r0 = m0 + 16*w + g, r1 = r0 + 8;
    #pragma unroll
    for (int jn = 0; jn < 8; jn++) {
        int cc = 8*jn + 2*t;
        *(float2*)&g_Ot[((size_t)(b*SEQ + r0))*CD + hh*HD + cc] =
            make_float2(O[jn][0]*i0, O[jn][1]*i0);
        *(float2*)&g_Ot[((size_t)(b*SEQ + r1))*CD + hh*HD + cc] =
            make_float2(O[jn][2]*i1, O[jn][3]*i1);
    }
}

// ---- epilogues ----
struct EpiQKV {
    __device__ void store2(int, int r, int c, float v0, float v1) const {
        int b = r >> 11, n = r & (SEQ-1);
        int s = c / CD; int rem = c - s*CD;
        int h = rem >> 6, d = rem & 63;
        float* dst = (s == 0) ? g_q : ((s == 1) ? g_k : g_v);
        *(float2*)&dst[(((size_t)b*NH + h)*SEQ + n)*HD + d] = make_float2(v0, v1);
    }
};
struct EpiOut {
    float* out; const float* pb;
    __device__ void store2(int, int r, int c, float v0, float v1) const {
        *(float2*)&out[(size_t)r*CD + c] = make_float2(v0 + pb[c], v1 + pb[c+1]);
    }
};

extern "C" void kernel_launch(void* const* d_in, const int* /*in_sizes*/, int /*n_in*/,
                              void* d_out, int /*out_size*/)
{
    const float* x      = (const float*)d_in[0];
    const float* qkv_w  = (const float*)d_in[1];
    const float* proj_w = (const float*)d_in[2];
    const float* proj_b = (const float*)d_in[3];
    const float* fp     = (const float*)d_in[4];
    float* out = (float*)d_out;

    float *p_Ot;
    cudaGetSymbolAddress((void**)&p_Ot, g_Ot);

    // 1. filter taps
    filter_kernel<<<dim3(SEQ/256, NH), 256>>>(fp);
    // 2. QKV projection
    mma_nt<<<dim3(QD/128, MROWS/128, 1), 256>>>(x, qkv_w, CD,
                                                (size_t)0, (size_t)0, EpiQKV{});
    // 3. spectral filtering (q scale folded), bf16 split
    mma_circ<<<dim3(SEQ/128, BB*NH), 256>>>();
    // 4-6. fused attention (QK^T + softmax + PV), bf16 split
    flash_attn<<<dim3(SEQ/128, BB*NH), 256>>>();
    // 7. output projection + bias
    mma_nt<<<dim3(CD/128, MROWS/128, 1), 256>>>(p_Ot, proj_w, CD,
                                                (size_t)0, (size_t)0, EpiOut{out, proj_b});
}

// round 8
// speedup vs baseline: 2.6318x; 1.1453x over previous
#include <cuda_runtime.h>
#include <math.h>

#ifndef M_PI
#define M_PI 3.14159265358979323846
#endif

namespace {
constexpr int BB  = 2;
constexpr int NH  = 12;
constexpr int SEQ = 2048;
constexpr int HD  = 64;
constexpr int CD  = 768;
constexpr int QD  = 2304;
constexpr int MROWS = BB * SEQ;  // 4096
}

// ---- scratch ----
__device__ float g_q [BB*NH*SEQ*HD];
__device__ float g_k [BB*NH*SEQ*HD];
__device__ float g_v [BB*NH*SEQ*HD];
__device__ float g_qf[BB*NH*SEQ*HD];
__device__ float g_kf[BB*NH*SEQ*HD];
__device__ float g_c [NH*SEQ];
__device__ float g_Ot[BB*SEQ*CD];

// ============================================================
// mma helpers
// ============================================================
__device__ __forceinline__ void mma16bf(float* c, const unsigned* a, const unsigned* b) {
    asm volatile(
        "mma.sync.aligned.m16n8k16.row.col.f32.bf16.bf16.f32 "
        "{%0,%1,%2,%3}, {%4,%5,%6,%7}, {%8,%9}, {%0,%1,%2,%3};"
        : "+f"(c[0]), "+f"(c[1]), "+f"(c[2]), "+f"(c[3])
        : "r"(a[0]), "r"(a[1]), "r"(a[2]), "r"(a[3]), "r"(b[0]), "r"(b[1]));
}
// pack (even,odd) f32 pair into bf16x2 hi + residual lo (even=lower half)
__device__ __forceinline__ void split_bf16_pair(float xe, float xo, unsigned& hi, unsigned& lo) {
    unsigned h;
    asm("cvt.rn.bf16x2.f32 %0, %1, %2;" : "=r"(h) : "f"(xo), "f"(xe));
    float re = xe - __uint_as_float(h << 16);
    float ro = xo - __uint_as_float(h & 0xffff0000u);
    unsigned l;
    asm("cvt.rn.bf16x2.f32 %0, %1, %2;" : "=r"(l) : "f"(ro), "f"(re));
    hi = h; lo = l;
}

// ============================================================
// Filter taps (closed form)
// ============================================================
__global__ void filter_kernel(const float* __restrict__ fp)
{
    int h = blockIdx.y;
    int u = blockIdx.x * blockDim.x + threadIdx.x;
    if (u >= SEQ) return;

    double p   = (double)fp[h];
    double sig = 1.0 / (1.0 + exp(-p));
    double md  = floor((double)SEQ * sig);
    int    m   = (int)md;
    double alpha = 4.0 / (double)SEQ;
    double theta = 2.0 * M_PI * (double)u / (double)SEQ;
    double wr = cos(theta), wi = sin(theta);
    double am = theta * (double)m;
    double wmr = cos(am), wmi = sin(am);

    double s1r;
    if (u == 0) {
        s1r = md;
    } else {
        double nr = 1.0 - wmr, ni = -wmi;
        double dr = 1.0 - wr,  di = -wi;
        double den = dr*dr + di*di;
        s1r = (nr*dr + ni*di) / den;
    }
    double e1 = exp(-alpha * (double)(SEQ - m));
    double ea = exp(-alpha);
    double nr2 = 1.0 - e1*wmr, ni2 = e1*wmi;
    double dr2 = 1.0 - ea*wr,  di2 = -ea*wi;
    double den2 = dr2*dr2 + di2*di2;
    double tr = (nr2*dr2 + ni2*di2) / den2;
    double ti = (ni2*dr2 - nr2*di2) / den2;
    double s2r = wmr*tr - wmi*ti;

    g_c[h*SEQ + u] = (float)((s1r + s2r) / (double)SEQ);
}

// ============================================================
// NT tensor-core GEMM (bf16 3-term split): C[m,n] = sum_k A[m,k]*B[n,k]
// block 128x128, TK=32 (16 bf16x2 pairs), 8 warps (4m x 2n).
// Pre-split at staging; stride 20 smem (conflict-free: 20g+t mod 32).
// ============================================================
template<class Epi>
__global__ __launch_bounds__(256) void mma_nt_bf(const float* __restrict__ A,
                                                 const float* __restrict__ B,
                                                 int K, size_t sA, size_t sB, Epi epi)
{
    __shared__ unsigned Ah[128*20], Al[128*20];
    __shared__ unsigned Bh[128*20], Bl[128*20];
    const int m0 = blockIdx.y * 128, n0 = blockIdx.x * 128;
    const float* Ab = A + (size_t)blockIdx.z * sA;
    const float* Bb = B + (size_t)blockIdx.z * sB;
    const int tid = threadIdx.x, lane = tid & 31, wid = tid >> 5;
    const int wm = (wid >> 1) * 32, wn = (wid & 1) * 64;
    const int g = lane >> 2, t = lane & 3;

    float C[2][8][4] = {};

    for (int k0 = 0; k0 < K; k0 += 32) {
        #pragma unroll
        for (int it = 0; it < 8; it++) {
            int i = tid + 256*it;
            int mm = i >> 4, kp = i & 15;
            float2 e = *(const float2*)(Ab + (size_t)(m0+mm)*K + k0 + 2*kp);
            unsigned hi, lo;
            split_bf16_pair(e.x, e.y, hi, lo);
            Ah[mm*20 + kp] = hi; Al[mm*20 + kp] = lo;
            float2 f = *(const float2*)(Bb + (size_t)(n0+mm)*K + k0 + 2*kp);
            split_bf16_pair(f.x, f.y, hi, lo);
            Bh[mm*20 + kp] = hi; Bl[mm*20 + kp] = lo;
        }
        __syncthreads();
        #pragma unroll
        for (int c = 0; c < 2; c++) {
            unsigned ah[2][4], al[2][4];
            #pragma unroll
            for (int im = 0; im < 2; im++) {
                const unsigned* ap  = &Ah[(wm + 16*im + g)*20 + 8*c + t];
                const unsigned* alp = &Al[(wm + 16*im + g)*20 + 8*c + t];
                ah[im][0] = ap[0];   ah[im][1] = ap[8*20];
                ah[im][2] = ap[4];   ah[im][3] = ap[8*20 + 4];
                al[im][0] = alp[0];  al[im][1] = alp[8*20];
                al[im][2] = alp[4];  al[im][3] = alp[8*20 + 4];
            }
            #pragma unroll
            for (int jn = 0; jn < 8; jn++) {
                const unsigned* bp  = &Bh[(wn + 8*jn + g)*20 + 8*c + t];
                const unsigned* blp = &Bl[(wn + 8*jn + g)*20 + 8*c + t];
                unsigned bh2[2] = { bp[0],  bp[4]  };
                unsigned bl2[2] = { blp[0], blp[4] };
                #pragma unroll
                for (int im = 0; im < 2; im++) {
                    mma16bf(C[im][jn], ah[im], bh2);
                    mma16bf(C[im][jn], ah[im], bl2);
                    mma16bf(C[im][jn], al[im], bh2);
                }
            }
        }
        __syncthreads();
    }
    #pragma unroll
    for (int im = 0; im < 2; im++)
        #pragma unroll
        for (int jn = 0; jn < 8; jn++) {
            int r  = m0 + wm + im*16 + g;
            int cc = n0 + wn + jn*8 + 2*t;
            epi.store2(blockIdx.z, r,   cc, C[im][jn][0], C[im][jn][1]);
            epi.store2(blockIdx.z, r+8, cc, C[im][jn][2], C[im][jn][3]);
        }
}

// ============================================================
// Circulant filter, bf16-split tensor-core version (unchanged).
// ============================================================
__global__ __launch_bounds__(256) void mma_circ()
{
    __shared__ unsigned Ah[128*20], Al[128*20];
    __shared__ unsigned Bh[128*17], Bl[128*17];
    __shared__ float csh[SEQ];

    const int m0 = blockIdx.x * 128;
    const int bh = blockIdx.y;
    const int h  = bh % NH;
    const float* srcq = g_q + (size_t)bh * SEQ * HD;
    const float* srck = g_k + (size_t)bh * SEQ * HD;

    const int tid = threadIdx.x, lane = tid & 31, wid = tid >> 5;
    const int wm = (wid >> 1) * 32, wn = (wid & 1) * 64;
    const int g = lane >> 2, t = lane & 3;

    for (int i = tid; i < SEQ; i += 256) csh[i] = g_c[h*SEQ + i];
    __syncthreads();

    float C[2][8][4] = {};

    for (int k0 = 0; k0 < SEQ; k0 += 32) {
        #pragma unroll
        for (int it = 0; it < 8; it++) {
            int i = tid + 256*it;
            int mm = i >> 4, kp = i & 15;
            int base = m0 + mm - k0 - 2*kp;
            float ce = csh[base & (SEQ-1)];
            float co = csh[(base - 1) & (SEQ-1)];
            unsigned hi, lo;
            split_bf16_pair(ce, co, hi, lo);
            Ah[mm*20 + kp] = hi;
            Al[mm*20 + kp] = lo;
        }
        #pragma unroll
        for (int it = 0; it < 8; it++) {
            int i = tid + 256*it;
            int n = i & 127, p = i >> 7;
            const float* src = (n < 64) ? srcq : srck;
            int col = n & 63;
            float e = src[(size_t)(k0 + 2*p)*HD + col];
            float o = src[(size_t)(k0 + 2*p + 1)*HD + col];
            unsigned hi, lo;
            split_bf16_pair(e, o, hi, lo);
            Bh[n*17 + p] = hi;
            Bl[n*17 + p] = lo;
        }
        __syncthreads();

        #pragma unroll
        for (int c = 0; c < 2; c++) {
            unsigned ah[2][4], al[2][4];
            #pragma unroll
            for (int im = 0; im < 2; im++) {
                const unsigned* ap  = &Ah[(wm + 16*im + g)*20 + 8*c + t];
                const unsigned* alp = &Al[(wm + 16*im + g)*20 + 8*c + t];
                ah[im][0] = ap[0];      ah[im][1] = ap[8*20];
                ah[im][2] = ap[4];      ah[im][3] = ap[8*20 + 4];
                al[im][0] = alp[0];     al[im][1] = alp[8*20];
                al[im][2] = alp[4];     al[im][3] = alp[8*20 + 4];
            }
            #pragma unroll
            for (int jn = 0; jn < 8; jn++) {
                const unsigned* bp  = &Bh[(wn + 8*jn + g)*17 + 8*c + t];
                const unsigned* blp = &Bl[(wn + 8*jn + g)*17 + 8*c + t];
                unsigned bh2[2] = { bp[0],  bp[4]  };
                unsigned bl2[2] = { blp[0], blp[4] };
                #pragma unroll
                for (int im = 0; im < 2; im++) {
                    mma16bf(C[im][jn], ah[im], bh2);
                    mma16bf(C[im][jn], ah[im], bl2);
                    mma16bf(C[im][jn], al[im], bh2);
                }
            }
        }
        __syncthreads();
    }

    float* qf = g_qf + (size_t)bh * SEQ * HD;
    float* kf = g_kf + (size_t)bh * SEQ * HD;
    #pragma unroll
    for (int im = 0; im < 2; im++)
        #pragma unroll
        for (int jn = 0; jn < 8; jn++) {
            int cc = wn + jn*8 + 2*t;
            #pragma unroll
            for (int half = 0; half < 2; half++) {
                int r = m0 + wm + im*16 + g + 8*half;
                float v0 = C[im][jn][2*half], v1 = C[im][jn][2*half+1];
                if (cc < 64) {
                    *(float2*)&qf[(size_t)r*HD + cc] = make_float2(v0*0.125f, v1*0.125f);
                } else {
                    *(float2*)&kf[(size_t)r*HD + cc - 64] = make_float2(v0, v1);
                }
            }
        }
}

// ============================================================
// Fused flash attention, bf16-split, 128-kv superstep in 2 chunks.
// grid (SEQ/128, BB*NH), 256 threads, 2 blocks/SM, dynamic smem 70KB.
// ============================================================
__global__ __launch_bounds__(256,2) void flash_attn()
{
    extern __shared__ unsigned dsm[];
    unsigned* Khs = dsm;                 // [128 kv][dpair 32] stride 36
    unsigned* Kls = Khs + 128*36;
    unsigned* Vhs = Kls + 128*36;        // [d 64][kvpair 64] stride 68
    unsigned* Vls = Vhs + 64*68;

    const int bh = blockIdx.y;
    const int m0 = blockIdx.x * 128;
    const float* qf = g_qf + (size_t)bh * SEQ * HD;
    const float* kf = g_kf + (size_t)bh * SEQ * HD;
    const float* vv = g_v  + (size_t)bh * SEQ * HD;

    const int tid = threadIdx.x, lane = tid & 31, w = tid >> 5;
    const int g = lane >> 2, t = lane & 3;

    // persistent Q fragments (bf16 split, packed pairs)
    unsigned qh[4][4], ql[4][4];
    {
        const float* r0 = qf + (size_t)(m0 + 16*w + g) * HD;
        const float* r1 = r0 + 8*HD;
        #pragma unroll
        for (int c = 0; c < 4; c++) {
            split_bf16_pair(r0[16*c + 2*t],     r0[16*c + 2*t + 1], qh[c][0], ql[c][0]);
            split_bf16_pair(r1[16*c + 2*t],     r1[16*c + 2*t + 1], qh[c][1], ql[c][1]);
            split_bf16_pair(r0[16*c + 8 + 2*t], r0[16*c + 9 + 2*t], qh[c][2], ql[c][2]);
            split_bf16_pair(r1[16*c + 8 + 2*t], r1[16*c + 9 + 2*t], qh[c][3], ql[c][3]);
        }
    }

    float O[8][4] = {};
    float mr0 = -1e30f, mr1 = -1e30f, l0 = 0.f, l1 = 0.f;

    for (int k0 = 0; k0 < SEQ; k0 += 128) {
        // ---- stage K: 128 kv rows x 64 d ----
        #pragma unroll
        for (int j = 0; j < 8; j++) {
            int r  = (tid >> 2) + 64*(j >> 2);
            int qd = (tid & 3) + 4*(j & 3);
            float4 kx = *(const float4*)(kf + (size_t)(k0 + r)*HD + qd*4);
            unsigned h01, l01, h23, l23;
            split_bf16_pair(kx.x, kx.y, h01, l01);
            split_bf16_pair(kx.z, kx.w, h23, l23);
            int p = 2*qd;
            Khs[r*36 + p] = h01; Khs[r*36 + p + 1] = h23;
            Kls[r*36 + p] = l01; Kls[r*36 + p + 1] = l23;
        }
        // ---- stage V: pairs 0..63 (128 kv), transposed ----
        #pragma unroll
        for (int j = 0; j < 4; j++) {
            int i = tid + 256*j;
            int kp = i & 63, d0 = (i >> 6) * 4;
            float4 a = *(const float4*)(vv + (size_t)(k0 + 2*kp)*HD + d0);
            float4 b = *(const float4*)(vv + (size_t)(k0 + 2*kp + 1)*HD + d0);
            const float ae[4] = {a.x, a.y, a.z, a.w};
            const float be[4] = {b.x, b.y, b.z, b.w};
            #pragma unroll
            for (int e = 0; e < 4; e++) {
                unsigned hi, lo;
                split_bf16_pair(ae[e], be[e], hi, lo);
                Vhs[(d0+e)*68 + kp] = hi;
                Vls[(d0+e)*68 + kp] = lo;
            }
        }
        __syncthreads();

        // ---- two 64-kv chunks ----
        #pragma unroll
        for (int ch = 0; ch < 2; ch++) {
            // S = Qf Kf^T
            float S[8][4] = {};
            #pragma unroll
            for (int c = 0; c < 4; c++) {
                #pragma unroll
                for (int jn = 0; jn < 8; jn++) {
                    const unsigned* kh = &Khs[(64*ch + 8*jn + g)*36 + 8*c + t];
                    const unsigned* kl = &Kls[(64*ch + 8*jn + g)*36 + 8*c + t];
                    unsigned bh2[2] = { kh[0], kh[4] };
                    unsigned bl2[2] = { kl[0], kl[4] };
                    mma16bf(S[jn], qh[c], bh2);
                    mma16bf(S[jn], qh[c], bl2);
                    mma16bf(S[jn], ql[c], bh2);
                }
            }

            // online softmax
            float rm0 = -1e30f, rm1 = -1e30f;
            #pragma unroll
            for (int jn = 0; jn < 8; jn++) {
                rm0 = fmaxf(rm0, fmaxf(S[jn][0], S[jn][1]));
                rm1 = fmaxf(rm1, fmaxf(S[jn][2], S[jn][3]));
            }
            rm0 = fmaxf(rm0, __shfl_xor_sync(0xffffffffu, rm0, 1));
            rm0 = fmaxf(rm0, __shfl_xor_sync(0xffffffffu, rm0, 2));
            rm1 = fmaxf(rm1, __shfl_xor_sync(0xffffffffu, rm1, 1));
            rm1 = fmaxf(rm1, __shfl_xor_sync(0xffffffffu, rm1, 2));
            float mn0 = fmaxf(mr0, rm0), mn1 = fmaxf(mr1, rm1);
            float a0 = __expf(mr0 - mn0), a1 = __expf(mr1 - mn1);
            mr0 = mn0; mr1 = mn1;

            #pragma unroll
            for (int jn = 0; jn < 8; jn++) {
                O[jn][0] *= a0; O[jn][1] *= a0; O[jn][2] *= a1; O[jn][3] *= a1;
            }

            // P conversion + P@V in two halves
            float ps0 = 0.f, ps1 = 0.f;
            #pragma unroll
            for (int half = 0; half < 2; half++) {
                unsigned ph[4][2], pl[4][2];
                #pragma unroll
                for (int q4 = 0; q4 < 4; q4++) {
                    int jn = 4*half + q4;
                    float p0 = __expf(S[jn][0] - mn0);
                    float p1 = __expf(S[jn][1] - mn0);
                    float p2 = __expf(S[jn][2] - mn1);
                    float p3 = __expf(S[jn][3] - mn1);
                    ps0 += p0 + p1; ps1 += p2 + p3;
                    split_bf16_pair(p0, p1, ph[q4][0], pl[q4][0]);
                    split_bf16_pair(p2, p3, ph[q4][1], pl[q4][1]);
                }
                #pragma unroll
                for (int kc2 = 0; kc2 < 2; kc2++) {
                    int kc = 32*ch + 8*(2*half + kc2);
                    unsigned ah2[4] = { ph[2*kc2][0], ph[2*kc2][1], ph[2*kc2+1][0], ph[2*kc2+1][1] };
                    unsigned al2[4] = { pl[2*kc2][0], pl[2*kc2][1], pl[2*kc2+1][0], pl[2*kc2+1][1] };
                    #pragma unroll
                    for (int jn = 0; jn < 8; jn++) {
                        const unsigned* vh = &Vhs[(8*jn + g)*68 + kc + t];
                        const unsigned* vl = &Vls[(8*jn + g)*68 + kc + t];
                        unsigned bh2[2] = { vh[0], vh[4] };
                        unsigned bl2[2] = { vl[0], vl[4] };
                        mma16bf(O[jn], ah2, bh2);
                        mma16bf(O[jn], ah2, bl2);
                        mma16bf(O[jn], al2, bh2);
                    }
                }
            }
            l0 = l0*a0 + ps0; l1 = l1*a1 + ps1;
        }
        __syncthreads();
    }

    // ---- epilogue ----
    l0 += __shfl_xor_sync(0xffffffffu, l0, 1);
    l0 += __shfl_xor_sync(0xffffffffu, l0, 2);
    l1 += __shfl_xor_sync(0xffffffffu, l1, 1);
    l1 += __shfl_xor_sync(0xffffffffu, l1, 2);
    float i0 = 1.f / l0, i1 = 1.f / l1;

    const int b = bh / NH, hh = bh - b*NH;
    const int r0 = m0 + 16*w + g, r1 = r0 + 8;
    #pragma unroll
    for (int jn = 0; jn < 8; jn++) {
        int cc = 8*jn + 2*t;
        *(float2*)&g_Ot[((size_t)(b*SEQ + r0))*CD + hh*HD + cc] =
            make_float2(O[jn][0]*i0, O[jn][1]*i0);
        *(float2*)&g_Ot[((size_t)(b*SEQ + r1))*CD + hh*HD + cc] =
            make_float2(O[jn][2]*i1, O[jn][3]*i1);
    }
}

// ---- epilogues ----
struct EpiQKV {
    __device__ void store2(int, int r, int c, float v0, float v1) const {
        int b = r >> 11, n = r & (SEQ-1);
        int s = c / CD; int rem = c - s*CD;
        int h = rem >> 6, d = rem & 63;
        float* dst = (s == 0) ? g_q : ((s == 1) ? g_k : g_v);
        *(float2*)&dst[(((size_t)b*NH + h)*SEQ + n)*HD + d] = make_float2(v0, v1);
    }
};
struct EpiOut {
    float* out; const float* pb;
    __device__ void store2(int, int r, int c, float v0, float v1) const {
        *(float2*)&out[(size_t)r*CD + c] = make_float2(v0 + pb[c], v1 + pb[c+1]);
    }
};

extern "C" void kernel_launch(void* const* d_in, const int* /*in_sizes*/, int /*n_in*/,
                              void* d_out, int /*out_size*/)
{
    const float* x      = (const float*)d_in[0];
    const float* qkv_w  = (const float*)d_in[1];
    const float* proj_w = (const float*)d_in[2];
    const float* proj_b = (const float*)d_in[3];
    const float* fp     = (const float*)d_in[4];
    float* out = (float*)d_out;

    float *p_Ot;
    cudaGetSymbolAddress((void**)&p_Ot, g_Ot);

    constexpr int FLASH_SMEM = (2*128*36 + 2*64*68) * 4;   // 71680 B
    cudaFuncSetAttribute(flash_attn, cudaFuncAttributeMaxDynamicSharedMemorySize, FLASH_SMEM);

    // 1. filter taps
    filter_kernel<<<dim3(SEQ/256, NH), 256>>>(fp);
    // 2. QKV projection (bf16 split)
    mma_nt_bf<<<dim3(QD/128, MROWS/128, 1), 256>>>(x, qkv_w, CD,
                                                   (size_t)0, (size_t)0, EpiQKV{});
    // 3. spectral filtering (q scale folded), bf16 split
    mma_circ<<<dim3(SEQ/128, BB*NH), 256>>>();
    // 4-6. fused attention (QK^T + softmax + PV), bf16 split, 128-kv superstep
    flash_attn<<<dim3(SEQ/128, BB*NH), 256, FLASH_SMEM>>>();
    // 7. output projection + bias (bf16 split)
    mma_nt_bf<<<dim3(CD/128, MROWS/128, 1), 256>>>(p_Ot, proj_w, CD,
                                                   (size_t)0, (size_t)0, EpiOut{out, proj_b});
}

// round 9
// speedup vs baseline: 2.7328x; 1.0384x over previous
#include <cuda_runtime.h>
#include <math.h>

#ifndef M_PI
#define M_PI 3.14159265358979323846
#endif

namespace {
constexpr int BB  = 2;
constexpr int NH  = 12;
constexpr int SEQ = 2048;
constexpr int HD  = 64;
constexpr int CD  = 768;
constexpr int QD  = 2304;
constexpr int MROWS = BB * SEQ;  // 4096
}

// ---- scratch ----
__device__ float g_q [BB*NH*SEQ*HD];
__device__ float g_k [BB*NH*SEQ*HD];
__device__ float g_v [BB*NH*SEQ*HD];
__device__ float g_qf[BB*NH*SEQ*HD];
__device__ float g_kf[BB*NH*SEQ*HD];
__device__ float g_c [NH*SEQ];
__device__ float g_Ot[BB*SEQ*CD];

// ============================================================
// mma helpers
// ============================================================
__device__ __forceinline__ void mma16bf(float* c, const unsigned* a, const unsigned* b) {
    asm volatile(
        "mma.sync.aligned.m16n8k16.row.col.f32.bf16.bf16.f32 "
        "{%0,%1,%2,%3}, {%4,%5,%6,%7}, {%8,%9}, {%0,%1,%2,%3};"
        : "+f"(c[0]), "+f"(c[1]), "+f"(c[2]), "+f"(c[3])
        : "r"(a[0]), "r"(a[1]), "r"(a[2]), "r"(a[3]), "r"(b[0]), "r"(b[1]));
}
// pack (even,odd) f32 pair into bf16x2 hi + residual lo (even=lower half)
__device__ __forceinline__ void split_bf16_pair(float xe, float xo, unsigned& hi, unsigned& lo) {
    unsigned h;
    asm("cvt.rn.bf16x2.f32 %0, %1, %2;" : "=r"(h) : "f"(xo), "f"(xe));
    float re = xe - __uint_as_float(h << 16);
    float ro = xo - __uint_as_float(h & 0xffff0000u);
    unsigned l;
    asm("cvt.rn.bf16x2.f32 %0, %1, %2;" : "=r"(l) : "f"(ro), "f"(re));
    hi = h; lo = l;
}
__device__ __forceinline__ unsigned sptr(const void* p) {
    return (unsigned)__cvta_generic_to_shared(p);
}
__device__ __forceinline__ void ldsm_x4(unsigned& r0, unsigned& r1, unsigned& r2, unsigned& r3,
                                        unsigned addr) {
    asm volatile("ldmatrix.sync.aligned.m8n8.x4.shared.b16 {%0,%1,%2,%3}, [%4];"
                 : "=r"(r0), "=r"(r1), "=r"(r2), "=r"(r3) : "r"(addr));
}

// ============================================================
// Filter taps (closed form)
// ============================================================
__global__ void filter_kernel(const float* __restrict__ fp)
{
    int h = blockIdx.y;
    int u = blockIdx.x * blockDim.x + threadIdx.x;
    if (u >= SEQ) return;

    double p   = (double)fp[h];
    double sig = 1.0 / (1.0 + exp(-p));
    double md  = floor((double)SEQ * sig);
    int    m   = (int)md;
    double alpha = 4.0 / (double)SEQ;
    double theta = 2.0 * M_PI * (double)u / (double)SEQ;
    double wr = cos(theta), wi = sin(theta);
    double am = theta * (double)m;
    double wmr = cos(am), wmi = sin(am);

    double s1r;
    if (u == 0) {
        s1r = md;
    } else {
        double nr = 1.0 - wmr, ni = -wmi;
        double dr = 1.0 - wr,  di = -wi;
        double den = dr*dr + di*di;
        s1r = (nr*dr + ni*di) / den;
    }
    double e1 = exp(-alpha * (double)(SEQ - m));
    double ea = exp(-alpha);
    double nr2 = 1.0 - e1*wmr, ni2 = e1*wmi;
    double dr2 = 1.0 - ea*wr,  di2 = -ea*wi;
    double den2 = dr2*dr2 + di2*di2;
    double tr = (nr2*dr2 + ni2*di2) / den2;
    double ti = (ni2*dr2 - nr2*di2) / den2;
    double s2r = wmr*tr - wmi*ti;

    g_c[h*SEQ + u] = (float)((s1r + s2r) / (double)SEQ);
}

// ============================================================
// NT tensor-core GEMM (bf16 3-term split), LDSM fragment loads.
// block 128x128, TK=32, 8 warps (4m x 2n). Stride 20 (80B, LDSM-safe).
// ============================================================
template<class Epi>
__global__ __launch_bounds__(256) void mma_nt_bf(const float* __restrict__ A,
                                                 const float* __restrict__ B,
                                                 int K, size_t sA, size_t sB, Epi epi)
{
    __shared__ __align__(16) unsigned Ah[128*20], Al[128*20];
    __shared__ __align__(16) unsigned Bh[128*20], Bl[128*20];
    const int m0 = blockIdx.y * 128, n0 = blockIdx.x * 128;
    const float* Ab = A + (size_t)blockIdx.z * sA;
    const float* Bb = B + (size_t)blockIdx.z * sB;
    const int tid = threadIdx.x, lane = tid & 31, wid = tid >> 5;
    const int wm = (wid >> 1) * 32, wn = (wid & 1) * 64;
    const int g = lane >> 2, t = lane & 3;
    const int tl = lane >> 3, rw = lane & 7;

    const unsigned ah_s = sptr(Ah), al_s = sptr(Al);
    const unsigned bh_s = sptr(Bh), bl_s = sptr(Bl);

    float C[2][8][4] = {};

    for (int k0 = 0; k0 < K; k0 += 32) {
        #pragma unroll
        for (int it = 0; it < 8; it++) {
            int i = tid + 256*it;
            int mm = i >> 4, kp = i & 15;
            float2 e = *(const float2*)(Ab + (size_t)(m0+mm)*K + k0 + 2*kp);
            unsigned hi, lo;
            split_bf16_pair(e.x, e.y, hi, lo);
            Ah[mm*20 + kp] = hi; Al[mm*20 + kp] = lo;
            float2 f = *(const float2*)(Bb + (size_t)(n0+mm)*K + k0 + 2*kp);
            split_bf16_pair(f.x, f.y, hi, lo);
            Bh[mm*20 + kp] = hi; Bl[mm*20 + kp] = lo;
        }
        __syncthreads();
        #pragma unroll
        for (int c = 0; c < 2; c++) {
            unsigned ah[2][4], al[2][4];
            #pragma unroll
            for (int im = 0; im < 2; im++) {
                // A tiles: tl&1 -> row-half, tl>>1 -> k-half
                unsigned off = (unsigned)(((wm + 16*im + 8*(tl & 1) + rw)*20
                                           + 8*c + 4*(tl >> 1)) * 4);
                ldsm_x4(ah[im][0], ah[im][1], ah[im][2], ah[im][3], ah_s + off);
                ldsm_x4(al[im][0], al[im][1], al[im][2], al[im][3], al_s + off);
            }
            #pragma unroll
            for (int jnp = 0; jnp < 4; jnp++) {
                // B tiles: tl>>1 -> jn within pair, tl&1 -> k-half
                unsigned off = (unsigned)(((wn + 8*(2*jnp + (tl >> 1)) + rw)*20
                                           + 8*c + 4*(tl & 1)) * 4);
                unsigned b0, b1, b2, b3, c0, c1, c2, c3;
                ldsm_x4(b0, b1, b2, b3, bh_s + off);
                ldsm_x4(c0, c1, c2, c3, bl_s + off);
                unsigned bh2[2] = { b0, b1 }, bl2[2] = { c0, c1 };
                unsigned bh3[2] = { b2, b3 }, bl3[2] = { c2, c3 };
                #pragma unroll
                for (int im = 0; im < 2; im++) {
                    mma16bf(C[im][2*jnp],   ah[im], bh2);
                    mma16bf(C[im][2*jnp],   ah[im], bl2);
                    mma16bf(C[im][2*jnp],   al[im], bh2);
                    mma16bf(C[im][2*jnp+1], ah[im], bh3);
                    mma16bf(C[im][2*jnp+1], ah[im], bl3);
                    mma16bf(C[im][2*jnp+1], al[im], bh3);
                }
            }
        }
        __syncthreads();
    }
    #pragma unroll
    for (int im = 0; im < 2; im++)
        #pragma unroll
        for (int jn = 0; jn < 8; jn++) {
            int r  = m0 + wm + im*16 + g;
            int cc = n0 + wn + jn*8 + 2*t;
            epi.store2(blockIdx.z, r,   cc, C[im][jn][0], C[im][jn][1]);
            epi.store2(blockIdx.z, r+8, cc, C[im][jn][2], C[im][jn][3]);
        }
}

// ============================================================
// Circulant filter, bf16-split + LDSM. Dynamic smem (48KB).
// Layout: Ah[2560] Al[2560] Bh[2560] Bl[2560] csh[2048 floats]
// ============================================================
__global__ __launch_bounds__(256) void mma_circ()
{
    extern __shared__ __align__(16) unsigned csm[];
    unsigned* Ah = csm;
    unsigned* Al = Ah + 128*20;
    unsigned* Bh = Al + 128*20;
    unsigned* Bl = Bh + 128*20;
    float*   csh = (float*)(Bl + 128*20);

    const int m0 = blockIdx.x * 128;
    const int bh = blockIdx.y;
    const int h  = bh % NH;
    const float* srcq = g_q + (size_t)bh * SEQ * HD;
    const float* srck = g_k + (size_t)bh * SEQ * HD;

    const int tid = threadIdx.x, lane = tid & 31, wid = tid >> 5;
    const int wm = (wid >> 1) * 32, wn = (wid & 1) * 64;
    const int g = lane >> 2, t = lane & 3;
    const int tl = lane >> 3, rw = lane & 7;

    const unsigned ah_s = sptr(Ah), al_s = sptr(Al);
    const unsigned bh_s = sptr(Bh), bl_s = sptr(Bl);

    for (int i = tid; i < SEQ; i += 256) csh[i] = g_c[h*SEQ + i];
    __syncthreads();

    float C[2][8][4] = {};

    for (int k0 = 0; k0 < SEQ; k0 += 32) {
        #pragma unroll
        for (int it = 0; it < 8; it++) {
            int i = tid + 256*it;
            int mm = i >> 4, kp = i & 15;
            int base = m0 + mm - k0 - 2*kp;
            float ce = csh[base & (SEQ-1)];
            float co = csh[(base - 1) & (SEQ-1)];
            unsigned hi, lo;
            split_bf16_pair(ce, co, hi, lo);
            Ah[mm*20 + kp] = hi;
            Al[mm*20 + kp] = lo;
        }
        #pragma unroll
        for (int it = 0; it < 8; it++) {
            int i = tid + 256*it;
            int n = i & 127, p = i >> 7;
            const float* src = (n < 64) ? srcq : srck;
            int col = n & 63;
            float e = src[(size_t)(k0 + 2*p)*HD + col];
            float o = src[(size_t)(k0 + 2*p + 1)*HD + col];
            unsigned hi, lo;
            split_bf16_pair(e, o, hi, lo);
            Bh[n*20 + p] = hi;
            Bl[n*20 + p] = lo;
        }
        __syncthreads();

        #pragma unroll
        for (int c = 0; c < 2; c++) {
            unsigned ah[2][4], al[2][4];
            #pragma unroll
            for (int im = 0; im < 2; im++) {
                unsigned off = (unsigned)(((wm + 16*im + 8*(tl & 1) + rw)*20
                                           + 8*c + 4*(tl >> 1)) * 4);
                ldsm_x4(ah[im][0], ah[im][1], ah[im][2], ah[im][3], ah_s + off);
                ldsm_x4(al[im][0], al[im][1], al[im][2], al[im][3], al_s + off);
            }
            #pragma unroll
            for (int jnp = 0; jnp < 4; jnp++) {
                unsigned off = (unsigned)(((wn + 8*(2*jnp + (tl >> 1)) + rw)*20
                                           + 8*c + 4*(tl & 1)) * 4);
                unsigned b0, b1, b2, b3, c0, c1, c2, c3;
                ldsm_x4(b0, b1, b2, b3, bh_s + off);
                ldsm_x4(c0, c1, c2, c3, bl_s + off);
                unsigned bh2[2] = { b0, b1 }, bl2[2] = { c0, c1 };
                unsigned bh3[2] = { b2, b3 }, bl3[2] = { c2, c3 };
                #pragma unroll
                for (int im = 0; im < 2; im++) {
                    mma16bf(C[im][2*jnp],   ah[im], bh2);
                    mma16bf(C[im][2*jnp],   ah[im], bl2);
                    mma16bf(C[im][2*jnp],   al[im], bh2);
                    mma16bf(C[im][2*jnp+1], ah[im], bh3);
                    mma16bf(C[im][2*jnp+1], ah[im], bl3);
                    mma16bf(C[im][2*jnp+1], al[im], bh3);
                }
            }
        }
        __syncthreads();
    }

    float* qf = g_qf + (size_t)bh * SEQ * HD;
    float* kf = g_kf + (size_t)bh * SEQ * HD;
    #pragma unroll
    for (int im = 0; im < 2; im++)
        #pragma unroll
        for (int jn = 0; jn < 8; jn++) {
            int cc = wn + jn*8 + 2*t;
            #pragma unroll
            for (int half = 0; half < 2; half++) {
                int r = m0 + wm + im*16 + g + 8*half;
                float v0 = C[im][jn][2*half], v1 = C[im][jn][2*half+1];
                if (cc < 64) {
                    *(float2*)&qf[(size_t)r*HD + cc] = make_float2(v0*0.125f, v1*0.125f);
                } else {
                    *(float2*)&kf[(size_t)r*HD + cc - 64] = make_float2(v0, v1);
                }
            }
        }
}

// ============================================================
// Fused flash attention, bf16-split + LDSM, 128-kv superstep.
// grid (SEQ/128, BB*NH), 256 threads, 2 blocks/SM, dynamic smem 70KB.
// ============================================================
__global__ __launch_bounds__(256,2) void flash_attn()
{
    extern __shared__ __align__(16) unsigned dsm[];
    unsigned* Khs = dsm;                 // [128 kv][dpair 32] stride 36
    unsigned* Kls = Khs + 128*36;
    unsigned* Vhs = Kls + 128*36;        // [d 64][kvpair 64] stride 68
    unsigned* Vls = Vhs + 64*68;

    const int bh = blockIdx.y;
    const int m0 = blockIdx.x * 128;
    const float* qf = g_qf + (size_t)bh * SEQ * HD;
    const float* kf = g_kf + (size_t)bh * SEQ * HD;
    const float* vv = g_v  + (size_t)bh * SEQ * HD;

    const int tid = threadIdx.x, lane = tid & 31, w = tid >> 5;
    const int g = lane >> 2, t = lane & 3;
    const int tl = lane >> 3, rw = lane & 7;

    const unsigned khs_s = sptr(Khs), kls_s = sptr(Kls);
    const unsigned vhs_s = sptr(Vhs), vls_s = sptr(Vls);

    // persistent Q fragments (bf16 split, packed pairs)
    unsigned qh[4][4], ql[4][4];
    {
        const float* r0 = qf + (size_t)(m0 + 16*w + g) * HD;
        const float* r1 = r0 + 8*HD;
        #pragma unroll
        for (int c = 0; c < 4; c++) {
            split_bf16_pair(r0[16*c + 2*t],     r0[16*c + 2*t + 1], qh[c][0], ql[c][0]);
            split_bf16_pair(r1[16*c + 2*t],     r1[16*c + 2*t + 1], qh[c][1], ql[c][1]);
            split_bf16_pair(r0[16*c + 8 + 2*t], r0[16*c + 9 + 2*t], qh[c][2], ql[c][2]);
            split_bf16_pair(r1[16*c + 8 + 2*t], r1[16*c + 9 + 2*t], qh[c][3], ql[c][3]);
        }
    }

    float O[8][4] = {};
    float mr0 = -1e30f, mr1 = -1e30f, l0 = 0.f, l1 = 0.f;

    for (int k0 = 0; k0 < SEQ; k0 += 128) {
        // ---- stage K: 128 kv rows x 64 d ----
        #pragma unroll
        for (int j = 0; j < 8; j++) {
            int r  = (tid >> 2) + 64*(j >> 2);
            int qd = (tid & 3) + 4*(j & 3);
            float4 kx = *(const float4*)(kf + (size_t)(k0 + r)*HD + qd*4);
            unsigned h01, l01, h23, l23;
            split_bf16_pair(kx.x, kx.y, h01, l01);
            split_bf16_pair(kx.z, kx.w, h23, l23);
            int p = 2*qd;
            Khs[r*36 + p] = h01; Khs[r*36 + p + 1] = h23;
            Kls[r*36 + p] = l01; Kls[r*36 + p + 1] = l23;
        }
        // ---- stage V: pairs 0..63 (128 kv), transposed ----
        #pragma unroll
        for (int j = 0; j < 4; j++) {
            int i = tid + 256*j;
            int kp = i & 63, d0 = (i >> 6) * 4;
            float4 a = *(const float4*)(vv + (size_t)(k0 + 2*kp)*HD + d0);
            float4 b = *(const float4*)(vv + (size_t)(k0 + 2*kp + 1)*HD + d0);
            const float ae[4] = {a.x, a.y, a.z, a.w};
            const float be[4] = {b.x, b.y, b.z, b.w};
            #pragma unroll
            for (int e = 0; e < 4; e++) {
                unsigned hi, lo;
                split_bf16_pair(ae[e], be[e], hi, lo);
                Vhs[(d0+e)*68 + kp] = hi;
                Vls[(d0+e)*68 + kp] = lo;
            }
        }
        __syncthreads();

        // ---- two 64-kv chunks ----
        #pragma unroll
        for (int ch = 0; ch < 2; ch++) {
            // S = Qf Kf^T
            float S[8][4] = {};
            #pragma unroll
            for (int c = 0; c < 4; c++) {
                #pragma unroll
                for (int jnp = 0; jnp < 4; jnp++) {
                    unsigned off = (unsigned)((((64*ch + 8*(2*jnp + (tl >> 1)) + rw)*36
                                                + 8*c + 4*(tl & 1))) * 4);
                    unsigned b0, b1, b2, b3, c0, c1, c2, c3;
                    ldsm_x4(b0, b1, b2, b3, khs_s + off);
                    ldsm_x4(c0, c1, c2, c3, kls_s + off);
                    unsigned bh2[2] = { b0, b1 }, bl2[2] = { c0, c1 };
                    unsigned bh3[2] = { b2, b3 }, bl3[2] = { c2, c3 };
                    mma16bf(S[2*jnp],   qh[c], bh2);
                    mma16bf(S[2*jnp],   qh[c], bl2);
                    mma16bf(S[2*jnp],   ql[c], bh2);
                    mma16bf(S[2*jnp+1], qh[c], bh3);
                    mma16bf(S[2*jnp+1], qh[c], bl3);
                    mma16bf(S[2*jnp+1], ql[c], bh3);
                }
            }

            // online softmax
            float rm0 = -1e30f, rm1 = -1e30f;
            #pragma unroll
            for (int jn = 0; jn < 8; jn++) {
                rm0 = fmaxf(rm0, fmaxf(S[jn][0], S[jn][1]));
                rm1 = fmaxf(rm1, fmaxf(S[jn][2], S[jn][3]));
            }
            rm0 = fmaxf(rm0, __shfl_xor_sync(0xffffffffu, rm0, 1));
            rm0 = fmaxf(rm0, __shfl_xor_sync(0xffffffffu, rm0, 2));
            rm1 = fmaxf(rm1, __shfl_xor_sync(0xffffffffu, rm1, 1));
            rm1 = fmaxf(rm1, __shfl_xor_sync(0xffffffffu, rm1, 2));
            float mn0 = fmaxf(mr0, rm0), mn1 = fmaxf(mr1, rm1);
            float a0 = __expf(mr0 - mn0), a1 = __expf(mr1 - mn1);
            mr0 = mn0; mr1 = mn1;

            #pragma unroll
            for (int jn = 0; jn < 8; jn++) {
                O[jn][0] *= a0; O[jn][1] *= a0; O[jn][2] *= a1; O[jn][3] *= a1;
            }

            // P conversion + P@V in two halves
            float ps0 = 0.f, ps1 = 0.f;
            #pragma unroll
            for (int half = 0; half < 2; half++) {
                unsigned ph[4][2], pl[4][2];
                #pragma unroll
                for (int q4 = 0; q4 < 4; q4++) {
                    int jn = 4*half + q4;
                    float p0 = __expf(S[jn][0] - mn0);
                    float p1 = __expf(S[jn][1] - mn0);
                    float p2 = __expf(S[jn][2] - mn1);
                    float p3 = __expf(S[jn][3] - mn1);
                    ps0 += p0 + p1; ps1 += p2 + p3;
                    split_bf16_pair(p0, p1, ph[q4][0], pl[q4][0]);
                    split_bf16_pair(p2, p3, ph[q4][1], pl[q4][1]);
                }
                #pragma unroll
                for (int kc2 = 0; kc2 < 2; kc2++) {
                    int kc = 32*ch + 8*(2*half + kc2);
                    unsigned ah2[4] = { ph[2*kc2][0], ph[2*kc2][1], ph[2*kc2+1][0], ph[2*kc2+1][1] };
                    unsigned al2[4] = { pl[2*kc2][0], pl[2*kc2][1], pl[2*kc2+1][0], pl[2*kc2+1][1] };
                    #pragma unroll
                    for (int jnp = 0; jnp < 4; jnp++) {
                        unsigned off = (unsigned)((((8*(2*jnp + (tl >> 1)) + rw)*68
                                                    + kc + 4*(tl & 1))) * 4);
                        unsigned b0, b1, b2, b3, c0, c1, c2, c3;
                        ldsm_x4(b0, b1, b2, b3, vhs_s + off);
                        ldsm_x4(c0, c1, c2, c3, vls_s + off);
                        unsigned bh2[2] = { b0, b1 }, bl2[2] = { c0, c1 };
                        unsigned bh3[2] = { b2, b3 }, bl3[2] = { c2, c3 };
                        mma16bf(O[2*jnp],   ah2, bh2);
                        mma16bf(O[2*jnp],   ah2, bl2);
                        mma16bf(O[2*jnp],   al2, bh2);
                        mma16bf(O[2*jnp+1], ah2, bh3);
                        mma16bf(O[2*jnp+1], ah2, bl3);
                        mma16bf(O[2*jnp+1], al2, bh3);
                    }
                }
            }
            l0 = l0*a0 + ps0; l1 = l1*a1 + ps1;
        }
        __syncthreads();
    }

    // ---- epilogue ----
    l0 += __shfl_xor_sync(0xffffffffu, l0, 1);
    l0 += __shfl_xor_sync(0xffffffffu, l0, 2);
    l1 += __shfl_xor_sync(0xffffffffu, l1, 1);
    l1 += __shfl_xor_sync(0xffffffffu, l1, 2);
    float i0 = 1.f / l0, i1 = 1.f / l1;

    const int b = bh / NH, hh = bh - b*NH;
    const int r0 = m0 + 16*w + g, r1 = r0 + 8;
    #pragma unroll
    for (int jn = 0; jn < 8; jn++) {
        int cc = 8*jn + 2*t;
        *(float2*)&g_Ot[((size_t)(b*SEQ + r0))*CD + hh*HD + cc] =
            make_float2(O[jn][0]*i0, O[jn][1]*i0);
        *(float2*)&g_Ot[((size_t)(b*SEQ + r1))*CD + hh*HD + cc] =
            make_float2(O[jn][2]*i1, O[jn][3]*i1);
    }
}

// ---- epilogues ----
struct EpiQKV {
    __device__ void store2(int, int r, int c, float v0, float v1) const {
        int b = r >> 11, n = r & (SEQ-1);
        int s = c / CD; int rem = c - s*CD;
        int h = rem >> 6, d = rem & 63;
        float* dst = (s == 0) ? g_q : ((s == 1) ? g_k : g_v);
        *(float2*)&dst[(((size_t)b*NH + h)*SEQ + n)*HD + d] = make_float2(v0, v1);
    }
};
struct EpiOut {
    float* out; const float* pb;
    __device__ void store2(int, int r, int c, float v0, float v1) const {
        *(float2*)&out[(size_t)r*CD + c] = make_float2(v0 + pb[c], v1 + pb[c+1]);
    }
};

extern "C" void kernel_launch(void* const* d_in, const int* /*in_sizes*/, int /*n_in*/,
                              void* d_out, int /*out_size*/)
{
    const float* x      = (const float*)d_in[0];
    const float* qkv_w  = (const float*)d_in[1];
    const float* proj_w = (const float*)d_in[2];
    const float* proj_b = (const float*)d_in[3];
    const float* fp     = (const float*)d_in[4];
    float* out = (float*)d_out;

    float *p_Ot;
    cudaGetSymbolAddress((void**)&p_Ot, g_Ot);

    constexpr int FLASH_SMEM = (2*128*36 + 2*64*68) * 4;   // 71680 B
    constexpr int CIRC_SMEM  = (4*128*20) * 4 + SEQ * 4;   // 49152 B
    cudaFuncSetAttribute(flash_attn, cudaFuncAttributeMaxDynamicSharedMemorySize, FLASH_SMEM);
    cudaFuncSetAttribute(mma_circ,   cudaFuncAttributeMaxDynamicSharedMemorySize, CIRC_SMEM);

    // 1. filter taps
    filter_kernel<<<dim3(SEQ/256, NH), 256>>>(fp);
    // 2. QKV projection (bf16 split, LDSM)
    mma_nt_bf<<<dim3(QD/128, MROWS/128, 1), 256>>>(x, qkv_w, CD,
                                                   (size_t)0, (size_t)0, EpiQKV{});
    // 3. spectral filtering (q scale folded), bf16 split, LDSM
    mma_circ<<<dim3(SEQ/128, BB*NH), 256, CIRC_SMEM>>>();
    // 4-6. fused attention, bf16 split, LDSM, 128-kv superstep
    flash_attn<<<dim3(SEQ/128, BB*NH), 256, FLASH_SMEM>>>();
    // 7. output projection + bias (bf16 split, LDSM)
    mma_nt_bf<<<dim3(CD/128, MROWS/128, 1), 256>>>(p_Ot, proj_w, CD,
                                                   (size_t)0, (size_t)0, EpiOut{out, proj_b});
}

// round 10
// speedup vs baseline: 3.2282x; 1.1813x over previous
#include <cuda_runtime.h>
#include <math.h>

#ifndef M_PI
#define M_PI 3.14159265358979323846
#endif

namespace {
constexpr int BB  = 2;
constexpr int NH  = 12;
constexpr int SEQ = 2048;
constexpr int HD  = 64;
constexpr int CD  = 768;
constexpr int QD  = 2304;
constexpr int MROWS = BB * SEQ;  // 4096
}

// ---- scratch ----
__device__ float g_q [BB*NH*SEQ*HD];
__device__ float g_k [BB*NH*SEQ*HD];
__device__ float g_v [BB*NH*SEQ*HD];
__device__ float g_qf[BB*NH*SEQ*HD];
__device__ float g_kf[BB*NH*SEQ*HD];
__device__ float g_Ot[BB*SEQ*CD];

// ============================================================
// mma helpers
// ============================================================
__device__ __forceinline__ void mma16bf(float* c, const unsigned* a, const unsigned* b) {
    asm volatile(
        "mma.sync.aligned.m16n8k16.row.col.f32.bf16.bf16.f32 "
        "{%0,%1,%2,%3}, {%4,%5,%6,%7}, {%8,%9}, {%0,%1,%2,%3};"
        : "+f"(c[0]), "+f"(c[1]), "+f"(c[2]), "+f"(c[3])
        : "r"(a[0]), "r"(a[1]), "r"(a[2]), "r"(a[3]), "r"(b[0]), "r"(b[1]));
}
// pack (even,odd) f32 pair into bf16x2 hi + residual lo (even=lower half)
__device__ __forceinline__ void split_bf16_pair(float xe, float xo, unsigned& hi, unsigned& lo) {
    unsigned h;
    asm("cvt.rn.bf16x2.f32 %0, %1, %2;" : "=r"(h) : "f"(xo), "f"(xe));
    float re = xe - __uint_as_float(h << 16);
    float ro = xo - __uint_as_float(h & 0xffff0000u);
    unsigned l;
    asm("cvt.rn.bf16x2.f32 %0, %1, %2;" : "=r"(l) : "f"(ro), "f"(re));
    hi = h; lo = l;
}
__device__ __forceinline__ unsigned sptr(const void* p) {
    return (unsigned)__cvta_generic_to_shared(p);
}
__device__ __forceinline__ void ldsm_x4(unsigned& r0, unsigned& r1, unsigned& r2, unsigned& r3,
                                        unsigned addr) {
    asm volatile("ldmatrix.sync.aligned.m8n8.x4.shared.b16 {%0,%1,%2,%3}, [%4];"
                 : "=r"(r0), "=r"(r1), "=r"(r2), "=r"(r3) : "r"(addr));
}

// ============================================================
// Spectral filter via in-smem Stockham FFT.
// One block per (d, bh, q|k) column: fwd FFT, multiply by A (real)
// + conj (+ fold 1/N and q-scale), fwd FFT again, take real part.
//   Re(ifft(V)) = Re(fft(conj V))/N
// grid (HD, BB*NH, 2), 256 threads, 32KB smem.
// ============================================================
__global__ __launch_bounds__(256) void fft_filter(const float* __restrict__ fp)
{
    __shared__ float2 buf[2][SEQ];

    const int d  = blockIdx.x;
    const int bh = blockIdx.y;
    const int h  = bh % NH;
    const bool isq = (blockIdx.z == 0);
    const float* src = (isq ? g_q : g_k) + (size_t)bh * SEQ * HD + d;
    float*       dst = (isq ? g_qf : g_kf) + (size_t)bh * SEQ * HD + d;
    const int tid = threadIdx.x;

    // load column (real -> complex)
    for (int i = tid; i < SEQ; i += 256)
        buf[0][i] = make_float2(src[(size_t)i * HD], 0.f);
    __syncthreads();

    int cur = 0;
    // ---- forward FFT (11 radix-2 Stockham stages) ----
    #pragma unroll 1
    for (int Ns = 1; Ns < SEQ; Ns <<= 1) {
        const float2* s = buf[cur];
        float2* dt = buf[cur ^ 1];
        const float na = -(float)M_PI / Ns;
        for (int j = tid; j < SEQ/2; j += 256) {
            float2 v0 = s[j];
            float2 v1 = s[j + SEQ/2];
            float ang = na * (j & (Ns - 1));
            float sn, cs; __sincosf(ang, &sn, &cs);
            float2 w = make_float2(cs*v1.x - sn*v1.y, cs*v1.y + sn*v1.x);
            int idxD = ((j & ~(Ns - 1)) << 1) | (j & (Ns - 1));
            dt[idxD]      = make_float2(v0.x + w.x, v0.y + w.y);
            dt[idxD + Ns] = make_float2(v0.x - w.x, v0.y - w.y);
        }
        __syncthreads();
        cur ^= 1;
    }

    // ---- filter * conj, fold 1/N (and 0.125 for q) ----
    {
        double p = (double)fp[h];
        double sig = 1.0 / (1.0 + exp(-p));
        float cutoff = (float)floor((double)SEQ * sig);
        float sc = (isq ? 0.125f : 1.0f) / (float)SEQ;
        float2* P = buf[cur];
        for (int i = tid; i < SEQ; i += 256) {
            float rel = (float)i - cutoff;
            float A = (rel >= 0.f) ? __expf(-rel * (4.0f / SEQ)) : 1.0f;
            A *= sc;
            float2 v = P[i];
            P[i] = make_float2(A * v.x, -A * v.y);
        }
    }
    __syncthreads();

    // ---- second forward FFT ----
    #pragma unroll 1
    for (int Ns = 1; Ns < SEQ; Ns <<= 1) {
        const float2* s = buf[cur];
        float2* dt = buf[cur ^ 1];
        const float na = -(float)M_PI / Ns;
        for (int j = tid; j < SEQ/2; j += 256) {
            float2 v0 = s[j];
            float2 v1 = s[j + SEQ/2];
            float ang = na * (j & (Ns - 1));
            float sn, cs; __sincosf(ang, &sn, &cs);
            float2 w = make_float2(cs*v1.x - sn*v1.y, cs*v1.y + sn*v1.x);
            int idxD = ((j & ~(Ns - 1)) << 1) | (j & (Ns - 1));
            dt[idxD]      = make_float2(v0.x + w.x, v0.y + w.y);
            dt[idxD + Ns] = make_float2(v0.x - w.x, v0.y - w.y);
        }
        __syncthreads();
        cur ^= 1;
    }

    // ---- store real part ----
    {
        const float2* P = buf[cur];
        for (int i = tid; i < SEQ; i += 256)
            dst[(size_t)i * HD] = P[i].x;
    }
}

// ============================================================
// NT tensor-core GEMM (bf16 3-term split), LDSM fragment loads.
// block 128x128, TK=32, 8 warps (4m x 2n). Stride 20 (80B, LDSM-safe).
// ============================================================
template<class Epi>
__global__ __launch_bounds__(256) void mma_nt_bf(const float* __restrict__ A,
                                                 const float* __restrict__ B,
                                                 int K, size_t sA, size_t sB, Epi epi)
{
    __shared__ __align__(16) unsigned Ah[128*20], Al[128*20];
    __shared__ __align__(16) unsigned Bh[128*20], Bl[128*20];
    const int m0 = blockIdx.y * 128, n0 = blockIdx.x * 128;
    const float* Ab = A + (size_t)blockIdx.z * sA;
    const float* Bb = B + (size_t)blockIdx.z * sB;
    const int tid = threadIdx.x, lane = tid & 31, wid = tid >> 5;
    const int wm = (wid >> 1) * 32, wn = (wid & 1) * 64;
    const int g = lane >> 2, t = lane & 3;
    const int tl = lane >> 3, rw = lane & 7;

    const unsigned ah_s = sptr(Ah), al_s = sptr(Al);
    const unsigned bh_s = sptr(Bh), bl_s = sptr(Bl);

    float C[2][8][4] = {};

    for (int k0 = 0; k0 < K; k0 += 32) {
        #pragma unroll
        for (int it = 0; it < 8; it++) {
            int i = tid + 256*it;
            int mm = i >> 4, kp = i & 15;
            float2 e = *(const float2*)(Ab + (size_t)(m0+mm)*K + k0 + 2*kp);
            unsigned hi, lo;
            split_bf16_pair(e.x, e.y, hi, lo);
            Ah[mm*20 + kp] = hi; Al[mm*20 + kp] = lo;
            float2 f = *(const float2*)(Bb + (size_t)(n0+mm)*K + k0 + 2*kp);
            split_bf16_pair(f.x, f.y, hi, lo);
            Bh[mm*20 + kp] = hi; Bl[mm*20 + kp] = lo;
        }
        __syncthreads();
        #pragma unroll
        for (int c = 0; c < 2; c++) {
            unsigned ah[2][4], al[2][4];
            #pragma unroll
            for (int im = 0; im < 2; im++) {
                unsigned off = (unsigned)(((wm + 16*im + 8*(tl & 1) + rw)*20
                                           + 8*c + 4*(tl >> 1)) * 4);
                ldsm_x4(ah[im][0], ah[im][1], ah[im][2], ah[im][3], ah_s + off);
                ldsm_x4(al[im][0], al[im][1], al[im][2], al[im][3], al_s + off);
            }
            #pragma unroll
            for (int jnp = 0; jnp < 4; jnp++) {
                unsigned off = (unsigned)(((wn + 8*(2*jnp + (tl >> 1)) + rw)*20
                                           + 8*c + 4*(tl & 1)) * 4);
                unsigned b0, b1, b2, b3, c0, c1, c2, c3;
                ldsm_x4(b0, b1, b2, b3, bh_s + off);
                ldsm_x4(c0, c1, c2, c3, bl_s + off);
                unsigned bh2[2] = { b0, b1 }, bl2[2] = { c0, c1 };
                unsigned bh3[2] = { b2, b3 }, bl3[2] = { c2, c3 };
                #pragma unroll
                for (int im = 0; im < 2; im++) {
                    mma16bf(C[im][2*jnp],   ah[im], bh2);
                    mma16bf(C[im][2*jnp],   ah[im], bl2);
                    mma16bf(C[im][2*jnp],   al[im], bh2);
                    mma16bf(C[im][2*jnp+1], ah[im], bh3);
                    mma16bf(C[im][2*jnp+1], ah[im], bl3);
                    mma16bf(C[im][2*jnp+1], al[im], bh3);
                }
            }
        }
        __syncthreads();
    }
    #pragma unroll
    for (int im = 0; im < 2; im++)
        #pragma unroll
        for (int jn = 0; jn < 8; jn++) {
            int r  = m0 + wm + im*16 + g;
            int cc = n0 + wn + jn*8 + 2*t;
            epi.store2(blockIdx.z, r,   cc, C[im][jn][0], C[im][jn][1]);
            epi.store2(blockIdx.z, r+8, cc, C[im][jn][2], C[im][jn][3]);
        }
}

// ============================================================
// Fused flash attention, bf16-split + LDSM, 128-kv superstep.
// grid (SEQ/128, BB*NH), 256 threads, 2 blocks/SM, dynamic smem 70KB.
// ============================================================
__global__ __launch_bounds__(256,2) void flash_attn()
{
    extern __shared__ __align__(16) unsigned dsm[];
    unsigned* Khs = dsm;                 // [128 kv][dpair 32] stride 36
    unsigned* Kls = Khs + 128*36;
    unsigned* Vhs = Kls + 128*36;        // [d 64][kvpair 64] stride 68
    unsigned* Vls = Vhs + 64*68;

    const int bh = blockIdx.y;
    const int m0 = blockIdx.x * 128;
    const float* qf = g_qf + (size_t)bh * SEQ * HD;
    const float* kf = g_kf + (size_t)bh * SEQ * HD;
    const float* vv = g_v  + (size_t)bh * SEQ * HD;

    const int tid = threadIdx.x, lane = tid & 31, w = tid >> 5;
    const int g = lane >> 2, t = lane & 3;
    const int tl = lane >> 3, rw = lane & 7;

    const unsigned khs_s = sptr(Khs), kls_s = sptr(Kls);
    const unsigned vhs_s = sptr(Vhs), vls_s = sptr(Vls);

    // persistent Q fragments (bf16 split, packed pairs)
    unsigned qh[4][4], ql[4][4];
    {
        const float* r0 = qf + (size_t)(m0 + 16*w + g) * HD;
        const float* r1 = r0 + 8*HD;
        #pragma unroll
        for (int c = 0; c < 4; c++) {
            split_bf16_pair(r0[16*c + 2*t],     r0[16*c + 2*t + 1], qh[c][0], ql[c][0]);
            split_bf16_pair(r1[16*c + 2*t],     r1[16*c + 2*t + 1], qh[c][1], ql[c][1]);
            split_bf16_pair(r0[16*c + 8 + 2*t], r0[16*c + 9 + 2*t], qh[c][2], ql[c][2]);
            split_bf16_pair(r1[16*c + 8 + 2*t], r1[16*c + 9 + 2*t], qh[c][3], ql[c][3]);
        }
    }

    float O[8][4] = {};
    float mr0 = -1e30f, mr1 = -1e30f, l0 = 0.f, l1 = 0.f;

    for (int k0 = 0; k0 < SEQ; k0 += 128) {
        // ---- stage K: 128 kv rows x 64 d ----
        #pragma unroll
        for (int j = 0; j < 8; j++) {
            int r  = (tid >> 2) + 64*(j >> 2);
            int qd = (tid & 3) + 4*(j & 3);
            float4 kx = *(const float4*)(kf + (size_t)(k0 + r)*HD + qd*4);
            unsigned h01, l01, h23, l23;
            split_bf16_pair(kx.x, kx.y, h01, l01);
            split_bf16_pair(kx.z, kx.w, h23, l23);
            int p = 2*qd;
            Khs[r*36 + p] = h01; Khs[r*36 + p + 1] = h23;
            Kls[r*36 + p] = l01; Kls[r*36 + p + 1] = l23;
        }
        // ---- stage V: pairs 0..63 (128 kv), transposed ----
        #pragma unroll
        for (int j = 0; j < 4; j++) {
            int i = tid + 256*j;
            int kp = i & 63, d0 = (i >> 6) * 4;
            float4 a = *(const float4*)(vv + (size_t)(k0 + 2*kp)*HD + d0);
            float4 b = *(const float4*)(vv + (size_t)(k0 + 2*kp + 1)*HD + d0);
            const float ae[4] = {a.x, a.y, a.z, a.w};
            const float be[4] = {b.x, b.y, b.z, b.w};
            #pragma unroll
            for (int e = 0; e < 4; e++) {
                unsigned hi, lo;
                split_bf16_pair(ae[e], be[e], hi, lo);
                Vhs[(d0+e)*68 + kp] = hi;
                Vls[(d0+e)*68 + kp] = lo;
            }
        }
        __syncthreads();

        // ---- two 64-kv chunks ----
        #pragma unroll
        for (int ch = 0; ch < 2; ch++) {
            // S = Qf Kf^T
            float S[8][4] = {};
            #pragma unroll
            for (int c = 0; c < 4; c++) {
                #pragma unroll
                for (int jnp = 0; jnp < 4; jnp++) {
                    unsigned off = (unsigned)((((64*ch + 8*(2*jnp + (tl >> 1)) + rw)*36
                                                + 8*c + 4*(tl & 1))) * 4);
                    unsigned b0, b1, b2, b3, c0, c1, c2, c3;
                    ldsm_x4(b0, b1, b2, b3, khs_s + off);
                    ldsm_x4(c0, c1, c2, c3, kls_s + off);
                    unsigned bh2[2] = { b0, b1 }, bl2[2] = { c0, c1 };
                    unsigned bh3[2] = { b2, b3 }, bl3[2] = { c2, c3 };
                    mma16bf(S[2*jnp],   qh[c], bh2);
                    mma16bf(S[2*jnp],   qh[c], bl2);
                    mma16bf(S[2*jnp],   ql[c], bh2);
                    mma16bf(S[2*jnp+1], qh[c], bh3);
                    mma16bf(S[2*jnp+1], qh[c], bl3);
                    mma16bf(S[2*jnp+1], ql[c], bh3);
                }
            }

            // online softmax
            float rm0 = -1e30f, rm1 = -1e30f;
            #pragma unroll
            for (int jn = 0; jn < 8; jn++) {
                rm0 = fmaxf(rm0, fmaxf(S[jn][0], S[jn][1]));
                rm1 = fmaxf(rm1, fmaxf(S[jn][2], S[jn][3]));
            }
            rm0 = fmaxf(rm0, __shfl_xor_sync(0xffffffffu, rm0, 1));
            rm0 = fmaxf(rm0, __shfl_xor_sync(0xffffffffu, rm0, 2));
            rm1 = fmaxf(rm1, __shfl_xor_sync(0xffffffffu, rm1, 1));
            rm1 = fmaxf(rm1, __shfl_xor_sync(0xffffffffu, rm1, 2));
            float mn0 = fmaxf(mr0, rm0), mn1 = fmaxf(mr1, rm1);
            float a0 = __expf(mr0 - mn0), a1 = __expf(mr1 - mn1);
            mr0 = mn0; mr1 = mn1;

            #pragma unroll
            for (int jn = 0; jn < 8; jn++) {
                O[jn][0] *= a0; O[jn][1] *= a0; O[jn][2] *= a1; O[jn][3] *= a1;
            }

            // P conversion + P@V in two halves
            float ps0 = 0.f, ps1 = 0.f;
            #pragma unroll
            for (int half = 0; half < 2; half++) {
                unsigned ph[4][2], pl[4][2];
                #pragma unroll
                for (int q4 = 0; q4 < 4; q4++) {
                    int jn = 4*half + q4;
                    float p0 = __expf(S[jn][0] - mn0);
                    float p1 = __expf(S[jn][1] - mn0);
                    float p2 = __expf(S[jn][2] - mn1);
                    float p3 = __expf(S[jn][3] - mn1);
                    ps0 += p0 + p1; ps1 += p2 + p3;
                    split_bf16_pair(p0, p1, ph[q4][0], pl[q4][0]);
                    split_bf16_pair(p2, p3, ph[q4][1], pl[q4][1]);
                }
                #pragma unroll
                for (int kc2 = 0; kc2 < 2; kc2++) {
                    int kc = 32*ch + 8*(2*half + kc2);
                    unsigned ah2[4] = { ph[2*kc2][0], ph[2*kc2][1], ph[2*kc2+1][0], ph[2*kc2+1][1] };
                    unsigned al2[4] = { pl[2*kc2][0], pl[2*kc2][1], pl[2*kc2+1][0], pl[2*kc2+1][1] };
                    #pragma unroll
                    for (int jnp = 0; jnp < 4; jnp++) {
                        unsigned off = (unsigned)((((8*(2*jnp + (tl >> 1)) + rw)*68
                                                    + kc + 4*(tl & 1))) * 4);
                        unsigned b0, b1, b2, b3, c0, c1, c2, c3;
                        ldsm_x4(b0, b1, b2, b3, vhs_s + off);
                        ldsm_x4(c0, c1, c2, c3, vls_s + off);
                        unsigned bh2[2] = { b0, b1 }, bl2[2] = { c0, c1 };
                        unsigned bh3[2] = { b2, b3 }, bl3[2] = { c2, c3 };
                        mma16bf(O[2*jnp],   ah2, bh2);
                        mma16bf(O[2*jnp],   ah2, bl2);
                        mma16bf(O[2*jnp],   al2, bh2);
                        mma16bf(O[2*jnp+1], ah2, bh3);
                        mma16bf(O[2*jnp+1], ah2, bl3);
                        mma16bf(O[2*jnp+1], al2, bh3);
                    }
                }
            }
            l0 = l0*a0 + ps0; l1 = l1*a1 + ps1;
        }
        __syncthreads();
    }

    // ---- epilogue ----
    l0 += __shfl_xor_sync(0xffffffffu, l0, 1);
    l0 += __shfl_xor_sync(0xffffffffu, l0, 2);
    l1 += __shfl_xor_sync(0xffffffffu, l1, 1);
    l1 += __shfl_xor_sync(0xffffffffu, l1, 2);
    float i0 = 1.f / l0, i1 = 1.f / l1;

    const int b = bh / NH, hh = bh - b*NH;
    const int r0 = m0 + 16*w + g, r1 = r0 + 8;
    #pragma unroll
    for (int jn = 0; jn < 8; jn++) {
        int cc = 8*jn + 2*t;
        *(float2*)&g_Ot[((size_t)(b*SEQ + r0))*CD + hh*HD + cc] =
            make_float2(O[jn][0]*i0, O[jn][1]*i0);
        *(float2*)&g_Ot[((size_t)(b*SEQ + r1))*CD + hh*HD + cc] =
            make_float2(O[jn][2]*i1, O[jn][3]*i1);
    }
}

// ---- epilogues ----
struct EpiQKV {
    __device__ void store2(int, int r, int c, float v0, float v1) const {
        int b = r >> 11, n = r & (SEQ-1);
        int s = c / CD; int rem = c - s*CD;
        int h = rem >> 6, d = rem & 63;
        float* dst = (s == 0) ? g_q : ((s == 1) ? g_k : g_v);
        *(float2*)&dst[(((size_t)b*NH + h)*SEQ + n)*HD + d] = make_float2(v0, v1);
    }
};
struct EpiOut {
    float* out; const float* pb;
    __device__ void store2(int, int r, int c, float v0, float v1) const {
        *(float2*)&out[(size_t)r*CD + c] = make_float2(v0 + pb[c], v1 + pb[c+1]);
    }
};

extern "C" void kernel_launch(void* const* d_in, const int* /*in_sizes*/, int /*n_in*/,
                              void* d_out, int /*out_size*/)
{
    const float* x      = (const float*)d_in[0];
    const float* qkv_w  = (const float*)d_in[1];
    const float* proj_w = (const float*)d_in[2];
    const float* proj_b = (const float*)d_in[3];
    const float* fp     = (const float*)d_in[4];
    float* out = (float*)d_out;

    float *p_Ot;
    cudaGetSymbolAddress((void**)&p_Ot, g_Ot);

    constexpr int FLASH_SMEM = (2*128*36 + 2*64*68) * 4;   // 71680 B
    cudaFuncSetAttribute(flash_attn, cudaFuncAttributeMaxDynamicSharedMemorySize, FLASH_SMEM);

    // 1. QKV projection (bf16 split, LDSM)
    mma_nt_bf<<<dim3(QD/128, MROWS/128, 1), 256>>>(x, qkv_w, CD,
                                                   (size_t)0, (size_t)0, EpiQKV{});
    // 2. spectral filtering via in-smem FFT (q scale + 1/N folded)
    fft_filter<<<dim3(HD, BB*NH, 2), 256>>>(fp);
    // 3-5. fused attention, bf16 split, LDSM, 128-kv superstep
    flash_attn<<<dim3(SEQ/128, BB*NH), 256, FLASH_SMEM>>>();
    // 6. output projection + bias (bf16 split, LDSM)
    mma_nt_bf<<<dim3(CD/128, MROWS/128, 1), 256>>>(p_Ot, proj_w, CD,
                                                   (size_t)0, (size_t)0, EpiOut{out, proj_b});
}

// round 13
// speedup vs baseline: 3.8812x; 1.2023x over previous
#include <cuda_runtime.h>
#include <math.h>

#ifndef M_PI
#define M_PI 3.14159265358979323846
#endif

namespace {
constexpr int BB  = 2;
constexpr int NH  = 12;
constexpr int SEQ = 2048;
constexpr int HD  = 64;
constexpr int CD  = 768;
constexpr int QD  = 2304;
constexpr int MROWS = BB * SEQ;  // 4096
}

// ---- scratch ----
__device__ float g_q [BB*NH*SEQ*HD];
__device__ float g_k [BB*NH*SEQ*HD];
__device__ float g_v [BB*NH*SEQ*HD];
__device__ float g_qf[BB*NH*SEQ*HD];
__device__ float g_kf[BB*NH*SEQ*HD];
__device__ float g_Ot[BB*SEQ*CD];
// pre-split bf16 planes
__device__ unsigned g_kh[BB*NH*SEQ*32], g_kl[BB*NH*SEQ*32];   // [bh][kv][dpair]
__device__ unsigned g_vh[BB*NH*SEQ*32], g_vl[BB*NH*SEQ*32];   // [bh][kb][d][kvpair]

// ============================================================
// mma helpers
// ============================================================
__device__ __forceinline__ void mma16bf(float* c, const unsigned* a, const unsigned* b) {
    asm volatile(
        "mma.sync.aligned.m16n8k16.row.col.f32.bf16.bf16.f32 "
        "{%0,%1,%2,%3}, {%4,%5,%6,%7}, {%8,%9}, {%0,%1,%2,%3};"
        : "+f"(c[0]), "+f"(c[1]), "+f"(c[2]), "+f"(c[3])
        : "r"(a[0]), "r"(a[1]), "r"(a[2]), "r"(a[3]), "r"(b[0]), "r"(b[1]));
}
__device__ __forceinline__ void split_bf16_pair(float xe, float xo, unsigned& hi, unsigned& lo) {
    unsigned h;
    asm("cvt.rn.bf16x2.f32 %0, %1, %2;" : "=r"(h) : "f"(xo), "f"(xe));
    float re = xe - __uint_as_float(h << 16);
    float ro = xo - __uint_as_float(h & 0xffff0000u);
    unsigned l;
    asm("cvt.rn.bf16x2.f32 %0, %1, %2;" : "=r"(l) : "f"(ro), "f"(re));
    hi = h; lo = l;
}
__device__ __forceinline__ unsigned sptr(const void* p) {
    return (unsigned)__cvta_generic_to_shared(p);
}
__device__ __forceinline__ void ldsm_x4(unsigned& r0, unsigned& r1, unsigned& r2, unsigned& r3,
                                        unsigned addr) {
    asm volatile("ldmatrix.sync.aligned.m8n8.x4.shared.b16 {%0,%1,%2,%3}, [%4];"
                 : "=r"(r0), "=r"(r1), "=r"(r2), "=r"(r3) : "r"(addr));
}

// ============================================================
// Spectral filter via in-smem Stockham FFT (unchanged).
// ============================================================
__global__ __launch_bounds__(256) void fft_filter(const float* __restrict__ fp)
{
    __shared__ float2 buf[2][SEQ];

    const int d  = blockIdx.x;
    const int bh = blockIdx.y;
    const int h  = bh % NH;
    const bool isq = (blockIdx.z == 0);
    const float* src = (isq ? g_q : g_k) + (size_t)bh * SEQ * HD + d;
    float*       dst = (isq ? g_qf : g_kf) + (size_t)bh * SEQ * HD + d;
    const int tid = threadIdx.x;

    for (int i = tid; i < SEQ; i += 256)
        buf[0][i] = make_float2(src[(size_t)i * HD], 0.f);
    __syncthreads();

    int cur = 0;
    #pragma unroll 1
    for (int Ns = 1; Ns < SEQ; Ns <<= 1) {
        const float2* s = buf[cur];
        float2* dt = buf[cur ^ 1];
        const float na = -(float)M_PI / Ns;
        for (int j = tid; j < SEQ/2; j += 256) {
            float2 v0 = s[j];
            float2 v1 = s[j + SEQ/2];
            float ang = na * (j & (Ns - 1));
            float sn, cs; __sincosf(ang, &sn, &cs);
            float2 w = make_float2(cs*v1.x - sn*v1.y, cs*v1.y + sn*v1.x);
            int idxD = ((j & ~(Ns - 1)) << 1) | (j & (Ns - 1));
            dt[idxD]      = make_float2(v0.x + w.x, v0.y + w.y);
            dt[idxD + Ns] = make_float2(v0.x - w.x, v0.y - w.y);
        }
        __syncthreads();
        cur ^= 1;
    }

    {
        double p = (double)fp[h];
        double sig = 1.0 / (1.0 + exp(-p));
        float cutoff = (float)floor((double)SEQ * sig);
        float sc = (isq ? 0.125f : 1.0f) / (float)SEQ;
        float2* P = buf[cur];
        for (int i = tid; i < SEQ; i += 256) {
            float rel = (float)i - cutoff;
            float A = (rel >= 0.f) ? __expf(-rel * (4.0f / SEQ)) : 1.0f;
            A *= sc;
            float2 v = P[i];
            P[i] = make_float2(A * v.x, -A * v.y);
        }
    }
    __syncthreads();

    #pragma unroll 1
    for (int Ns = 1; Ns < SEQ; Ns <<= 1) {
        const float2* s = buf[cur];
        float2* dt = buf[cur ^ 1];
        const float na = -(float)M_PI / Ns;
        for (int j = tid; j < SEQ/2; j += 256) {
            float2 v0 = s[j];
            float2 v1 = s[j + SEQ/2];
            float ang = na * (j & (Ns - 1));
            float sn, cs; __sincosf(ang, &sn, &cs);
            float2 w = make_float2(cs*v1.x - sn*v1.y, cs*v1.y + sn*v1.x);
            int idxD = ((j & ~(Ns - 1)) << 1) | (j & (Ns - 1));
            dt[idxD]      = make_float2(v0.x + w.x, v0.y + w.y);
            dt[idxD + Ns] = make_float2(v0.x - w.x, v0.y - w.y);
        }
        __syncthreads();
        cur ^= 1;
    }

    {
        const float2* P = buf[cur];
        for (int i = tid; i < SEQ; i += 256)
            dst[(size_t)i * HD] = P[i].x;
    }
}

// ============================================================
// Repack K: g_kf (fp32 [bh][kv][64]) -> bf16 hi/lo pair planes.
// Pair p of a row = contiguous floats (2p, 2p+1).
// ============================================================
__global__ __launch_bounds__(256) void repack_k()
{
    int idx = blockIdx.x * 256 + threadIdx.x;    // global pair index
    float2 e = *(const float2*)(g_kf + (size_t)idx * 2);
    unsigned hi, lo;
    split_bf16_pair(e.x, e.y, hi, lo);
    g_kh[idx] = hi;
    g_kl[idx] = lo;
}

// ============================================================
// Repack V: g_v (fp32 [bh][kv][64]) -> transposed bf16 planes
// [bh][kb][d 64][kvpair 64] (kv paired). Block per (kb, bh).
// ============================================================
__global__ __launch_bounds__(256) void repack_v()
{
    __shared__ float vs[128*65];
    const int kb = blockIdx.x, bh = blockIdx.y;
    const float* src = g_v + ((size_t)bh * SEQ + kb * 128) * HD;
    const int tid = threadIdx.x;

    for (int i = tid; i < 128*16; i += 256) {       // 128 rows x 16 float4
        int r = i >> 4, q4 = (i & 15) * 4;
        float4 t = *(const float4*)(src + (size_t)r * HD + q4);
        vs[r*65 + q4]     = t.x;
        vs[r*65 + q4 + 1] = t.y;
        vs[r*65 + q4 + 2] = t.z;
        vs[r*65 + q4 + 3] = t.w;
    }
    __syncthreads();

    unsigned* dh = g_vh + ((size_t)bh * 16 + kb) * 64 * 64;
    unsigned* dl = g_vl + ((size_t)bh * 16 + kb) * 64 * 64;
    for (int i = tid; i < 64*64; i += 256) {
        int d = i >> 6, kp = i & 63;
        float e = vs[(2*kp)*65 + d];
        float o = vs[(2*kp + 1)*65 + d];
        unsigned hi, lo;
        split_bf16_pair(e, o, hi, lo);
        dh[i] = hi;
        dl[i] = lo;
    }
}

// ============================================================
// NT tensor-core GEMM (bf16 3-term split), LDSM, 2 blocks/SM.
// ============================================================
template<class Epi>
__global__ __launch_bounds__(256,2) void mma_nt_bf(const float* __restrict__ A,
                                                   const float* __restrict__ B,
                                                   int K, size_t sA, size_t sB, Epi epi)
{
    __shared__ __align__(16) unsigned Ah[128*20], Al[128*20];
    __shared__ __align__(16) unsigned Bh[128*20], Bl[128*20];
    const int m0 = blockIdx.y * 128, n0 = blockIdx.x * 128;
    const float* Ab = A + (size_t)blockIdx.z * sA;
    const float* Bb = B + (size_t)blockIdx.z * sB;
    const int tid = threadIdx.x, lane = tid & 31, wid = tid >> 5;
    const int wm = (wid >> 1) * 32, wn = (wid & 1) * 64;
    const int g = lane >> 2, t = lane & 3;
    const int tl = lane >> 3, rw = lane & 7;

    const unsigned ah_s = sptr(Ah), al_s = sptr(Al);
    const unsigned bh_s = sptr(Bh), bl_s = sptr(Bl);

    float C[2][8][4] = {};

    for (int k0 = 0; k0 < K; k0 += 32) {
        #pragma unroll
        for (int it = 0; it < 8; it++) {
            int i = tid + 256*it;
            int mm = i >> 4, kp = i & 15;
            float2 e = *(const float2*)(Ab + (size_t)(m0+mm)*K + k0 + 2*kp);
            unsigned hi, lo;
            split_bf16_pair(e.x, e.y, hi, lo);
            Ah[mm*20 + kp] = hi; Al[mm*20 + kp] = lo;
            float2 f = *(const float2*)(Bb + (size_t)(n0+mm)*K + k0 + 2*kp);
            split_bf16_pair(f.x, f.y, hi, lo);
            Bh[mm*20 + kp] = hi; Bl[mm*20 + kp] = lo;
        }
        __syncthreads();
        #pragma unroll
        for (int c = 0; c < 2; c++) {
            unsigned ah[2][4], al[2][4];
            #pragma unroll
            for (int im = 0; im < 2; im++) {
                unsigned off = (unsigned)(((wm + 16*im + 8*(tl & 1) + rw)*20
                                           + 8*c + 4*(tl >> 1)) * 4);
                ldsm_x4(ah[im][0], ah[im][1], ah[im][2], ah[im][3], ah_s + off);
                ldsm_x4(al[im][0], al[im][1], al[im][2], al[im][3], al_s + off);
            }
            #pragma unroll
            for (int jnp = 0; jnp < 4; jnp++) {
                unsigned off = (unsigned)(((wn + 8*(2*jnp + (tl >> 1)) + rw)*20
                                           + 8*c + 4*(tl & 1)) * 4);
                unsigned b0, b1, b2, b3, c0, c1, c2, c3;
                ldsm_x4(b0, b1, b2, b3, bh_s + off);
                ldsm_x4(c0, c1, c2, c3, bl_s + off);
                unsigned bh2[2] = { b0, b1 }, bl2[2] = { c0, c1 };
                unsigned bh3[2] = { b2, b3 }, bl3[2] = { c2, c3 };
                #pragma unroll
                for (int im = 0; im < 2; im++) {
                    mma16bf(C[im][2*jnp],   ah[im], bh2);
                    mma16bf(C[im][2*jnp],   ah[im], bl2);
                    mma16bf(C[im][2*jnp],   al[im], bh2);
                    mma16bf(C[im][2*jnp+1], ah[im], bh3);
                    mma16bf(C[im][2*jnp+1], ah[im], bl3);
                    mma16bf(C[im][2*jnp+1], al[im], bh3);
                }
            }
        }
        __syncthreads();
    }
    #pragma unroll
    for (int im = 0; im < 2; im++)
        #pragma unroll
        for (int jn = 0; jn < 8; jn++) {
            int r  = m0 + wm + im*16 + g;
            int cc = n0 + wn + jn*8 + 2*t;
            epi.store2(blockIdx.z, r,   cc, C[im][jn][0], C[im][jn][1]);
            epi.store2(blockIdx.z, r+8, cc, C[im][jn][2], C[im][jn][3]);
        }
}

// ============================================================
// Fused flash attention: staging now pure uint4 copies of
// pre-split planes. 128-kv superstep, 2 chunks, LDSM, 2 blocks/SM.
// ============================================================
__global__ __launch_bounds__(256,2) void flash_attn()
{
    extern __shared__ __align__(16) unsigned dsm[];
    unsigned* Khs = dsm;                 // [128 kv][dpair 32] stride 36
    unsigned* Kls = Khs + 128*36;
    unsigned* Vhs = Kls + 128*36;        // [d 64][kvpair 64] stride 68
    unsigned* Vls = Vhs + 64*68;

    const int bh = blockIdx.y;
    const int m0 = blockIdx.x * 128;
    const float* qf = g_qf + (size_t)bh * SEQ * HD;

    const int tid = threadIdx.x, lane = tid & 31, w = tid >> 5;
    const int g = lane >> 2, t = lane & 3;
    const int tl = lane >> 3, rw = lane & 7;

    const unsigned khs_s = sptr(Khs), kls_s = sptr(Kls);
    const unsigned vhs_s = sptr(Vhs), vls_s = sptr(Vls);

    // persistent Q fragments (bf16 split, packed pairs)
    unsigned qh[4][4], ql[4][4];
    {
        const float* r0 = qf + (size_t)(m0 + 16*w + g) * HD;
        const float* r1 = r0 + 8*HD;
        #pragma unroll
        for (int c = 0; c < 4; c++) {
            split_bf16_pair(r0[16*c + 2*t],     r0[16*c + 2*t + 1], qh[c][0], ql[c][0]);
            split_bf16_pair(r1[16*c + 2*t],     r1[16*c + 2*t + 1], qh[c][1], ql[c][1]);
            split_bf16_pair(r0[16*c + 8 + 2*t], r0[16*c + 9 + 2*t], qh[c][2], ql[c][2]);
            split_bf16_pair(r1[16*c + 8 + 2*t], r1[16*c + 9 + 2*t], qh[c][3], ql[c][3]);
        }
    }

    float O[8][4] = {};
    float mr0 = -1e30f, mr1 = -1e30f, l0 = 0.f, l1 = 0.f;

    for (int k0 = 0; k0 < SEQ; k0 += 128) {
        // ---- stage K planes: 128 rows x 32 pairs (uint4 copies) ----
        {
            const unsigned* kh_g = g_kh + ((size_t)bh * SEQ + k0) * 32;
            const unsigned* kl_g = g_kl + ((size_t)bh * SEQ + k0) * 32;
            #pragma unroll
            for (int j = 0; j < 4; j++) {
                int i = tid + 256*j;               // 1024 uint4 per plane
                int r = i >> 3, p4 = (i & 7) * 4;
                *(uint4*)&Khs[r*36 + p4] = *(const uint4*)&kh_g[r*32 + p4];
                *(uint4*)&Kls[r*36 + p4] = *(const uint4*)&kl_g[r*32 + p4];
            }
        }
        // ---- stage V planes: 64 d x 64 pairs ----
        {
            const unsigned* vh_g = g_vh + ((size_t)bh * 16 + (k0 >> 7)) * 64 * 64;
            const unsigned* vl_g = g_vl + ((size_t)bh * 16 + (k0 >> 7)) * 64 * 64;
            #pragma unroll
            for (int j = 0; j < 4; j++) {
                int i = tid + 256*j;               // 1024 uint4 per plane
                int d = i >> 4, p4 = (i & 15) * 4;
                *(uint4*)&Vhs[d*68 + p4] = *(const uint4*)&vh_g[d*64 + p4];
                *(uint4*)&Vls[d*68 + p4] = *(const uint4*)&vl_g[d*64 + p4];
            }
        }
        __syncthreads();

        // ---- two 64-kv chunks ----
        #pragma unroll
        for (int ch = 0; ch < 2; ch++) {
            float S[8][4] = {};
            #pragma unroll
            for (int c = 0; c < 4; c++) {
                #pragma unroll
                for (int jnp = 0; jnp < 4; jnp++) {
                    unsigned off = (unsigned)((((64*ch + 8*(2*jnp + (tl >> 1)) + rw)*36
                                                + 8*c + 4*(tl & 1))) * 4);
                    unsigned b0, b1, b2, b3, c0, c1, c2, c3;
                    ldsm_x4(b0, b1, b2, b3, khs_s + off);
                    ldsm_x4(c0, c1, c2, c3, kls_s + off);
                    unsigned bh2[2] = { b0, b1 }, bl2[2] = { c0, c1 };
                    unsigned bh3[2] = { b2, b3 }, bl3[2] = { c2, c3 };
                    mma16bf(S[2*jnp],   qh[c], bh2);
                    mma16bf(S[2*jnp],   qh[c], bl2);
                    mma16bf(S[2*jnp],   ql[c], bh2);
                    mma16bf(S[2*jnp+1], qh[c], bh3);
                    mma16bf(S[2*jnp+1], qh[c], bl3);
                    mma16bf(S[2*jnp+1], ql[c], bh3);
                }
            }

            float rm0 = -1e30f, rm1 = -1e30f;
            #pragma unroll
            for (int jn = 0; jn < 8; jn++) {
                rm0 = fmaxf(rm0, fmaxf(S[jn][0], S[jn][1]));
                rm1 = fmaxf(rm1, fmaxf(S[jn][2], S[jn][3]));
            }
            rm0 = fmaxf(rm0, __shfl_xor_sync(0xffffffffu, rm0, 1));
            rm0 = fmaxf(rm0, __shfl_xor_sync(0xffffffffu, rm0, 2));
            rm1 = fmaxf(rm1, __shfl_xor_sync(0xffffffffu, rm1, 1));
            rm1 = fmaxf(rm1, __shfl_xor_sync(0xffffffffu, rm1, 2));
            float mn0 = fmaxf(mr0, rm0), mn1 = fmaxf(mr1, rm1);
            float a0 = __expf(mr0 - mn0), a1 = __expf(mr1 - mn1);
            mr0 = mn0; mr1 = mn1;

            #pragma unroll
            for (int jn = 0; jn < 8; jn++) {
                O[jn][0] *= a0; O[jn][1] *= a0; O[jn][2] *= a1; O[jn][3] *= a1;
            }

            float ps0 = 0.f, ps1 = 0.f;
            #pragma unroll
            for (int half = 0; half < 2; half++) {
                unsigned ph[4][2], pl[4][2];
                #pragma unroll
                for (int q4 = 0; q4 < 4; q4++) {
                    int jn = 4*half + q4;
                    float p0 = __expf(S[jn][0] - mn0);
                    float p1 = __expf(S[jn][1] - mn0);
                    float p2 = __expf(S[jn][2] - mn1);
                    float p3 = __expf(S[jn][3] - mn1);
                    ps0 += p0 + p1; ps1 += p2 + p3;
                    split_bf16_pair(p0, p1, ph[q4][0], pl[q4][0]);
                    split_bf16_pair(p2, p3, ph[q4][1], pl[q4][1]);
                }
                #pragma unroll
                for (int kc2 = 0; kc2 < 2; kc2++) {
                    int kc = 32*ch + 8*(2*half + kc2);
                    unsigned ah2[4] = { ph[2*kc2][0], ph[2*kc2][1], ph[2*kc2+1][0], ph[2*kc2+1][1] };
                    unsigned al2[4] = { pl[2*kc2][0], pl[2*kc2][1], pl[2*kc2+1][0], pl[2*kc2+1][1] };
                    #pragma unroll
                    for (int jnp = 0; jnp < 4; jnp++) {
                        unsigned off = (unsigned)((((8*(2*jnp + (tl >> 1)) + rw)*68
                                                    + kc + 4*(tl & 1))) * 4);
                        unsigned b0, b1, b2, b3, c0, c1, c2, c3;
                        ldsm_x4(b0, b1, b2, b3, vhs_s + off);
                        ldsm_x4(c0, c1, c2, c3, vls_s + off);
                        unsigned bh2[2] = { b0, b1 }, bl2[2] = { c0, c1 };
                        unsigned bh3[2] = { b2, b3 }, bl3[2] = { c2, c3 };
                        mma16bf(O[2*jnp],   ah2, bh2);
                        mma16bf(O[2*jnp],   ah2, bl2);
                        mma16bf(O[2*jnp],   al2, bh2);
                        mma16bf(O[2*jnp+1], ah2, bh3);
                        mma16bf(O[2*jnp+1], ah2, bl3);
                        mma16bf(O[2*jnp+1], al2, bh3);
                    }
                }
            }
            l0 = l0*a0 + ps0; l1 = l1*a1 + ps1;
        }
        __syncthreads();
    }

    // ---- epilogue ----
    l0 += __shfl_xor_sync(0xffffffffu, l0, 1);
    l0 += __shfl_xor_sync(0xffffffffu, l0, 2);
    l1 += __shfl_xor_sync(0xffffffffu, l1, 1);
    l1 += __shfl_xor_sync(0xffffffffu, l1, 2);
    float i0 = 1.f / l0, i1 = 1.f / l1;

    const int b = bh / NH, hh = bh - b*NH;
    const int r0 = m0 + 16*w + g, r1 = r0 + 8;
    #pragma unroll
    for (int jn = 0; jn < 8; jn++) {
        int cc = 8*jn + 2*t;
        *(float2*)&g_Ot[((size_t)(b*SEQ + r0))*CD + hh*HD + cc] =
            make_float2(O[jn][0]*i0, O[jn][1]*i0);
        *(float2*)&g_Ot[((size_t)(b*SEQ + r1))*CD + hh*HD + cc] =
            make_float2(O[jn][2]*i1, O[jn][3]*i1);
    }
}

// ---- epilogues ----
struct EpiQKV {
    __device__ void store2(int, int r, int c, float v0, float v1) const {
        int b = r >> 11, n = r & (SEQ-1);
        int s = c / CD; int rem = c - s*CD;
        int h = rem >> 6, d = rem & 63;
        float* dst = (s == 0) ? g_q : ((s == 1) ? g_k : g_v);
        *(float2*)&dst[(((size_t)b*NH + h)*SEQ + n)*HD + d] = make_float2(v0, v1);
    }
};
struct EpiOut {
    float* out; const float* pb;
    __device__ void store2(int, int r, int c, float v0, float v1) const {
        *(float2*)&out[(size_t)r*CD + c] = make_float2(v0 + pb[c], v1 + pb[c+1]);
    }
};

extern "C" void kernel_launch(void* const* d_in, const int* /*in_sizes*/, int /*n_in*/,
                              void* d_out, int /*out_size*/)
{
    const float* x      = (const float*)d_in[0];
    const float* qkv_w  = (const float*)d_in[1];
    const float* proj_w = (const float*)d_in[2];
    const float* proj_b = (const float*)d_in[3];
    const float* fp     = (const float*)d_in[4];
    float* out = (float*)d_out;

    float *p_Ot;
    cudaGetSymbolAddress((void**)&p_Ot, g_Ot);

    constexpr int FLASH_SMEM = (2*128*36 + 2*64*68) * 4;   // 71680 B
    cudaFuncSetAttribute(flash_attn, cudaFuncAttributeMaxDynamicSharedMemorySize, FLASH_SMEM);

    // 1. QKV projection (bf16 split, LDSM, 2 blocks/SM)
    mma_nt_bf<<<dim3(QD/128, MROWS/128, 1), 256>>>(x, qkv_w, CD,
                                                   (size_t)0, (size_t)0, EpiQKV{});
    // 2. spectral filtering via in-smem FFT
    fft_filter<<<dim3(HD, BB*NH, 2), 256>>>(fp);
    // 3. pre-split K and V into bf16 hi/lo planes
    repack_k<<<BB*NH*SEQ*32/256, 256>>>();
    repack_v<<<dim3(16, BB*NH), 256>>>();
    // 4-6. fused attention (pure-copy staging)
    flash_attn<<<dim3(SEQ/128, BB*NH), 256, FLASH_SMEM>>>();
    // 7. output projection + bias
    mma_nt_bf<<<dim3(CD/128, MROWS/128, 1), 256>>>(p_Ot, proj_w, CD,
                                                   (size_t)0, (size_t)0, EpiOut{out, proj_b});
}

// round 14
// speedup vs baseline: 3.9656x; 1.0218x over previous
#include <cuda_runtime.h>
#include <math.h>

#ifndef M_PI
#define M_PI 3.14159265358979323846
#endif

namespace {
constexpr int BB  = 2;
constexpr int NH  = 12;
constexpr int SEQ = 2048;
constexpr int HD  = 64;
constexpr int CD  = 768;
constexpr int QD  = 2304;
constexpr int MROWS = BB * SEQ;  // 4096
}

// ---- scratch ----
__device__ float g_q [BB*NH*SEQ*HD];
__device__ float g_k [BB*NH*SEQ*HD];
__device__ float g_v [BB*NH*SEQ*HD];
__device__ float g_qf[BB*NH*SEQ*HD];
__device__ float g_kf[BB*NH*SEQ*HD];
__device__ float g_Ot[BB*SEQ*CD];
// pre-split bf16 planes
__device__ unsigned g_kh[BB*NH*SEQ*32], g_kl[BB*NH*SEQ*32];   // [bh][kv][dpair]
__device__ unsigned g_vh[BB*NH*SEQ*32], g_vl[BB*NH*SEQ*32];   // [bh][kt 32][d 64][kvpair 32]

// ============================================================
// helpers
// ============================================================
__device__ __forceinline__ void mma16bf(float* c, const unsigned* a, const unsigned* b) {
    asm volatile(
        "mma.sync.aligned.m16n8k16.row.col.f32.bf16.bf16.f32 "
        "{%0,%1,%2,%3}, {%4,%5,%6,%7}, {%8,%9}, {%0,%1,%2,%3};"
        : "+f"(c[0]), "+f"(c[1]), "+f"(c[2]), "+f"(c[3])
        : "r"(a[0]), "r"(a[1]), "r"(a[2]), "r"(a[3]), "r"(b[0]), "r"(b[1]));
}
__device__ __forceinline__ void split_bf16_pair(float xe, float xo, unsigned& hi, unsigned& lo) {
    unsigned h;
    asm("cvt.rn.bf16x2.f32 %0, %1, %2;" : "=r"(h) : "f"(xo), "f"(xe));
    float re = xe - __uint_as_float(h << 16);
    float ro = xo - __uint_as_float(h & 0xffff0000u);
    unsigned l;
    asm("cvt.rn.bf16x2.f32 %0, %1, %2;" : "=r"(l) : "f"(ro), "f"(re));
    hi = h; lo = l;
}
__device__ __forceinline__ unsigned sptr(const void* p) {
    return (unsigned)__cvta_generic_to_shared(p);
}
__device__ __forceinline__ void ldsm_x4(unsigned& r0, unsigned& r1, unsigned& r2, unsigned& r3,
                                        unsigned addr) {
    asm volatile("ldmatrix.sync.aligned.m8n8.x4.shared.b16 {%0,%1,%2,%3}, [%4];"
                 : "=r"(r0), "=r"(r1), "=r"(r2), "=r"(r3) : "r"(addr));
}
__device__ __forceinline__ void cp16(unsigned smem_byte, const void* gptr) {
    asm volatile("cp.async.cg.shared.global [%0], [%1], 16;"
                 :: "r"(smem_byte), "l"(gptr));
}

// ============================================================
// Spectral filter via in-smem Stockham FFT (unchanged).
// ============================================================
__global__ __launch_bounds__(256) void fft_filter(const float* __restrict__ fp)
{
    __shared__ float2 buf[2][SEQ];

    const int d  = blockIdx.x;
    const int bh = blockIdx.y;
    const int h  = bh % NH;
    const bool isq = (blockIdx.z == 0);
    const float* src = (isq ? g_q : g_k) + (size_t)bh * SEQ * HD + d;
    float*       dst = (isq ? g_qf : g_kf) + (size_t)bh * SEQ * HD + d;
    const int tid = threadIdx.x;

    for (int i = tid; i < SEQ; i += 256)
        buf[0][i] = make_float2(src[(size_t)i * HD], 0.f);
    __syncthreads();

    int cur = 0;
    #pragma unroll 1
    for (int Ns = 1; Ns < SEQ; Ns <<= 1) {
        const float2* s = buf[cur];
        float2* dt = buf[cur ^ 1];
        const float na = -(float)M_PI / Ns;
        for (int j = tid; j < SEQ/2; j += 256) {
            float2 v0 = s[j];
            float2 v1 = s[j + SEQ/2];
            float ang = na * (j & (Ns - 1));
            float sn, cs; __sincosf(ang, &sn, &cs);
            float2 w = make_float2(cs*v1.x - sn*v1.y, cs*v1.y + sn*v1.x);
            int idxD = ((j & ~(Ns - 1)) << 1) | (j & (Ns - 1));
            dt[idxD]      = make_float2(v0.x + w.x, v0.y + w.y);
            dt[idxD + Ns] = make_float2(v0.x - w.x, v0.y - w.y);
        }
        __syncthreads();
        cur ^= 1;
    }

    {
        double p = (double)fp[h];
        double sig = 1.0 / (1.0 + exp(-p));
        float cutoff = (float)floor((double)SEQ * sig);
        float sc = (isq ? 0.125f : 1.0f) / (float)SEQ;
        float2* P = buf[cur];
        for (int i = tid; i < SEQ; i += 256) {
            float rel = (float)i - cutoff;
            float A = (rel >= 0.f) ? __expf(-rel * (4.0f / SEQ)) : 1.0f;
            A *= sc;
            float2 v = P[i];
            P[i] = make_float2(A * v.x, -A * v.y);
        }
    }
    __syncthreads();

    #pragma unroll 1
    for (int Ns = 1; Ns < SEQ; Ns <<= 1) {
        const float2* s = buf[cur];
        float2* dt = buf[cur ^ 1];
        const float na = -(float)M_PI / Ns;
        for (int j = tid; j < SEQ/2; j += 256) {
            float2 v0 = s[j];
            float2 v1 = s[j + SEQ/2];
            float ang = na * (j & (Ns - 1));
            float sn, cs; __sincosf(ang, &sn, &cs);
            float2 w = make_float2(cs*v1.x - sn*v1.y, cs*v1.y + sn*v1.x);
            int idxD = ((j & ~(Ns - 1)) << 1) | (j & (Ns - 1));
            dt[idxD]      = make_float2(v0.x + w.x, v0.y + w.y);
            dt[idxD + Ns] = make_float2(v0.x - w.x, v0.y - w.y);
        }
        __syncthreads();
        cur ^= 1;
    }

    {
        const float2* P = buf[cur];
        for (int i = tid; i < SEQ; i += 256)
            dst[(size_t)i * HD] = P[i].x;
    }
}

// ============================================================
// Repack K: g_kf -> bf16 hi/lo pair planes (pairs along d).
// ============================================================
__global__ __launch_bounds__(256) void repack_k()
{
    int idx = blockIdx.x * 256 + threadIdx.x;
    float2 e = *(const float2*)(g_kf + (size_t)idx * 2);
    unsigned hi, lo;
    split_bf16_pair(e.x, e.y, hi, lo);
    g_kh[idx] = hi;
    g_kl[idx] = lo;
}

// ============================================================
// Repack V: g_v -> transposed planes [bh][kt 32][d 64][kvpair 32].
// Block per (kt, bh), kt = 64-kv tile.
// ============================================================
__global__ __launch_bounds__(256) void repack_v()
{
    __shared__ float vs[64*65];
    const int kt = blockIdx.x, bh = blockIdx.y;
    const float* src = g_v + ((size_t)bh * SEQ + kt * 64) * HD;
    const int tid = threadIdx.x;

    for (int i = tid; i < 64*16; i += 256) {        // 64 rows x 16 float4
        int r = i >> 4, q4 = (i & 15) * 4;
        float4 t = *(const float4*)(src + (size_t)r * HD + q4);
        vs[r*65 + q4]     = t.x;
        vs[r*65 + q4 + 1] = t.y;
        vs[r*65 + q4 + 2] = t.z;
        vs[r*65 + q4 + 3] = t.w;
    }
    __syncthreads();

    unsigned* dh = g_vh + ((size_t)bh * 32 + kt) * 64 * 32;
    unsigned* dl = g_vl + ((size_t)bh * 32 + kt) * 64 * 32;
    for (int i = tid; i < 64*32; i += 256) {
        int d = i >> 5, kp = i & 31;
        float e = vs[(2*kp)*65 + d];
        float o = vs[(2*kp + 1)*65 + d];
        unsigned hi, lo;
        split_bf16_pair(e, o, hi, lo);
        dh[i] = hi;
        dl[i] = lo;
    }
}

// ============================================================
// NT tensor-core GEMM (bf16 3-term split), LDSM, 2 blocks/SM.
// ============================================================
template<class Epi>
__global__ __launch_bounds__(256,2) void mma_nt_bf(const float* __restrict__ A,
                                                   const float* __restrict__ B,
                                                   int K, size_t sA, size_t sB, Epi epi)
{
    __shared__ __align__(16) unsigned Ah[128*20], Al[128*20];
    __shared__ __align__(16) unsigned Bh[128*20], Bl[128*20];
    const int m0 = blockIdx.y * 128, n0 = blockIdx.x * 128;
    const float* Ab = A + (size_t)blockIdx.z * sA;
    const float* Bb = B + (size_t)blockIdx.z * sB;
    const int tid = threadIdx.x, lane = tid & 31, wid = tid >> 5;
    const int wm = (wid >> 1) * 32, wn = (wid & 1) * 64;
    const int g = lane >> 2, t = lane & 3;
    const int tl = lane >> 3, rw = lane & 7;

    const unsigned ah_s = sptr(Ah), al_s = sptr(Al);
    const unsigned bh_s = sptr(Bh), bl_s = sptr(Bl);

    float C[2][8][4] = {};

    for (int k0 = 0; k0 < K; k0 += 32) {
        #pragma unroll
        for (int it = 0; it < 8; it++) {
            int i = tid + 256*it;
            int mm = i >> 4, kp = i & 15;
            float2 e = *(const float2*)(Ab + (size_t)(m0+mm)*K + k0 + 2*kp);
            unsigned hi, lo;
            split_bf16_pair(e.x, e.y, hi, lo);
            Ah[mm*20 + kp] = hi; Al[mm*20 + kp] = lo;
            float2 f = *(const float2*)(Bb + (size_t)(n0+mm)*K + k0 + 2*kp);
            split_bf16_pair(f.x, f.y, hi, lo);
            Bh[mm*20 + kp] = hi; Bl[mm*20 + kp] = lo;
        }
        __syncthreads();
        #pragma unroll
        for (int c = 0; c < 2; c++) {
            unsigned ah[2][4], al[2][4];
            #pragma unroll
            for (int im = 0; im < 2; im++) {
                unsigned off = (unsigned)(((wm + 16*im + 8*(tl & 1) + rw)*20
                                           + 8*c + 4*(tl >> 1)) * 4);
                ldsm_x4(ah[im][0], ah[im][1], ah[im][2], ah[im][3], ah_s + off);
                ldsm_x4(al[im][0], al[im][1], al[im][2], al[im][3], al_s + off);
            }
            #pragma unroll
            for (int jnp = 0; jnp < 4; jnp++) {
                unsigned off = (unsigned)(((wn + 8*(2*jnp + (tl >> 1)) + rw)*20
                                           + 8*c + 4*(tl & 1)) * 4);
                unsigned b0, b1, b2, b3, c0, c1, c2, c3;
                ldsm_x4(b0, b1, b2, b3, bh_s + off);
                ldsm_x4(c0, c1, c2, c3, bl_s + off);
                unsigned bh2[2] = { b0, b1 }, bl2[2] = { c0, c1 };
                unsigned bh3[2] = { b2, b3 }, bl3[2] = { c2, c3 };
                #pragma unroll
                for (int im = 0; im < 2; im++) {
                    mma16bf(C[im][2*jnp],   ah[im], bh2);
                    mma16bf(C[im][2*jnp],   ah[im], bl2);
                    mma16bf(C[im][2*jnp],   al[im], bh2);
                    mma16bf(C[im][2*jnp+1], ah[im], bh3);
                    mma16bf(C[im][2*jnp+1], ah[im], bl3);
                    mma16bf(C[im][2*jnp+1], al[im], bh3);
                }
            }
        }
        __syncthreads();
    }
    #pragma unroll
    for (int im = 0; im < 2; im++)
        #pragma unroll
        for (int jn = 0; jn < 8; jn++) {
            int r  = m0 + wm + im*16 + g;
            int cc = n0 + wn + jn*8 + 2*t;
            epi.store2(blockIdx.z, r,   cc, C[im][jn][0], C[im][jn][1]);
            epi.store2(blockIdx.z, r+8, cc, C[im][jn][2], C[im][jn][3]);
        }
}

// ============================================================
// Fused flash attention: no-max softmax (scores bounded),
// cp.async 3-stage pipelined staging, 64-kv tiles, LDSM.
// grid (SEQ/128, BB*NH), 256 threads, 2 blocks/SM, smem 108KB.
// ============================================================
__global__ __launch_bounds__(256,2) void flash_attn()
{
    extern __shared__ __align__(16) unsigned dsm[];
    constexpr unsigned STG = 36864;      // bytes per stage
    constexpr unsigned KL_OFF = 9216, VH_OFF = 18432, VL_OFF = 27648;
    constexpr int NT = SEQ / 64;         // 32 kv tiles

    const int bh = blockIdx.y;
    const int m0 = blockIdx.x * 128;
    const float* qf = g_qf + (size_t)bh * SEQ * HD;
    const unsigned* kh_g = g_kh + (size_t)bh * SEQ * 32;
    const unsigned* kl_g = g_kl + (size_t)bh * SEQ * 32;
    const unsigned* vh_g = g_vh + (size_t)bh * SEQ * 32;
    const unsigned* vl_g = g_vl + (size_t)bh * SEQ * 32;

    const int tid = threadIdx.x, lane = tid & 31, w = tid >> 5;
    const int g = lane >> 2, t4 = lane & 3;
    const int tl = lane >> 3, rw = lane & 7;
    const unsigned smem0 = sptr(dsm);

    // persistent Q fragments (bf16 split, packed pairs)
    unsigned qh[4][4], ql[4][4];
    {
        const float* r0 = qf + (size_t)(m0 + 16*w + g) * HD;
        const float* r1 = r0 + 8*HD;
        #pragma unroll
        for (int c = 0; c < 4; c++) {
            split_bf16_pair(r0[16*c + 2*t4],     r0[16*c + 2*t4 + 1], qh[c][0], ql[c][0]);
            split_bf16_pair(r1[16*c + 2*t4],     r1[16*c + 2*t4 + 1], qh[c][1], ql[c][1]);
            split_bf16_pair(r0[16*c + 8 + 2*t4], r0[16*c + 9 + 2*t4], qh[c][2], ql[c][2]);
            split_bf16_pair(r1[16*c + 8 + 2*t4], r1[16*c + 9 + 2*t4], qh[c][3], ql[c][3]);
        }
    }

    auto issue = [&](int kt, int s) {
        unsigned base = smem0 + (unsigned)s * STG;
        const unsigned* kh = kh_g + kt*64*32;
        const unsigned* kl = kl_g + kt*64*32;
        const unsigned* vh = vh_g + kt*64*32;
        const unsigned* vl = vl_g + kt*64*32;
        #pragma unroll
        for (int j = 0; j < 2; j++) {
            int i = tid + 256*j;
            int r = i >> 3, p4 = (i & 7) * 4;
            unsigned doff = (unsigned)((r*36 + p4) * 4);
            cp16(base + doff,          kh + r*32 + p4);
            cp16(base + KL_OFF + doff, kl + r*32 + p4);
            cp16(base + VH_OFF + doff, vh + r*32 + p4);
            cp16(base + VL_OFF + doff, vl + r*32 + p4);
        }
    };

    float O[8][4] = {};
    float l0 = 0.f, l1 = 0.f;

    issue(0, 0);
    asm volatile("cp.async.commit_group;" ::: "memory");
    issue(1, 1);
    asm volatile("cp.async.commit_group;" ::: "memory");

    int s = 0;
    for (int kt = 0; kt < NT; kt++) {
        asm volatile("cp.async.wait_group 1;" ::: "memory");
        __syncthreads();
        if (kt + 2 < NT) issue(kt + 2, (s + 2) % 3);
        asm volatile("cp.async.commit_group;" ::: "memory");

        const unsigned khs_b = smem0 + (unsigned)s * STG;
        const unsigned kls_b = khs_b + KL_OFF;
        const unsigned vhs_b = khs_b + VH_OFF;
        const unsigned vls_b = khs_b + VL_OFF;

        // ---- S = Qf Kf^T ----
        float S[8][4] = {};
        #pragma unroll
        for (int c = 0; c < 4; c++) {
            #pragma unroll
            for (int jnp = 0; jnp < 4; jnp++) {
                unsigned off = (unsigned)(((8*(2*jnp + (tl >> 1)) + rw)*36
                                           + 8*c + 4*(tl & 1)) * 4);
                unsigned b0, b1, b2, b3, c0, c1, c2, c3;
                ldsm_x4(b0, b1, b2, b3, khs_b + off);
                ldsm_x4(c0, c1, c2, c3, kls_b + off);
                unsigned bh2[2] = { b0, b1 }, bl2[2] = { c0, c1 };
                unsigned bh3[2] = { b2, b3 }, bl3[2] = { c2, c3 };
                mma16bf(S[2*jnp],   qh[c], bh2);
                mma16bf(S[2*jnp],   qh[c], bl2);
                mma16bf(S[2*jnp],   ql[c], bh2);
                mma16bf(S[2*jnp+1], qh[c], bh3);
                mma16bf(S[2*jnp+1], qh[c], bl3);
                mma16bf(S[2*jnp+1], ql[c], bh3);
            }
        }

        // ---- softmax numerator (no max subtraction; scores bounded) ----
        float ps0 = 0.f, ps1 = 0.f;
        #pragma unroll
        for (int half = 0; half < 2; half++) {
            unsigned ph[4][2], pl[4][2];
            #pragma unroll
            for (int q4 = 0; q4 < 4; q4++) {
                int jn = 4*half + q4;
                float p0 = __expf(S[jn][0]);
                float p1 = __expf(S[jn][1]);
                float p2 = __expf(S[jn][2]);
                float p3 = __expf(S[jn][3]);
                ps0 += p0 + p1; ps1 += p2 + p3;
                split_bf16_pair(p0, p1, ph[q4][0], pl[q4][0]);
                split_bf16_pair(p2, p3, ph[q4][1], pl[q4][1]);
            }
            #pragma unroll
            for (int kc2 = 0; kc2 < 2; kc2++) {
                int kc = 8*(2*half + kc2);
                unsigned ah2[4] = { ph[2*kc2][0], ph[2*kc2][1], ph[2*kc2+1][0], ph[2*kc2+1][1] };
                unsigned al2[4] = { pl[2*kc2][0], pl[2*kc2][1], pl[2*kc2+1][0], pl[2*kc2+1][1] };
                #pragma unroll
                for (int jnp = 0; jnp < 4; jnp++) {
                    unsigned off = (unsigned)(((8*(2*jnp + (tl >> 1)) + rw)*36
                                               + kc + 4*(tl & 1)) * 4);
                    unsigned b0, b1, b2, b3, c0, c1, c2, c3;
                    ldsm_x4(b0, b1, b2, b3, vhs_b + off);
                    ldsm_x4(c0, c1, c2, c3, vls_b + off);
                    unsigned bh2[2] = { b0, b1 }, bl2[2] = { c0, c1 };
                    unsigned bh3[2] = { b2, b3 }, bl3[2] = { c2, c3 };
                    mma16bf(O[2*jnp],   ah2, bh2);
                    mma16bf(O[2*jnp],   ah2, bl2);
                    mma16bf(O[2*jnp],   al2, bh2);
                    mma16bf(O[2*jnp+1], ah2, bh3);
                    mma16bf(O[2*jnp+1], ah2, bl3);
                    mma16bf(O[2*jnp+1], al2, bh3);
                }
            }
        }
        l0 += ps0; l1 += ps1;
        s = (s + 1) % 3;
    }

    // ---- epilogue ----
    l0 += __shfl_xor_sync(0xffffffffu, l0, 1);
    l0 += __shfl_xor_sync(0xffffffffu, l0, 2);
    l1 += __shfl_xor_sync(0xffffffffu, l1, 1);
    l1 += __shfl_xor_sync(0xffffffffu, l1, 2);
    float i0 = 1.f / l0, i1 = 1.f / l1;

    const int b = bh / NH, hh = bh - b*NH;
    const int r0 = m0 + 16*w + g, r1 = r0 + 8;
    #pragma unroll
    for (int jn = 0; jn < 8; jn++) {
        int cc = 8*jn + 2*t4;
        *(float2*)&g_Ot[((size_t)(b*SEQ + r0))*CD + hh*HD + cc] =
            make_float2(O[jn][0]*i0, O[jn][1]*i0);
        *(float2*)&g_Ot[((size_t)(b*SEQ + r1))*CD + hh*HD + cc] =
            make_float2(O[jn][2]*i1, O[jn][3]*i1);
    }
}

// ---- epilogues ----
struct EpiQKV {
    __device__ void store2(int, int r, int c, float v0, float v1) const {
        int b = r >> 11, n = r & (SEQ-1);
        int s = c / CD; int rem = c - s*CD;
        int h = rem >> 6, d = rem & 63;
        float* dst = (s == 0) ? g_q : ((s == 1) ? g_k : g_v);
        *(float2*)&dst[(((size_t)b*NH + h)*SEQ + n)*HD + d] = make_float2(v0, v1);
    }
};
struct EpiOut {
    float* out; const float* pb;
    __device__ void store2(int, int r, int c, float v0, float v1) const {
        *(float2*)&out[(size_t)r*CD + c] = make_float2(v0 + pb[c], v1 + pb[c+1]);
    }
};

extern "C" void kernel_launch(void* const* d_in, const int* /*in_sizes*/, int /*n_in*/,
                              void* d_out, int /*out_size*/)
{
    const float* x      = (const float*)d_in[0];
    const float* qkv_w  = (const float*)d_in[1];
    const float* proj_w = (const float*)d_in[2];
    const float* proj_b = (const float*)d_in[3];
    const float* fp     = (const float*)d_in[4];
    float* out = (float*)d_out;

    float *p_Ot;
    cudaGetSymbolAddress((void**)&p_Ot, g_Ot);

    constexpr int FLASH_SMEM = 3 * 36864;   // 110592 B (3-stage pipeline)
    cudaFuncSetAttribute(flash_attn, cudaFuncAttributeMaxDynamicSharedMemorySize, FLASH_SMEM);

    // 1. QKV projection (bf16 split, LDSM, 2 blocks/SM)
    mma_nt_bf<<<dim3(QD/128, MROWS/128, 1), 256>>>(x, qkv_w, CD,
                                                   (size_t)0, (size_t)0, EpiQKV{});
    // 2. spectral filtering via in-smem FFT
    fft_filter<<<dim3(HD, BB*NH, 2), 256>>>(fp);
    // 3. pre-split K and V into bf16 hi/lo planes
    repack_k<<<BB*NH*SEQ*32/256, 256>>>();
    repack_v<<<dim3(32, BB*NH), 256>>>();
    // 4-6. fused attention (no-max softmax, cp.async pipeline)
    flash_attn<<<dim3(SEQ/128, BB*NH), 256, FLASH_SMEM>>>();
    // 7. output projection + bias
    mma_nt_bf<<<dim3(CD/128, MROWS/128, 1), 256>>>(p_Ot, proj_w, CD,
                                                   (size_t)0, (size_t)0, EpiOut{out, proj_b});
}

// round 15
// speedup vs baseline: 4.0111x; 1.0115x over previous
#include <cuda_runtime.h>
#include <math.h>

#ifndef M_PI
#define M_PI 3.14159265358979323846
#endif

namespace {
constexpr int BB  = 2;
constexpr int NH  = 12;
constexpr int SEQ = 2048;
constexpr int HD  = 64;
constexpr int CD  = 768;
constexpr int QD  = 2304;
constexpr int MROWS = BB * SEQ;  // 4096
}

// ---- scratch ----
__device__ float g_q [BB*NH*SEQ*HD];
__device__ float g_k [BB*NH*SEQ*HD];
__device__ float g_v [BB*NH*SEQ*HD];
__device__ float g_qf[BB*NH*SEQ*HD];
__device__ float g_kf[BB*NH*SEQ*HD];
__device__ float g_Ot[BB*SEQ*CD];
// split-kv partials
__device__ float g_Op[2][BB*NH*SEQ*HD];
__device__ float g_lp[2][BB*NH*SEQ];
// pre-split bf16 planes
__device__ unsigned g_kh[BB*NH*SEQ*32], g_kl[BB*NH*SEQ*32];   // [bh][kv][dpair]
__device__ unsigned g_vh[BB*NH*SEQ*32], g_vl[BB*NH*SEQ*32];   // [bh][kt 32][d 64][kvpair 32]

// ============================================================
// helpers
// ============================================================
__device__ __forceinline__ void mma16bf(float* c, const unsigned* a, const unsigned* b) {
    asm volatile(
        "mma.sync.aligned.m16n8k16.row.col.f32.bf16.bf16.f32 "
        "{%0,%1,%2,%3}, {%4,%5,%6,%7}, {%8,%9}, {%0,%1,%2,%3};"
        : "+f"(c[0]), "+f"(c[1]), "+f"(c[2]), "+f"(c[3])
        : "r"(a[0]), "r"(a[1]), "r"(a[2]), "r"(a[3]), "r"(b[0]), "r"(b[1]));
}
__device__ __forceinline__ void split_bf16_pair(float xe, float xo, unsigned& hi, unsigned& lo) {
    unsigned h;
    asm("cvt.rn.bf16x2.f32 %0, %1, %2;" : "=r"(h) : "f"(xo), "f"(xe));
    float re = xe - __uint_as_float(h << 16);
    float ro = xo - __uint_as_float(h & 0xffff0000u);
    unsigned l;
    asm("cvt.rn.bf16x2.f32 %0, %1, %2;" : "=r"(l) : "f"(ro), "f"(re));
    hi = h; lo = l;
}
__device__ __forceinline__ unsigned sptr(const void* p) {
    return (unsigned)__cvta_generic_to_shared(p);
}
__device__ __forceinline__ void ldsm_x4(unsigned& r0, unsigned& r1, unsigned& r2, unsigned& r3,
                                        unsigned addr) {
    asm volatile("ldmatrix.sync.aligned.m8n8.x4.shared.b16 {%0,%1,%2,%3}, [%4];"
                 : "=r"(r0), "=r"(r1), "=r"(r2), "=r"(r3) : "r"(addr));
}
__device__ __forceinline__ void cp16(unsigned smem_byte, const void* gptr) {
    asm volatile("cp.async.cg.shared.global [%0], [%1], 16;"
                 :: "r"(smem_byte), "l"(gptr));
}

// ============================================================
// Spectral filter via in-smem Stockham FFT (unchanged).
// ============================================================
__global__ __launch_bounds__(256) void fft_filter(const float* __restrict__ fp)
{
    __shared__ float2 buf[2][SEQ];

    const int d  = blockIdx.x;
    const int bh = blockIdx.y;
    const int h  = bh % NH;
    const bool isq = (blockIdx.z == 0);
    const float* src = (isq ? g_q : g_k) + (size_t)bh * SEQ * HD + d;
    float*       dst = (isq ? g_qf : g_kf) + (size_t)bh * SEQ * HD + d;
    const int tid = threadIdx.x;

    for (int i = tid; i < SEQ; i += 256)
        buf[0][i] = make_float2(src[(size_t)i * HD], 0.f);
    __syncthreads();

    int cur = 0;
    #pragma unroll 1
    for (int Ns = 1; Ns < SEQ; Ns <<= 1) {
        const float2* s = buf[cur];
        float2* dt = buf[cur ^ 1];
        const float na = -(float)M_PI / Ns;
        for (int j = tid; j < SEQ/2; j += 256) {
            float2 v0 = s[j];
            float2 v1 = s[j + SEQ/2];
            float ang = na * (j & (Ns - 1));
            float sn, cs; __sincosf(ang, &sn, &cs);
            float2 w = make_float2(cs*v1.x - sn*v1.y, cs*v1.y + sn*v1.x);
            int idxD = ((j & ~(Ns - 1)) << 1) | (j & (Ns - 1));
            dt[idxD]      = make_float2(v0.x + w.x, v0.y + w.y);
            dt[idxD + Ns] = make_float2(v0.x - w.x, v0.y - w.y);
        }
        __syncthreads();
        cur ^= 1;
    }

    {
        double p = (double)fp[h];
        double sig = 1.0 / (1.0 + exp(-p));
        float cutoff = (float)floor((double)SEQ * sig);
        float sc = (isq ? 0.125f : 1.0f) / (float)SEQ;
        float2* P = buf[cur];
        for (int i = tid; i < SEQ; i += 256) {
            float rel = (float)i - cutoff;
            float A = (rel >= 0.f) ? __expf(-rel * (4.0f / SEQ)) : 1.0f;
            A *= sc;
            float2 v = P[i];
            P[i] = make_float2(A * v.x, -A * v.y);
        }
    }
    __syncthreads();

    #pragma unroll 1
    for (int Ns = 1; Ns < SEQ; Ns <<= 1) {
        const float2* s = buf[cur];
        float2* dt = buf[cur ^ 1];
        const float na = -(float)M_PI / Ns;
        for (int j = tid; j < SEQ/2; j += 256) {
            float2 v0 = s[j];
            float2 v1 = s[j + SEQ/2];
            float ang = na * (j & (Ns - 1));
            float sn, cs; __sincosf(ang, &sn, &cs);
            float2 w = make_float2(cs*v1.x - sn*v1.y, cs*v1.y + sn*v1.x);
            int idxD = ((j & ~(Ns - 1)) << 1) | (j & (Ns - 1));
            dt[idxD]      = make_float2(v0.x + w.x, v0.y + w.y);
            dt[idxD + Ns] = make_float2(v0.x - w.x, v0.y - w.y);
        }
        __syncthreads();
        cur ^= 1;
    }

    {
        const float2* P = buf[cur];
        for (int i = tid; i < SEQ; i += 256)
            dst[(size_t)i * HD] = P[i].x;
    }
}

// ============================================================
// Repack K: g_kf -> bf16 hi/lo pair planes (pairs along d).
// ============================================================
__global__ __launch_bounds__(256) void repack_k()
{
    int idx = blockIdx.x * 256 + threadIdx.x;
    float2 e = *(const float2*)(g_kf + (size_t)idx * 2);
    unsigned hi, lo;
    split_bf16_pair(e.x, e.y, hi, lo);
    g_kh[idx] = hi;
    g_kl[idx] = lo;
}

// ============================================================
// Repack V: g_v -> transposed planes [bh][kt 32][d 64][kvpair 32].
// ============================================================
__global__ __launch_bounds__(256) void repack_v()
{
    __shared__ float vs[64*65];
    const int kt = blockIdx.x, bh = blockIdx.y;
    const float* src = g_v + ((size_t)bh * SEQ + kt * 64) * HD;
    const int tid = threadIdx.x;

    for (int i = tid; i < 64*16; i += 256) {
        int r = i >> 4, q4 = (i & 15) * 4;
        float4 t = *(const float4*)(src + (size_t)r * HD + q4);
        vs[r*65 + q4]     = t.x;
        vs[r*65 + q4 + 1] = t.y;
        vs[r*65 + q4 + 2] = t.z;
        vs[r*65 + q4 + 3] = t.w;
    }
    __syncthreads();

    unsigned* dh = g_vh + ((size_t)bh * 32 + kt) * 64 * 32;
    unsigned* dl = g_vl + ((size_t)bh * 32 + kt) * 64 * 32;
    for (int i = tid; i < 64*32; i += 256) {
        int d = i >> 5, kp = i & 31;
        float e = vs[(2*kp)*65 + d];
        float o = vs[(2*kp + 1)*65 + d];
        unsigned hi, lo;
        split_bf16_pair(e, o, hi, lo);
        dh[i] = hi;
        dl[i] = lo;
    }
}

// ============================================================
// NT tensor-core GEMM (bf16 3-term split), LDSM, 2 blocks/SM.
// ============================================================
template<class Epi>
__global__ __launch_bounds__(256,2) void mma_nt_bf(const float* __restrict__ A,
                                                   const float* __restrict__ B,
                                                   int K, size_t sA, size_t sB, Epi epi)
{
    __shared__ __align__(16) unsigned Ah[128*20], Al[128*20];
    __shared__ __align__(16) unsigned Bh[128*20], Bl[128*20];
    const int m0 = blockIdx.y * 128, n0 = blockIdx.x * 128;
    const float* Ab = A + (size_t)blockIdx.z * sA;
    const float* Bb = B + (size_t)blockIdx.z * sB;
    const int tid = threadIdx.x, lane = tid & 31, wid = tid >> 5;
    const int wm = (wid >> 1) * 32, wn = (wid & 1) * 64;
    const int g = lane >> 2, t = lane & 3;
    const int tl = lane >> 3, rw = lane & 7;

    const unsigned ah_s = sptr(Ah), al_s = sptr(Al);
    const unsigned bh_s = sptr(Bh), bl_s = sptr(Bl);

    float C[2][8][4] = {};

    for (int k0 = 0; k0 < K; k0 += 32) {
        #pragma unroll
        for (int it = 0; it < 8; it++) {
            int i = tid + 256*it;
            int mm = i >> 4, kp = i & 15;
            float2 e = *(const float2*)(Ab + (size_t)(m0+mm)*K + k0 + 2*kp);
            unsigned hi, lo;
            split_bf16_pair(e.x, e.y, hi, lo);
            Ah[mm*20 + kp] = hi; Al[mm*20 + kp] = lo;
            float2 f = *(const float2*)(Bb + (size_t)(n0+mm)*K + k0 + 2*kp);
            split_bf16_pair(f.x, f.y, hi, lo);
            Bh[mm*20 + kp] = hi; Bl[mm*20 + kp] = lo;
        }
        __syncthreads();
        #pragma unroll
        for (int c = 0; c < 2; c++) {
            unsigned ah[2][4], al[2][4];
            #pragma unroll
            for (int im = 0; im < 2; im++) {
                unsigned off = (unsigned)(((wm + 16*im + 8*(tl & 1) + rw)*20
                                           + 8*c + 4*(tl >> 1)) * 4);
                ldsm_x4(ah[im][0], ah[im][1], ah[im][2], ah[im][3], ah_s + off);
                ldsm_x4(al[im][0], al[im][1], al[im][2], al[im][3], al_s + off);
            }
            #pragma unroll
            for (int jnp = 0; jnp < 4; jnp++) {
                unsigned off = (unsigned)(((wn + 8*(2*jnp + (tl >> 1)) + rw)*20
                                           + 8*c + 4*(tl & 1)) * 4);
                unsigned b0, b1, b2, b3, c0, c1, c2, c3;
                ldsm_x4(b0, b1, b2, b3, bh_s + off);
                ldsm_x4(c0, c1, c2, c3, bl_s + off);
                unsigned bh2[2] = { b0, b1 }, bl2[2] = { c0, c1 };
                unsigned bh3[2] = { b2, b3 }, bl3[2] = { c2, c3 };
                #pragma unroll
                for (int im = 0; im < 2; im++) {
                    mma16bf(C[im][2*jnp],   ah[im], bh2);
                    mma16bf(C[im][2*jnp],   ah[im], bl2);
                    mma16bf(C[im][2*jnp],   al[im], bh2);
                    mma16bf(C[im][2*jnp+1], ah[im], bh3);
                    mma16bf(C[im][2*jnp+1], ah[im], bl3);
                    mma16bf(C[im][2*jnp+1], al[im], bh3);
                }
            }
        }
        __syncthreads();
    }
    #pragma unroll
    for (int im = 0; im < 2; im++)
        #pragma unroll
        for (int jn = 0; jn < 8; jn++) {
            int r  = m0 + wm + im*16 + g;
            int cc = n0 + wn + jn*8 + 2*t;
            epi.store2(blockIdx.z, r,   cc, C[im][jn][0], C[im][jn][1]);
            epi.store2(blockIdx.z, r+8, cc, C[im][jn][2], C[im][jn][3]);
        }
}

// ============================================================
// Fused flash attention, split-KV: grid (16, 24, 2). Each block
// processes 16 of 32 kv tiles, writes unnormalized partial O + l.
// cp.async 3-stage pipeline, no-max softmax, LDSM, 2 blocks/SM.
// ============================================================
__global__ __launch_bounds__(256,2) void flash_attn()
{
    extern __shared__ __align__(16) unsigned dsm[];
    constexpr unsigned STG = 36864;
    constexpr unsigned KL_OFF = 9216, VH_OFF = 18432, VL_OFF = 27648;
    constexpr int NTL = 16;              // tiles per kv-half

    const int bh = blockIdx.y;
    const int m0 = blockIdx.x * 128;
    const int half = blockIdx.z;
    const int kt0 = half * NTL;
    const float* qf = g_qf + (size_t)bh * SEQ * HD;
    const unsigned* kh_g = g_kh + (size_t)bh * SEQ * 32;
    const unsigned* kl_g = g_kl + (size_t)bh * SEQ * 32;
    const unsigned* vh_g = g_vh + (size_t)bh * SEQ * 32;
    const unsigned* vl_g = g_vl + (size_t)bh * SEQ * 32;

    const int tid = threadIdx.x, lane = tid & 31, w = tid >> 5;
    const int g = lane >> 2, t4 = lane & 3;
    const int tl = lane >> 3, rw = lane & 7;
    const unsigned smem0 = sptr(dsm);

    // persistent Q fragments (bf16 split, packed pairs)
    unsigned qh[4][4], ql[4][4];
    {
        const float* r0 = qf + (size_t)(m0 + 16*w + g) * HD;
        const float* r1 = r0 + 8*HD;
        #pragma unroll
        for (int c = 0; c < 4; c++) {
            split_bf16_pair(r0[16*c + 2*t4],     r0[16*c + 2*t4 + 1], qh[c][0], ql[c][0]);
            split_bf16_pair(r1[16*c + 2*t4],     r1[16*c + 2*t4 + 1], qh[c][1], ql[c][1]);
            split_bf16_pair(r0[16*c + 8 + 2*t4], r0[16*c + 9 + 2*t4], qh[c][2], ql[c][2]);
            split_bf16_pair(r1[16*c + 8 + 2*t4], r1[16*c + 9 + 2*t4], qh[c][3], ql[c][3]);
        }
    }

    auto issue = [&](int kt, int s) {
        unsigned base = smem0 + (unsigned)s * STG;
        const unsigned* kh = kh_g + kt*64*32;
        const unsigned* kl = kl_g + kt*64*32;
        const unsigned* vh = vh_g + kt*64*32;
        const unsigned* vl = vl_g + kt*64*32;
        #pragma unroll
        for (int j = 0; j < 2; j++) {
            int i = tid + 256*j;
            int r = i >> 3, p4 = (i & 7) * 4;
            unsigned doff = (unsigned)((r*36 + p4) * 4);
            cp16(base + doff,          kh + r*32 + p4);
            cp16(base + KL_OFF + doff, kl + r*32 + p4);
            cp16(base + VH_OFF + doff, vh + r*32 + p4);
            cp16(base + VL_OFF + doff, vl + r*32 + p4);
        }
    };

    float O[8][4] = {};
    float l0 = 0.f, l1 = 0.f;

    issue(kt0 + 0, 0);
    asm volatile("cp.async.commit_group;" ::: "memory");
    issue(kt0 + 1, 1);
    asm volatile("cp.async.commit_group;" ::: "memory");

    int s = 0;
    for (int lt = 0; lt < NTL; lt++) {
        asm volatile("cp.async.wait_group 1;" ::: "memory");
        __syncthreads();
        if (lt + 2 < NTL) issue(kt0 + lt + 2, (s + 2) % 3);
        asm volatile("cp.async.commit_group;" ::: "memory");

        const unsigned khs_b = smem0 + (unsigned)s * STG;
        const unsigned kls_b = khs_b + KL_OFF;
        const unsigned vhs_b = khs_b + VH_OFF;
        const unsigned vls_b = khs_b + VL_OFF;

        // ---- S = Qf Kf^T ----
        float S[8][4] = {};
        #pragma unroll
        for (int c = 0; c < 4; c++) {
            #pragma unroll
            for (int jnp = 0; jnp < 4; jnp++) {
                unsigned off = (unsigned)(((8*(2*jnp + (tl >> 1)) + rw)*36
                                           + 8*c + 4*(tl & 1)) * 4);
                unsigned b0, b1, b2, b3, c0, c1, c2, c3;
                ldsm_x4(b0, b1, b2, b3, khs_b + off);
                ldsm_x4(c0, c1, c2, c3, kls_b + off);
                unsigned bh2[2] = { b0, b1 }, bl2[2] = { c0, c1 };
                unsigned bh3[2] = { b2, b3 }, bl3[2] = { c2, c3 };
                mma16bf(S[2*jnp],   qh[c], bh2);
                mma16bf(S[2*jnp],   qh[c], bl2);
                mma16bf(S[2*jnp],   ql[c], bh2);
                mma16bf(S[2*jnp+1], qh[c], bh3);
                mma16bf(S[2*jnp+1], qh[c], bl3);
                mma16bf(S[2*jnp+1], ql[c], bh3);
            }
        }

        // ---- softmax numerator (no max; scores bounded) ----
        float ps0 = 0.f, ps1 = 0.f;
        #pragma unroll
        for (int half2 = 0; half2 < 2; half2++) {
            unsigned ph[4][2], pl[4][2];
            #pragma unroll
            for (int q4 = 0; q4 < 4; q4++) {
                int jn = 4*half2 + q4;
                float p0 = __expf(S[jn][0]);
                float p1 = __expf(S[jn][1]);
                float p2 = __expf(S[jn][2]);
                float p3 = __expf(S[jn][3]);
                ps0 += p0 + p1; ps1 += p2 + p3;
                split_bf16_pair(p0, p1, ph[q4][0], pl[q4][0]);
                split_bf16_pair(p2, p3, ph[q4][1], pl[q4][1]);
            }
            #pragma unroll
            for (int kc2 = 0; kc2 < 2; kc2++) {
                int kc = 8*(2*half2 + kc2);
                unsigned ah2[4] = { ph[2*kc2][0], ph[2*kc2][1], ph[2*kc2+1][0], ph[2*kc2+1][1] };
                unsigned al2[4] = { pl[2*kc2][0], pl[2*kc2][1], pl[2*kc2+1][0], pl[2*kc2+1][1] };
                #pragma unroll
                for (int jnp = 0; jnp < 4; jnp++) {
                    unsigned off = (unsigned)(((8*(2*jnp + (tl >> 1)) + rw)*36
                                               + kc + 4*(tl & 1)) * 4);
                    unsigned b0, b1, b2, b3, c0, c1, c2, c3;
                    ldsm_x4(b0, b1, b2, b3, vhs_b + off);
                    ldsm_x4(c0, c1, c2, c3, vls_b + off);
                    unsigned bh2[2] = { b0, b1 }, bl2[2] = { c0, c1 };
                    unsigned bh3[2] = { b2, b3 }, bl3[2] = { c2, c3 };
                    mma16bf(O[2*jnp],   ah2, bh2);
                    mma16bf(O[2*jnp],   ah2, bl2);
                    mma16bf(O[2*jnp],   al2, bh2);
                    mma16bf(O[2*jnp+1], ah2, bh3);
                    mma16bf(O[2*jnp+1], ah2, bl3);
                    mma16bf(O[2*jnp+1], al2, bh3);
                }
            }
        }
        l0 += ps0; l1 += ps1;
        s = (s + 1) % 3;
    }

    // ---- epilogue: partial l (quad-reduced) + unnormalized O ----
    l0 += __shfl_xor_sync(0xffffffffu, l0, 1);
    l0 += __shfl_xor_sync(0xffffffffu, l0, 2);
    l1 += __shfl_xor_sync(0xffffffffu, l1, 1);
    l1 += __shfl_xor_sync(0xffffffffu, l1, 2);

    const size_t r0g = (size_t)bh * SEQ + m0 + 16*w + g;
    const size_t r1g = r0g + 8;
    float* op = g_Op[half];
    #pragma unroll
    for (int jn = 0; jn < 8; jn++) {
        int cc = 8*jn + 2*t4;
        *(float2*)&op[r0g*HD + cc] = make_float2(O[jn][0], O[jn][1]);
        *(float2*)&op[r1g*HD + cc] = make_float2(O[jn][2], O[jn][3]);
    }
    if (t4 == 0) {
        g_lp[half][r0g] = l0;
        g_lp[half][r1g] = l1;
    }
}

// ============================================================
// Combine split-KV partials: O = (O0+O1)/(l0+l1), write merged layout.
// One float4 per thread.
// ============================================================
__global__ __launch_bounds__(256) void combine_o()
{
    int idx = blockIdx.x * 256 + threadIdx.x;
    int r  = idx >> 4;                 // row = bh*SEQ + n
    int d4 = (idx & 15) * 4;
    float4 a = *(const float4*)&g_Op[0][(size_t)r*HD + d4];
    float4 b = *(const float4*)&g_Op[1][(size_t)r*HD + d4];
    float inv = 1.f / (g_lp[0][r] + g_lp[1][r]);
    int bh = r >> 11, n = r & (SEQ-1);
    int bb = bh / NH, hh = bh - bb*NH;
    float4 o = make_float4((a.x+b.x)*inv, (a.y+b.y)*inv, (a.z+b.z)*inv, (a.w+b.w)*inv);
    *(float4*)&g_Ot[((size_t)(bb*SEQ + n))*CD + hh*HD + d4] = o;
}

// ---- epilogues ----
struct EpiQKV {
    __device__ void store2(int, int r, int c, float v0, float v1) const {
        int b = r >> 11, n = r & (SEQ-1);
        int s = c / CD; int rem = c - s*CD;
        int h = rem >> 6, d = rem & 63;
        float* dst = (s == 0) ? g_q : ((s == 1) ? g_k : g_v);
        *(float2*)&dst[(((size_t)b*NH + h)*SEQ + n)*HD + d] = make_float2(v0, v1);
    }
};
struct EpiOut {
    float* out; const float* pb;
    __device__ void store2(int, int r, int c, float v0, float v1) const {
        *(float2*)&out[(size_t)r*CD + c] = make_float2(v0 + pb[c], v1 + pb[c+1]);
    }
};

extern "C" void kernel_launch(void* const* d_in, const int* /*in_sizes*/, int /*n_in*/,
                              void* d_out, int /*out_size*/)
{
    const float* x      = (const float*)d_in[0];
    const float* qkv_w  = (const float*)d_in[1];
    const float* proj_w = (const float*)d_in[2];
    const float* proj_b = (const float*)d_in[3];
    const float* fp     = (const float*)d_in[4];
    float* out = (float*)d_out;

    float *p_Ot;
    cudaGetSymbolAddress((void**)&p_Ot, g_Ot);

    constexpr int FLASH_SMEM = 3 * 36864;   // 110592 B (3-stage pipeline)
    cudaFuncSetAttribute(flash_attn, cudaFuncAttributeMaxDynamicSharedMemorySize, FLASH_SMEM);

    // 1. QKV projection (bf16 split, LDSM, 2 blocks/SM)
    mma_nt_bf<<<dim3(QD/128, MROWS/128, 1), 256>>>(x, qkv_w, CD,
                                                   (size_t)0, (size_t)0, EpiQKV{});
    // 2. spectral filtering via in-smem FFT
    fft_filter<<<dim3(HD, BB*NH, 2), 256>>>(fp);
    // 3. pre-split K and V into bf16 hi/lo planes
    repack_k<<<BB*NH*SEQ*32/256, 256>>>();
    repack_v<<<dim3(32, BB*NH), 256>>>();
    // 4-6. fused attention, split-KV (2 halves), partial O + l
    flash_attn<<<dim3(SEQ/128, BB*NH, 2), 256, FLASH_SMEM>>>();
    // 6b. combine partials -> merged layout
    combine_o<<<BB*NH*SEQ*16/256, 256>>>();
    // 7. output projection + bias
    mma_nt_bf<<<dim3(CD/128, MROWS/128, 1), 256>>>(p_Ot, proj_w, CD,
                                                   (size_t)0, (size_t)0, EpiOut{out, proj_b});
}

// round 17
// speedup vs baseline: 4.5550x; 1.1356x over previous
#include <cuda_runtime.h>
#include <math.h>

#ifndef M_PI
#define M_PI 3.14159265358979323846
#endif

namespace {
constexpr int BB  = 2;
constexpr int NH  = 12;
constexpr int SEQ = 2048;
constexpr int HD  = 64;
constexpr int CD  = 768;
constexpr int QD  = 2304;
constexpr int MROWS = BB * SEQ;  // 4096
constexpr int NSPLIT = 4;        // kv splits
}

// ---- scratch ----
__device__ float g_q [BB*NH*SEQ*HD];
__device__ float g_k [BB*NH*SEQ*HD];
__device__ float g_v [BB*NH*SEQ*HD];
__device__ float g_qf[BB*NH*SEQ*HD];
__device__ float g_Ot[BB*SEQ*CD];
// split-kv partials
__device__ float g_Op[NSPLIT][BB*NH*SEQ*HD];
__device__ float g_lp[NSPLIT][BB*NH*SEQ];
// pre-split bf16 planes
__device__ unsigned g_kh[BB*NH*SEQ*32], g_kl[BB*NH*SEQ*32];   // [bh][kv][dpair]
__device__ unsigned g_vh[BB*NH*SEQ*32], g_vl[BB*NH*SEQ*32];   // [bh][kt 32][d 64][kvpair 32]

// ============================================================
// helpers
// ============================================================
__device__ __forceinline__ void mma16bf(float* c, const unsigned* a, const unsigned* b) {
    asm volatile(
        "mma.sync.aligned.m16n8k16.row.col.f32.bf16.bf16.f32 "
        "{%0,%1,%2,%3}, {%4,%5,%6,%7}, {%8,%9}, {%0,%1,%2,%3};"
        : "+f"(c[0]), "+f"(c[1]), "+f"(c[2]), "+f"(c[3])
        : "r"(a[0]), "r"(a[1]), "r"(a[2]), "r"(a[3]), "r"(b[0]), "r"(b[1]));
}
__device__ __forceinline__ void split_bf16_pair(float xe, float xo, unsigned& hi, unsigned& lo) {
    unsigned h;
    asm("cvt.rn.bf16x2.f32 %0, %1, %2;" : "=r"(h) : "f"(xo), "f"(xe));
    float re = xe - __uint_as_float(h << 16);
    float ro = xo - __uint_as_float(h & 0xffff0000u);
    unsigned l;
    asm("cvt.rn.bf16x2.f32 %0, %1, %2;" : "=r"(l) : "f"(ro), "f"(re));
    hi = h; lo = l;
}
__device__ __forceinline__ unsigned sptr(const void* p) {
    return (unsigned)__cvta_generic_to_shared(p);
}
__device__ __forceinline__ void ldsm_x4(unsigned& r0, unsigned& r1, unsigned& r2, unsigned& r3,
                                        unsigned addr) {
    asm volatile("ldmatrix.sync.aligned.m8n8.x4.shared.b16 {%0,%1,%2,%3}, [%4];"
                 : "=r"(r0), "=r"(r1), "=r"(r2), "=r"(r3) : "r"(addr));
}
__device__ __forceinline__ void cp16(unsigned smem_byte, const void* gptr) {
    asm volatile("cp.async.cg.shared.global [%0], [%1], 16;"
                 :: "r"(smem_byte), "l"(gptr));
}

// ============================================================
// Spectral filter via in-smem Stockham FFT — TWO real columns per
// block. KEY: reference Re(ifft(A*X)) == ifft(Asym*X) for real x,
// Asym[k] = (A[k]+A[N-k])/2 (symmetric). With symmetric real filter
// the packed transform separates exactly:
//   ifft(Asym * fft(x + iy)) = x_filt + i*y_filt.
// q branch: writes fp32 qf (scale 0.125*log2e/N folded).
// k branch: writes bf16 hi/lo K planes directly (pairs = (d0, d1)).
// grid (HD/2, BB*NH, 2), 256 threads.
// ============================================================
__global__ __launch_bounds__(256) void fft_filter(const float* __restrict__ fp)
{
    __shared__ float2 buf[2][SEQ];

    const int d0 = blockIdx.x * 2;
    const int bh = blockIdx.y;
    const int h  = bh % NH;
    const bool isq = (blockIdx.z == 0);
    const float* src = (isq ? g_q : g_k) + (size_t)bh * SEQ * HD + d0;
    const int tid = threadIdx.x;

    // load column pair as complex
    for (int i = tid; i < SEQ; i += 256) {
        float2 z = *(const float2*)(src + (size_t)i * HD);
        buf[0][i] = z;
    }
    __syncthreads();

    int cur = 0;
    // ---- forward FFT ----
    #pragma unroll 1
    for (int Ns = 1; Ns < SEQ; Ns <<= 1) {
        const float2* s = buf[cur];
        float2* dt = buf[cur ^ 1];
        const float na = -(float)M_PI / Ns;
        for (int j = tid; j < SEQ/2; j += 256) {
            float2 v0 = s[j];
            float2 v1 = s[j + SEQ/2];
            float ang = na * (j & (Ns - 1));
            float sn, cs; __sincosf(ang, &sn, &cs);
            float2 w = make_float2(cs*v1.x - sn*v1.y, cs*v1.y + sn*v1.x);
            int idxD = ((j & ~(Ns - 1)) << 1) | (j & (Ns - 1));
            dt[idxD]      = make_float2(v0.x + w.x, v0.y + w.y);
            dt[idxD + Ns] = make_float2(v0.x - w.x, v0.y - w.y);
        }
        __syncthreads();
        cur ^= 1;
    }

    // ---- Asym * conj (scale folded; q also carries 0.125*log2e) ----
    {
        double p = (double)fp[h];
        double sig = 1.0 / (1.0 + exp(-p));
        float cutoff = (float)floor((double)SEQ * sig);
        float sc = (isq ? 0.5f * 0.125f * 1.44269504089f : 0.5f) / (float)SEQ;
        float2* P = buf[cur];
        for (int i = tid; i < SEQ; i += 256) {
            float rel = (float)i - cutoff;
            float A1 = (rel >= 0.f) ? __expf(-rel * (4.0f / SEQ)) : 1.0f;
            int im = (SEQ - i) & (SEQ - 1);
            float rel2 = (float)im - cutoff;
            float A2 = (rel2 >= 0.f) ? __expf(-rel2 * (4.0f / SEQ)) : 1.0f;
            float A = (A1 + A2) * sc;     // symmetric filter * 0.5 * scale
            float2 v = P[i];
            P[i] = make_float2(A * v.x, -A * v.y);
        }
    }
    __syncthreads();

    // ---- second forward FFT (ifft via conj) ----
    #pragma unroll 1
    for (int Ns = 1; Ns < SEQ; Ns <<= 1) {
        const float2* s = buf[cur];
        float2* dt = buf[cur ^ 1];
        const float na = -(float)M_PI / Ns;
        for (int j = tid; j < SEQ/2; j += 256) {
            float2 v0 = s[j];
            float2 v1 = s[j + SEQ/2];
            float ang = na * (j & (Ns - 1));
            float sn, cs; __sincosf(ang, &sn, &cs);
            float2 w = make_float2(cs*v1.x - sn*v1.y, cs*v1.y + sn*v1.x);
            int idxD = ((j & ~(Ns - 1)) << 1) | (j & (Ns - 1));
            dt[idxD]      = make_float2(v0.x + w.x, v0.y + w.y);
            dt[idxD + Ns] = make_float2(v0.x - w.x, v0.y - w.y);
        }
        __syncthreads();
        cur ^= 1;
    }

    // ---- store: U = conj(x_filt + i y_filt) => d0 = U.x, d1 = -U.y ----
    if (isq) {
        float* dst = g_qf + (size_t)bh * SEQ * HD + d0;
        const float2* P = buf[cur];
        for (int i = tid; i < SEQ; i += 256) {
            float2 u = P[i];
            *(float2*)(dst + (size_t)i * HD) = make_float2(u.x, -u.y);
        }
    } else {
        unsigned* kh = g_kh + (size_t)bh * SEQ * 32 + (d0 >> 1);
        unsigned* kl = g_kl + (size_t)bh * SEQ * 32 + (d0 >> 1);
        const float2* P = buf[cur];
        for (int i = tid; i < SEQ; i += 256) {
            float2 u = P[i];
            unsigned hi, lo;
            split_bf16_pair(u.x, -u.y, hi, lo);
            kh[(size_t)i * 32] = hi;
            kl[(size_t)i * 32] = lo;
        }
    }
}

// ============================================================
// Repack V: g_v -> transposed planes [bh][kt 32][d 64][kvpair 32].
// ============================================================
__global__ __launch_bounds__(256) void repack_v()
{
    __shared__ float vs[64*65];
    const int kt = blockIdx.x, bh = blockIdx.y;
    const float* src = g_v + ((size_t)bh * SEQ + kt * 64) * HD;
    const int tid = threadIdx.x;

    for (int i = tid; i < 64*16; i += 256) {
        int r = i >> 4, q4 = (i & 15) * 4;
        float4 t = *(const float4*)(src + (size_t)r * HD + q4);
        vs[r*65 + q4]     = t.x;
        vs[r*65 + q4 + 1] = t.y;
        vs[r*65 + q4 + 2] = t.z;
        vs[r*65 + q4 + 3] = t.w;
    }
    __syncthreads();

    unsigned* dh = g_vh + ((size_t)bh * 32 + kt) * 64 * 32;
    unsigned* dl = g_vl + ((size_t)bh * 32 + kt) * 64 * 32;
    for (int i = tid; i < 64*32; i += 256) {
        int d = i >> 5, kp = i & 31;
        float e = vs[(2*kp)*65 + d];
        float o = vs[(2*kp + 1)*65 + d];
        unsigned hi, lo;
        split_bf16_pair(e, o, hi, lo);
        dh[i] = hi;
        dl[i] = lo;
    }
}

// ============================================================
// NT tensor-core GEMM (bf16 3-term split), LDSM, 2 blocks/SM.
// ============================================================
template<class Epi>
__global__ __launch_bounds__(256,2) void mma_nt_bf(const float* __restrict__ A,
                                                   const float* __restrict__ B,
                                                   int K, size_t sA, size_t sB, Epi epi)
{
    __shared__ __align__(16) unsigned Ah[128*20], Al[128*20];
    __shared__ __align__(16) unsigned Bh[128*20], Bl[128*20];
    const int m0 = blockIdx.y * 128, n0 = blockIdx.x * 128;
    const float* Ab = A + (size_t)blockIdx.z * sA;
    const float* Bb = B + (size_t)blockIdx.z * sB;
    const int tid = threadIdx.x, lane = tid & 31, wid = tid >> 5;
    const int wm = (wid >> 1) * 32, wn = (wid & 1) * 64;
    const int g = lane >> 2, t = lane & 3;
    const int tl = lane >> 3, rw = lane & 7;

    const unsigned ah_s = sptr(Ah), al_s = sptr(Al);
    const unsigned bh_s = sptr(Bh), bl_s = sptr(Bl);

    float C[2][8][4] = {};

    for (int k0 = 0; k0 < K; k0 += 32) {
        #pragma unroll
        for (int it = 0; it < 8; it++) {
            int i = tid + 256*it;
            int mm = i >> 4, kp = i & 15;
            float2 e = *(const float2*)(Ab + (size_t)(m0+mm)*K + k0 + 2*kp);
            unsigned hi, lo;
            split_bf16_pair(e.x, e.y, hi, lo);
            Ah[mm*20 + kp] = hi; Al[mm*20 + kp] = lo;
            float2 f = *(const float2*)(Bb + (size_t)(n0+mm)*K + k0 + 2*kp);
            split_bf16_pair(f.x, f.y, hi, lo);
            Bh[mm*20 + kp] = hi; Bl[mm*20 + kp] = lo;
        }
        __syncthreads();
        #pragma unroll
        for (int c = 0; c < 2; c++) {
            unsigned ah[2][4], al[2][4];
            #pragma unroll
            for (int im = 0; im < 2; im++) {
                unsigned off = (unsigned)(((wm + 16*im + 8*(tl & 1) + rw)*20
                                           + 8*c + 4*(tl >> 1)) * 4);
                ldsm_x4(ah[im][0], ah[im][1], ah[im][2], ah[im][3], ah_s + off);
                ldsm_x4(al[im][0], al[im][1], al[im][2], al[im][3], al_s + off);
            }
            #pragma unroll
            for (int jnp = 0; jnp < 4; jnp++) {
                unsigned off = (unsigned)(((wn + 8*(2*jnp + (tl >> 1)) + rw)*20
                                           + 8*c + 4*(tl & 1)) * 4);
                unsigned b0, b1, b2, b3, c0, c1, c2, c3;
                ldsm_x4(b0, b1, b2, b3, bh_s + off);
                ldsm_x4(c0, c1, c2, c3, bl_s + off);
                unsigned bh2[2] = { b0, b1 }, bl2[2] = { c0, c1 };
                unsigned bh3[2] = { b2, b3 }, bl3[2] = { c2, c3 };
                #pragma unroll
                for (int im = 0; im < 2; im++) {
                    mma16bf(C[im][2*jnp],   ah[im], bh2);
                    mma16bf(C[im][2*jnp],   ah[im], bl2);
                    mma16bf(C[im][2*jnp],   al[im], bh2);
                    mma16bf(C[im][2*jnp+1], ah[im], bh3);
                    mma16bf(C[im][2*jnp+1], ah[im], bl3);
                    mma16bf(C[im][2*jnp+1], al[im], bh3);
                }
            }
        }
        __syncthreads();
    }
    #pragma unroll
    for (int im = 0; im < 2; im++)
        #pragma unroll
        for (int jn = 0; jn < 8; jn++) {
            int r  = m0 + wm + im*16 + g;
            int cc = n0 + wn + jn*8 + 2*t;
            epi.store2(blockIdx.z, r,   cc, C[im][jn][0], C[im][jn][1]);
            epi.store2(blockIdx.z, r+8, cc, C[im][jn][2], C[im][jn][3]);
        }
}

// ============================================================
// Fused flash attention, 4-way split-KV: grid (16, 24, 4).
// Each block does 8 kv tiles -> unnormalized partial O + l.
// exp2 softmax (log2e folded into qf), cp.async 3-stage, LDSM.
// ============================================================
__global__ __launch_bounds__(256,2) void flash_attn()
{
    extern __shared__ __align__(16) unsigned dsm[];
    constexpr unsigned STG = 36864;
    constexpr unsigned KL_OFF = 9216, VH_OFF = 18432, VL_OFF = 27648;
    constexpr int NTL = 32 / NSPLIT;     // 8 tiles per split

    const int bh = blockIdx.y;
    const int m0 = blockIdx.x * 128;
    const int half = blockIdx.z;
    const int kt0 = half * NTL;
    const float* qf = g_qf + (size_t)bh * SEQ * HD;
    const unsigned* kh_g = g_kh + (size_t)bh * SEQ * 32;
    const unsigned* kl_g = g_kl + (size_t)bh * SEQ * 32;
    const unsigned* vh_g = g_vh + (size_t)bh * SEQ * 32;
    const unsigned* vl_g = g_vl + (size_t)bh * SEQ * 32;

    const int tid = threadIdx.x, lane = tid & 31, w = tid >> 5;
    const int g = lane >> 2, t4 = lane & 3;
    const int tl = lane >> 3, rw = lane & 7;
    const unsigned smem0 = sptr(dsm);

    // persistent Q fragments (bf16 split, packed pairs)
    unsigned qh[4][4], ql[4][4];
    {
        const float* r0 = qf + (size_t)(m0 + 16*w + g) * HD;
        const float* r1 = r0 + 8*HD;
        #pragma unroll
        for (int c = 0; c < 4; c++) {
            split_bf16_pair(r0[16*c + 2*t4],     r0[16*c + 2*t4 + 1], qh[c][0], ql[c][0]);
            split_bf16_pair(r1[16*c + 2*t4],     r1[16*c + 2*t4 + 1], qh[c][1], ql[c][1]);
            split_bf16_pair(r0[16*c + 8 + 2*t4], r0[16*c + 9 + 2*t4], qh[c][2], ql[c][2]);
            split_bf16_pair(r1[16*c + 8 + 2*t4], r1[16*c + 9 + 2*t4], qh[c][3], ql[c][3]);
        }
    }

    auto issue = [&](int kt, int s) {
        unsigned base = smem0 + (unsigned)s * STG;
        const unsigned* kh = kh_g + kt*64*32;
        const unsigned* kl = kl_g + kt*64*32;
        const unsigned* vh = vh_g + kt*64*32;
        const unsigned* vl = vl_g + kt*64*32;
        #pragma unroll
        for (int j = 0; j < 2; j++) {
            int i = tid + 256*j;
            int r = i >> 3, p4 = (i & 7) * 4;
            unsigned doff = (unsigned)((r*36 + p4) * 4);
            cp16(base + doff,          kh + r*32 + p4);
            cp16(base + KL_OFF + doff, kl + r*32 + p4);
            cp16(base + VH_OFF + doff, vh + r*32 + p4);
            cp16(base + VL_OFF + doff, vl + r*32 + p4);
        }
    };

    float O[8][4] = {};
    float l0 = 0.f, l1 = 0.f;

    issue(kt0 + 0, 0);
    asm volatile("cp.async.commit_group;" ::: "memory");
    issue(kt0 + 1, 1);
    asm volatile("cp.async.commit_group;" ::: "memory");

    int s = 0;
    for (int lt = 0; lt < NTL; lt++) {
        asm volatile("cp.async.wait_group 1;" ::: "memory");
        __syncthreads();
        if (lt + 2 < NTL) issue(kt0 + lt + 2, (s + 2) % 3);
        asm volatile("cp.async.commit_group;" ::: "memory");

        const unsigned khs_b = smem0 + (unsigned)s * STG;
        const unsigned kls_b = khs_b + KL_OFF;
        const unsigned vhs_b = khs_b + VH_OFF;
        const unsigned vls_b = khs_b + VL_OFF;

        // ---- S' = Qf Kf^T (log2e pre-folded) ----
        float S[8][4] = {};
        #pragma unroll
        for (int c = 0; c < 4; c++) {
            #pragma unroll
            for (int jnp = 0; jnp < 4; jnp++) {
                unsigned off = (unsigned)(((8*(2*jnp + (tl >> 1)) + rw)*36
                                           + 8*c + 4*(tl & 1)) * 4);
                unsigned b0, b1, b2, b3, c0, c1, c2, c3;
                ldsm_x4(b0, b1, b2, b3, khs_b + off);
                ldsm_x4(c0, c1, c2, c3, kls_b + off);
                unsigned bh2[2] = { b0, b1 }, bl2[2] = { c0, c1 };
                unsigned bh3[2] = { b2, b3 }, bl3[2] = { c2, c3 };
                mma16bf(S[2*jnp],   qh[c], bh2);
                mma16bf(S[2*jnp],   qh[c], bl2);
                mma16bf(S[2*jnp],   ql[c], bh2);
                mma16bf(S[2*jnp+1], qh[c], bh3);
                mma16bf(S[2*jnp+1], qh[c], bl3);
                mma16bf(S[2*jnp+1], ql[c], bh3);
            }
        }

        // ---- softmax numerator: P = exp2(S') ----
        float ps0 = 0.f, ps1 = 0.f;
        #pragma unroll
        for (int half2 = 0; half2 < 2; half2++) {
            unsigned ph[4][2], pl[4][2];
            #pragma unroll
            for (int q4 = 0; q4 < 4; q4++) {
                int jn = 4*half2 + q4;
                float p0 = exp2f(S[jn][0]);
                float p1 = exp2f(S[jn][1]);
                float p2 = exp2f(S[jn][2]);
                float p3 = exp2f(S[jn][3]);
                ps0 += p0 + p1; ps1 += p2 + p3;
                split_bf16_pair(p0, p1, ph[q4][0], pl[q4][0]);
                split_bf16_pair(p2, p3, ph[q4][1], pl[q4][1]);
            }
            #pragma unroll
            for (int kc2 = 0; kc2 < 2; kc2++) {
                int kc = 8*(2*half2 + kc2);
                unsigned ah2[4] = { ph[2*kc2][0], ph[2*kc2][1], ph[2*kc2+1][0], ph[2*kc2+1][1] };
                unsigned al2[4] = { pl[2*kc2][0], pl[2*kc2][1], pl[2*kc2+1][0], pl[2*kc2+1][1] };
                #pragma unroll
                for (int jnp = 0; jnp < 4; jnp++) {
                    unsigned off = (unsigned)(((8*(2*jnp + (tl >> 1)) + rw)*36
                                               + kc + 4*(tl & 1)) * 4);
                    unsigned b0, b1, b2, b3, c0, c1, c2, c3;
                    ldsm_x4(b0, b1, b2, b3, vhs_b + off);
                    ldsm_x4(c0, c1, c2, c3, vls_b + off);
                    unsigned bh2[2] = { b0, b1 }, bl2[2] = { c0, c1 };
                    unsigned bh3[2] = { b2, b3 }, bl3[2] = { c2, c3 };
                    mma16bf(O[2*jnp],   ah2, bh2);
                    mma16bf(O[2*jnp],   ah2, bl2);
                    mma16bf(O[2*jnp],   al2, bh2);
                    mma16bf(O[2*jnp+1], ah2, bh3);
                    mma16bf(O[2*jnp+1], ah2, bl3);
                    mma16bf(O[2*jnp+1], al2, bh3);
                }
            }
        }
        l0 += ps0; l1 += ps1;
        s = (s + 1) % 3;
    }

    // ---- epilogue: partial l (quad-reduced) + unnormalized O ----
    l0 += __shfl_xor_sync(0xffffffffu, l0, 1);
    l0 += __shfl_xor_sync(0xffffffffu, l0, 2);
    l1 += __shfl_xor_sync(0xffffffffu, l1, 1);
    l1 += __shfl_xor_sync(0xffffffffu, l1, 2);

    const size_t r0g = (size_t)bh * SEQ + m0 + 16*w + g;
    const size_t r1g = r0g + 8;
    float* op = g_Op[half];
    #pragma unroll
    for (int jn = 0; jn < 8; jn++) {
        int cc = 8*jn + 2*t4;
        *(float2*)&op[r0g*HD + cc] = make_float2(O[jn][0], O[jn][1]);
        *(float2*)&op[r1g*HD + cc] = make_float2(O[jn][2], O[jn][3]);
    }
    if (t4 == 0) {
        g_lp[half][r0g] = l0;
        g_lp[half][r1g] = l1;
    }
}

// ============================================================
// Combine split-KV partials: O = sum(Oi)/sum(li), merged layout.
// ============================================================
__global__ __launch_bounds__(256) void combine_o()
{
    int idx = blockIdx.x * 256 + threadIdx.x;
    int r  = idx >> 4;
    int d4 = (idx & 15) * 4;
    float4 acc = *(const float4*)&g_Op[0][(size_t)r*HD + d4];
    float ls = g_lp[0][r];
    #pragma unroll
    for (int p = 1; p < NSPLIT; p++) {
        float4 b = *(const float4*)&g_Op[p][(size_t)r*HD + d4];
        acc.x += b.x; acc.y += b.y; acc.z += b.z; acc.w += b.w;
        ls += g_lp[p][r];
    }
    float inv = 1.f / ls;
    int bh = r >> 11, n = r & (SEQ-1);
    int bb = bh / NH, hh = bh - bb*NH;
    float4 o = make_float4(acc.x*inv, acc.y*inv, acc.z*inv, acc.w*inv);
    *(float4*)&g_Ot[((size_t)(bb*SEQ + n))*CD + hh*HD + d4] = o;
}

// ---- epilogues ----
struct EpiQKV {
    __device__ void store2(int, int r, int c, float v0, float v1) const {
        int b = r >> 11, n = r & (SEQ-1);
        int s = c / CD; int rem = c - s*CD;
        int h = rem >> 6, d = rem & 63;
        float* dst = (s == 0) ? g_q : ((s == 1) ? g_k : g_v);
        *(float2*)&dst[(((size_t)b*NH + h)*SEQ + n)*HD + d] = make_float2(v0, v1);
    }
};
struct EpiOut {
    float* out; const float* pb;
    __device__ void store2(int, int r, int c, float v0, float v1) const {
        *(float2*)&out[(size_t)r*CD + c] = make_float2(v0 + pb[c], v1 + pb[c+1]);
    }
};

extern "C" void kernel_launch(void* const* d_in, const int* /*in_sizes*/, int /*n_in*/,
                              void* d_out, int /*out_size*/)
{
    const float* x      = (const float*)d_in[0];
    const float* qkv_w  = (const float*)d_in[1];
    const float* proj_w = (const float*)d_in[2];
    const float* proj_b = (const float*)d_in[3];
    const float* fp     = (const float*)d_in[4];
    float* out = (float*)d_out;

    float *p_Ot;
    cudaGetSymbolAddress((void**)&p_Ot, g_Ot);

    constexpr int FLASH_SMEM = 3 * 36864;   // 110592 B (3-stage pipeline)
    cudaFuncSetAttribute(flash_attn, cudaFuncAttributeMaxDynamicSharedMemorySize, FLASH_SMEM);

    // 1. QKV projection (bf16 split, LDSM, 2 blocks/SM)
    mma_nt_bf<<<dim3(QD/128, MROWS/128, 1), 256>>>(x, qkv_w, CD,
                                                   (size_t)0, (size_t)0, EpiQKV{});
    // 2. spectral filtering via paired-column FFT (symmetric filter —
    //    exact identity with reference's Re(ifft(A*X)))
    fft_filter<<<dim3(HD/2, BB*NH, 2), 256>>>(fp);
    // 3. pre-split V planes
    repack_v<<<dim3(32, BB*NH), 256>>>();
    // 4-6. fused attention, 4-way split-KV, exp2 softmax
    flash_attn<<<dim3(SEQ/128, BB*NH, NSPLIT), 256, FLASH_SMEM>>>();
    // 6b. combine partials -> merged layout
    combine_o<<<BB*NH*SEQ*16/256, 256>>>();
    // 7. output projection + bias
    mma_nt_bf<<<dim3(CD/128, MROWS/128, 1), 256>>>(p_Ot, proj_w, CD,
                                                   (size_t)0, (size_t)0, EpiOut{out, proj_b});
}